// round 9
// baseline (speedup 1.0000x reference)
#include <cuda_runtime.h>
#include <cuda_bf16.h>
#include <cstdint>
#include <cfloat>

#define N_PTS 8192
#define KNN   16
#define CIN   256
#define COUT  256
#define NK    (N_PTS*KNN)       // 131072
#define HDIM  64
#define SLOPE 0.01f
#define EPS   1e-5f
#define QPB   8
#define ASTR  40                // A smem row stride in halves
#define BSTR  136               // B smem row stride in halves

// kNN grid params
#define GDIM  8
#define GCELLS (GDIM*GDIM*GDIM)   // 512
#define KRAD  0.25f
#define KRAD2 0.0625f

// weight-split buffer offsets (natural [K,N] layout, bf16 hi/lo)
#define OQ   0
#define OKV  65536              // 256*256
#define OP2  196608             // + 256*512
#define OW   212992             // + 64*256
#define TOTW 278528             // + 256*256

// dynamic smem layout for mma_gemm (bytes)
#define SA0   0
#define SA0L  10240
#define SA1   20480
#define SA1L  30720
#define SB0   40960
#define SB0L  49664
#define SB1   58368
#define SB1L  67072
#define SAUX  75776
#define DSMEM 82688

// ---------------- device scratch (static, allocation-free) ----------------
__device__ int      g_idx[NK];
__device__ float    g_q  [N_PTS*COUT];
__device__ float    g_kv [N_PTS*512];     // [kf | vf]
__device__ float    g_bkv[512];
__device__ uint16_t g_bth[TOTW];          // weights bf16 hi, [K,N]
__device__ uint16_t g_btl[TOTW];          // weights bf16 lo, [K,N]
__device__ float    g_w1 [NK*COUT];
__device__ float    g_w2 [NK*COUT];
__device__ float    g_m[9];               // pe4 moments
__device__ float    g_s1[COUT], g_q1[COUT];
__device__ float    g_s2[COUT], g_q2[COUT];
// grid structures
__device__ int      g_cellCnt[GCELLS];
__device__ int      g_cellFill[GCELLS];
__device__ int      g_cellStart[GCELLS+1];
__device__ float4   g_spts[N_PTS];
__device__ int      g_sidx[N_PTS];

// ---------------- PTX helpers ----------------
__device__ __forceinline__ uint32_t su32(const void* p) {
    return (uint32_t)__cvta_generic_to_shared(p);
}
__device__ __forceinline__ void ldsm4(uint32_t r[4], uint32_t a) {
    asm volatile("ldmatrix.sync.aligned.m8n8.x4.shared.b16 {%0,%1,%2,%3}, [%4];"
        : "=r"(r[0]), "=r"(r[1]), "=r"(r[2]), "=r"(r[3]) : "r"(a));
}
__device__ __forceinline__ void ldsm4t(uint32_t r[4], uint32_t a) {
    asm volatile("ldmatrix.sync.aligned.m8n8.x4.trans.shared.b16 {%0,%1,%2,%3}, [%4];"
        : "=r"(r[0]), "=r"(r[1]), "=r"(r[2]), "=r"(r[3]) : "r"(a));
}
__device__ __forceinline__ void mma16816(float c[4], const uint32_t a[4], const uint32_t b[2]) {
    asm volatile("mma.sync.aligned.m16n8k16.row.col.f32.bf16.bf16.f32 "
        "{%0,%1,%2,%3}, {%4,%5,%6,%7}, {%8,%9}, {%0,%1,%2,%3};"
        : "+f"(c[0]), "+f"(c[1]), "+f"(c[2]), "+f"(c[3])
        : "r"(a[0]), "r"(a[1]), "r"(a[2]), "r"(a[3]), "r"(b[0]), "r"(b[1]));
}
__device__ __forceinline__ void split1(float x, uint16_t& hi, uint16_t& lo) {
    __nv_bfloat16 h = __float2bfloat16_rn(x);
    __nv_bfloat16 l = __float2bfloat16_rn(x - __bfloat162float(h));
    hi = *(uint16_t*)&h; lo = *(uint16_t*)&l;
}
__device__ __forceinline__ void pack8(const float* v, uint4& H, uint4& L) {
    uint16_t h[8], l[8];
#pragma unroll
    for (int i = 0; i < 8; i++) split1(v[i], h[i], l[i]);
    H.x = (uint32_t)h[0] | ((uint32_t)h[1] << 16);
    H.y = (uint32_t)h[2] | ((uint32_t)h[3] << 16);
    H.z = (uint32_t)h[4] | ((uint32_t)h[5] << 16);
    H.w = (uint32_t)h[6] | ((uint32_t)h[7] << 16);
    L.x = (uint32_t)l[0] | ((uint32_t)l[1] << 16);
    L.y = (uint32_t)l[2] | ((uint32_t)l[3] << 16);
    L.z = (uint32_t)l[4] | ((uint32_t)l[5] << 16);
    L.w = (uint32_t)l[6] | ((uint32_t)l[7] << 16);
}

// ---------------- prep: weight split + bias concat + zero stats + grid zero ----
__global__ void prep_kernel(const float* __restrict__ wq,
                            const float* __restrict__ wk, const float* __restrict__ wv,
                            const float* __restrict__ wp2, const float* __restrict__ ww,
                            const float* __restrict__ bk, const float* __restrict__ bv) {
    int i = blockIdx.x * 256 + threadIdx.x;
    if (i < TOTW) {
        float val;
        if (i < OKV) {                       // wq [256,256]
            val = wq[i];
        } else if (i < OP2) {                // wkv [256,512]: row k = [wk_k | wv_k]
            int j = i - OKV, k = j >> 9, n = j & 511;
            val = (n < 256) ? wk[k*256 + n] : wv[k*256 + (n - 256)];
        } else if (i < OW) {                 // wp2 [64,256]
            val = wp2[i - OP2];
        } else {                             // ww [256,256]
            val = ww[i - OW];
        }
        uint16_t h, l;
        split1(val, h, l);
        g_bth[i] = h; g_btl[i] = l;
    }
    if (i < 512) {
        g_bkv[i] = (i < 256) ? bk[i] : bv[i - 256];
        g_cellCnt[i] = 0;
    }
    if (i < 9) g_m[i] = 0.f;
    if (i < COUT) { g_s1[i] = 0.f; g_q1[i] = 0.f; g_s2[i] = 0.f; g_q2[i] = 0.f; }
}

// ---------------- kNN: exact grid-accelerated, integrated fallback ----------------
__device__ __forceinline__ float norm3_ref(float x, float y, float z) {
    return __fadd_rn(__fadd_rn(__fmul_rn(x, x), __fmul_rn(y, y)), __fmul_rn(z, z));
}
__device__ __forceinline__ int gcell(float v) {
    int c = (int)(v * (float)GDIM);
    return c < 0 ? 0 : (c > GDIM-1 ? GDIM-1 : c);
}

__global__ void grid_count_kernel(const float* __restrict__ xyz_i) {
    int i = blockIdx.x * 256 + threadIdx.x;
    if (i >= N_PTS) return;
    int cx = gcell(xyz_i[i*3+0]);
    int cy = gcell(xyz_i[i*3+1]);
    int cz = gcell(xyz_i[i*3+2]);
    atomicAdd(&g_cellCnt[(cz*GDIM + cy)*GDIM + cx], 1);
}
__global__ void grid_scan_kernel() {
    __shared__ int s[GCELLS];
    int t = threadIdx.x;                  // 512
    int own = g_cellCnt[t];
    s[t] = own;
    __syncthreads();
    for (int off = 1; off < GCELLS; off <<= 1) {
        int u = 0;
        if (t >= off) u = s[t - off];
        __syncthreads();
        s[t] += u;
        __syncthreads();
    }
    g_cellStart[t] = s[t] - own;          // exclusive
    if (t == GCELLS-1) g_cellStart[GCELLS] = N_PTS;
    g_cellFill[t] = 0;
}
__global__ void grid_scatter_kernel(const float* __restrict__ xyz_i) {
    int i = blockIdx.x * 256 + threadIdx.x;
    if (i >= N_PTS) return;
    float x = xyz_i[i*3+0], y = xyz_i[i*3+1], z = xyz_i[i*3+2];
    int cell = (gcell(z)*GDIM + gcell(y))*GDIM + gcell(x);
    int pos = g_cellStart[cell] + atomicAdd(&g_cellFill[cell], 1);
    g_spts[pos] = make_float4(x, y, z, norm3_ref(x, y, z));
    g_sidx[pos] = i;
}

// warp per query: grid cells within KRAD; exact d2; lexicographic top-16;
// integrated exact fallback (full scan over sorted array) if radius insufficient.
__global__ void knn_grid_kernel(const float* __restrict__ xyz_last) {
    __shared__ float ld[QPB][KNN][32];
    __shared__ int   li[QPB][KNN][32];
    const int tid = threadIdx.x;
    const int w = tid >> 5, lane = tid & 31;
    const int q = blockIdx.x * QPB + w;
    const float qx = xyz_last[q*3+0];
    const float qy = xyz_last[q*3+1];
    const float qz = xyz_last[q*3+2];
    const float nq = norm3_ref(qx, qy, qz);
    const float cw = 1.f / (float)GDIM;

    float dist[KNN];
    int   idx [KNN];
#pragma unroll
    for (int j = 0; j < KNN; j++) { dist[j] = FLT_MAX; idx[j] = 0x7fffffff; }

    int zlo = (int)floorf((qz - KRAD) * (float)GDIM); if (zlo < 0) zlo = 0;
    int zhi = (int)floorf((qz + KRAD) * (float)GDIM); if (zhi > GDIM-1) zhi = GDIM-1;
    int ylo = (int)floorf((qy - KRAD) * (float)GDIM); if (ylo < 0) ylo = 0;
    int yhi = (int)floorf((qy + KRAD) * (float)GDIM); if (yhi > GDIM-1) yhi = GDIM-1;

    for (int z = zlo; z <= zhi; z++) {
        float dz = fmaxf(0.f, fmaxf((float)z * cw - qz, qz - (float)(z+1) * cw));
        float dz2 = dz * dz;
        for (int y = ylo; y <= yhi; y++) {
            float dy = fmaxf(0.f, fmaxf((float)y * cw - qy, qy - (float)(y+1) * cw));
            float dyz2 = dz2 + dy * dy;
            if (dyz2 > KRAD2) continue;
            float xr = sqrtf(KRAD2 - dyz2) + 1e-6f;
            int xlo = (int)floorf((qx - xr) * (float)GDIM); if (xlo < 0) xlo = 0;
            int xhi = (int)floorf((qx + xr) * (float)GDIM); if (xhi > GDIM-1) xhi = GDIM-1;
            int base = (z*GDIM + y)*GDIM;
            int s = g_cellStart[base + xlo];
            int e = g_cellStart[base + xhi + 1];
            for (int i = s + lane; i < e; i += 32) {
                float4 pv = g_spts[i];
                float t = __fmul_rn(qx, pv.x);
                t = __fmaf_rn(qy, pv.y, t);
                t = __fmaf_rn(qz, pv.z, t);
                float d2 = __fsub_rn(__fadd_rn(nq, pv.w), __fmul_rn(2.0f, t));
                int gi = g_sidx[i];
                bool ins = (d2 < dist[KNN-1]) || (d2 == dist[KNN-1] && gi < idx[KNN-1]);
                if (ins) {
                    dist[KNN-1] = d2;
                    idx[KNN-1]  = gi;
#pragma unroll
                    for (int j = KNN-1; j > 0; j--) {
                        float da = dist[j-1], db = dist[j];
                        int   ia = idx[j-1],  ib = idx[j];
                        bool sw = (db < da) || (db == da && ib < ia);
                        dist[j-1] = sw ? db : da;
                        dist[j]   = sw ? da : db;
                        idx[j-1]  = sw ? ib : ia;
                        idx[j]    = sw ? ia : ib;
                    }
                }
            }
        }
    }
#pragma unroll
    for (int j = 0; j < KNN; j++) { ld[w][j][lane] = dist[j]; li[w][j][lane] = idx[j]; }
    __syncwarp();

    int pos = 0;
    float last_v = FLT_MAX;
    for (int r = 0; r < KNN; r++) {
        float v = (pos < KNN) ? ld[w][pos][lane] : FLT_MAX;
        int  gi = (pos < KNN) ? li[w][pos][lane] : 0x7fffffff;
        int  owner = lane;
#pragma unroll
        for (int off = 16; off > 0; off >>= 1) {
            float v2  = __shfl_xor_sync(0xffffffffu, v, off);
            int   g2  = __shfl_xor_sync(0xffffffffu, gi, off);
            int   o2  = __shfl_xor_sync(0xffffffffu, owner, off);
            if (v2 < v || (v2 == v && g2 < gi)) { v = v2; gi = g2; owner = o2; }
        }
        if (lane == 0) g_idx[q*KNN + r] = gi;
        last_v = v;
        if (lane == owner) pos++;
    }
    // soundness: all non-enumerated points have d2 > KRAD2 (minus fp slack)
    if (!(last_v + 1e-4f < KRAD2)) {
        // exact fallback: full scan over sorted array (warp-local, rare)
#pragma unroll
        for (int j = 0; j < KNN; j++) { dist[j] = FLT_MAX; idx[j] = 0x7fffffff; }
        for (int i = lane; i < N_PTS; i += 32) {
            float4 pv = g_spts[i];
            float t = __fmul_rn(qx, pv.x);
            t = __fmaf_rn(qy, pv.y, t);
            t = __fmaf_rn(qz, pv.z, t);
            float d2 = __fsub_rn(__fadd_rn(nq, pv.w), __fmul_rn(2.0f, t));
            int gi = g_sidx[i];
            bool ins = (d2 < dist[KNN-1]) || (d2 == dist[KNN-1] && gi < idx[KNN-1]);
            if (ins) {
                dist[KNN-1] = d2;
                idx[KNN-1]  = gi;
#pragma unroll
                for (int j = KNN-1; j > 0; j--) {
                    float da = dist[j-1], db = dist[j];
                    int   ia = idx[j-1],  ib = idx[j];
                    bool sw = (db < da) || (db == da && ib < ia);
                    dist[j-1] = sw ? db : da;
                    dist[j]   = sw ? da : db;
                    idx[j-1]  = sw ? ib : ia;
                    idx[j]    = sw ? ia : ib;
                }
            }
        }
#pragma unroll
        for (int j = 0; j < KNN; j++) { ld[w][j][lane] = dist[j]; li[w][j][lane] = idx[j]; }
        __syncwarp();
        pos = 0;
        for (int r = 0; r < KNN; r++) {
            float v = (pos < KNN) ? ld[w][pos][lane] : FLT_MAX;
            int  gi = (pos < KNN) ? li[w][pos][lane] : 0x7fffffff;
            int  owner = lane;
#pragma unroll
            for (int off = 16; off > 0; off >>= 1) {
                float v2  = __shfl_xor_sync(0xffffffffu, v, off);
                int   g2  = __shfl_xor_sync(0xffffffffu, gi, off);
                int   o2  = __shfl_xor_sync(0xffffffffu, owner, off);
                if (v2 < v || (v2 == v && g2 < gi)) { v = v2; gi = g2; owner = o2; }
            }
            if (lane == 0) g_idx[q*KNN + r] = gi;
            if (lane == owner) pos++;
        }
    }
}

// ---------------- pe4 moments ----------------
__global__ void moments_kernel(const float* __restrict__ xyz_i,
                               const float* __restrict__ xyz_last) {
    float a0=0,a1=0,a2=0,a3=0,a4=0,a5=0,a6=0,a7=0,a8=0;
    for (int s = blockIdx.x * 256 + threadIdx.x; s < NK; s += gridDim.x * 256) {
        int n = s >> 4;
        int j = g_idx[s];
        float x = xyz_i[j*3+0] - xyz_last[n*3+0];
        float y = xyz_i[j*3+1] - xyz_last[n*3+1];
        float z = xyz_i[j*3+2] - xyz_last[n*3+2];
        a0 += x; a1 += y; a2 += z;
        a3 = fmaf(x,x,a3); a4 = fmaf(y,y,a4); a5 = fmaf(z,z,a5);
        a6 = fmaf(x,y,a6); a7 = fmaf(x,z,a7); a8 = fmaf(y,z,a8);
    }
    float v[9] = {a0,a1,a2,a3,a4,a5,a6,a7,a8};
#pragma unroll
    for (int i = 0; i < 9; i++) {
#pragma unroll
        for (int off = 16; off > 0; off >>= 1)
            v[i] += __shfl_xor_sync(0xffffffffu, v[i], off);
    }
    if ((threadIdx.x & 31) == 0) {
#pragma unroll
        for (int i = 0; i < 9; i++) atomicAdd(&g_m[i], v[i]);
    }
}

// ---------------- mma.sync GEMM: double-buffered, 512 threads, bf16 3-product ----
// MODE 0: plain; MODE 1: A generated from xyz (pe), BN-pe affine computed inline
//         from g_m, C := w1 = q - kf[idx] + pe, BN1 stats;
// MODE 2: f = lrelu(x*bn1), bn1 affine computed inline from g_s1/g_q1, C := w2, BN2 stats
template<int MODE>
__global__ __launch_bounds__(512)
void mma_gemm(const float* __restrict__ A,
              const uint16_t* __restrict__ Bth, const uint16_t* __restrict__ Btl,
              const float* __restrict__ bias, float* __restrict__ C,
              int M, int N, int K,
              const float* __restrict__ xyz_i, const float* __restrict__ xyz_last,
              const float* __restrict__ t_i, const float* __restrict__ t_last,
              const float* __restrict__ wp1, const float* __restrict__ bp1,
              const float* __restrict__ gma, const float* __restrict__ bta) {
    extern __shared__ char smem[];
    float* spx    = (float*)(smem + SAUX);
    float* spy    = (float*)(smem + SAUX + 512);
    float* spz    = (float*)(smem + SAUX + 1024);
    float* swp    = (float*)(smem + SAUX + 1536);   // 256 f
    float* sbp    = (float*)(smem + SAUX + 2560);   // 64 f
    float* sps    = (float*)(smem + SAUX + 2816);
    float* ssh    = (float*)(smem + SAUX + 3072);
    float* ssc    = (float*)(smem + SAUX + 3328);   // 256 f
    float* ssh2   = (float*)(smem + SAUX + 4352);   // 256 f
    float* sbias  = (float*)(smem + SAUX + 5376);   // 128 f
    float* sstatS = (float*)(smem + SAUX + 5888);
    float* sstatQ = (float*)(smem + SAUX + 6400);

    const int tid = threadIdx.x;
    const int lane = tid & 31, wid = tid >> 5;
    const int wm = wid >> 2, wn = wid & 3;          // 4x4 warp grid, 32x32 tiles
    const int m0 = blockIdx.y * 128, n0 = blockIdx.x * 128;

    // ---- prologue ----
    float dtv = 0.f;
    if (MODE == 1) {
        if (tid < 128) {
            int m = m0 + tid;
            int n = m >> 4;
            int j = g_idx[m];
            spx[tid] = xyz_i[j*3+0] - xyz_last[n*3+0];
            spy[tid] = xyz_i[j*3+1] - xyz_last[n*3+1];
            spz[tid] = xyz_i[j*3+2] - xyz_last[n*3+2];
        }
        if (tid < 256) swp[tid] = wp1[tid];
        dtv = t_i[0] - t_last[0];
        if (tid < 64) {
            // inline finalize_pe: analytic BN over generated h
            float inv = 1.f / (float)NK;
            float mx = g_m[0]*inv, my = g_m[1]*inv, mz = g_m[2]*inv;
            float exx = g_m[3]*inv, eyy = g_m[4]*inv, ezz = g_m[5]*inv;
            float exy = g_m[6]*inv, exz = g_m[7]*inv, eyz = g_m[8]*inv;
            float w0 = wp1[tid], w1 = wp1[64+tid], w2 = wp1[128+tid], w3 = wp1[192+tid];
            float a  = bp1[tid] + w3*dtv;
            float lm = w0*mx + w1*my + w2*mz;
            float mean = a + lm;
            float e2 = a*a + 2.f*a*lm
                     + w0*w0*exx + w1*w1*eyy + w2*w2*ezz
                     + 2.f*(w0*w1*exy + w0*w2*exz + w1*w2*eyz);
            float var = e2 - mean*mean;
            float s = gma[tid] * rsqrtf(var + EPS);
            sps[tid] = s;
            ssh[tid] = bta[tid] - mean*s;
            sbp[tid] = bp1[tid];
        }
    }
    if (MODE == 2 && tid < 256) {
        // inline finalize BN1
        float inv = 1.f / (float)NK;
        float m = g_s1[tid] * inv;
        float v = g_q1[tid] * inv - m*m;
        float s = gma[tid] * rsqrtf(v + EPS);
        ssc[tid]  = s;
        ssh2[tid] = bta[tid] - m*s;
    }
    if (tid < 128) { sbias[tid] = bias[n0 + tid]; sstatS[tid] = 0.f; sstatQ[tid] = 0.f; }
    __syncthreads();

    float acc[2][4][4];
#pragma unroll
    for (int i = 0; i < 2; i++)
#pragma unroll
        for (int j = 0; j < 4; j++)
#pragma unroll
            for (int e = 0; e < 4; e++) acc[i][j][e] = 0.f;

    const int arow = tid >> 2, ac = (tid & 3) * 8;     // A: 128 rows x 32 k
    const int brow = tid >> 4, bc = (tid & 15) * 8;    // B: 32 k-rows x 128 n

    float4 a0r, a1r;
    uint4 bhr, blr;

    auto load_regs = [&](int s) {
        const int kb = s * 32;
        if (MODE != 1) {
            a0r = *(const float4*)(A + (size_t)(m0 + arow)*K + kb + ac);
            a1r = *(const float4*)(A + (size_t)(m0 + arow)*K + kb + ac + 4);
        }
        bhr = *(const uint4*)(Bth + (size_t)(kb + brow)*N + n0 + bc);
        blr = *(const uint4*)(Btl + (size_t)(kb + brow)*N + n0 + bc);
    };
    auto store_stage = [&](int s, int buf) {
        char* dAh = smem + (buf ? SA1  : SA0);
        char* dAl = smem + (buf ? SA1L : SA0L);
        char* dBh = smem + (buf ? SB1  : SB0);
        char* dBl = smem + (buf ? SB1L : SB0L);
        const int kb = s * 32;
        float v[8];
        if (MODE == 1) {
            float px = spx[arow], py = spy[arow], pz = spz[arow];
#pragma unroll
            for (int e = 0; e < 8; e++) {
                int c = kb + ac + e;
                float hh = sbp[c];
                hh = fmaf(px,  swp[c],     hh);
                hh = fmaf(py,  swp[64+c],  hh);
                hh = fmaf(pz,  swp[128+c], hh);
                hh = fmaf(dtv, swp[192+c], hh);
                float x = fmaf(hh, sps[c], ssh[c]);
                v[e] = (x >= 0.f) ? x : SLOPE*x;
            }
        } else {
            v[0]=a0r.x; v[1]=a0r.y; v[2]=a0r.z; v[3]=a0r.w;
            v[4]=a1r.x; v[5]=a1r.y; v[6]=a1r.z; v[7]=a1r.w;
            if (MODE == 2) {
                int c = kb + ac;
#pragma unroll
                for (int e = 0; e < 8; e++) {
                    float x = fmaf(v[e], ssc[c+e], ssh2[c+e]);
                    v[e] = (x >= 0.f) ? x : SLOPE*x;
                }
            }
        }
        uint4 H, L;
        pack8(v, H, L);
        *(uint4*)(dAh + (arow*ASTR + ac)*2) = H;
        *(uint4*)(dAl + (arow*ASTR + ac)*2) = L;
        *(uint4*)(dBh + (brow*BSTR + bc)*2) = bhr;
        *(uint4*)(dBl + (brow*BSTR + bc)*2) = blr;
    };

    const uint32_t AhB[2] = { su32(smem + SA0),  su32(smem + SA1)  };
    const uint32_t AlB[2] = { su32(smem + SA0L), su32(smem + SA1L) };
    const uint32_t BhB[2] = { su32(smem + SB0),  su32(smem + SB1)  };
    const uint32_t BlB[2] = { su32(smem + SB0L), su32(smem + SB1L) };
    uint32_t a_off[2], b_off[2];
#pragma unroll
    for (int mt = 0; mt < 2; mt++)
        a_off[mt] = (uint32_t)(((wm*32 + mt*16 + (lane & 15))*ASTR + (lane >> 4)*8) * 2);
#pragma unroll
    for (int p = 0; p < 2; p++)
        b_off[p] = (uint32_t)(((lane & 15)*BSTR + wn*32 + p*16 + (lane >> 4)*8) * 2);

    auto compute = [&](int buf) {
#pragma unroll
        for (int ko = 0; ko < 2; ko++) {
            uint32_t ah[2][4], al_[2][4];
#pragma unroll
            for (int mt = 0; mt < 2; mt++) {
                ldsm4(ah[mt],  AhB[buf] + a_off[mt] + ko*32);
                ldsm4(al_[mt], AlB[buf] + a_off[mt] + ko*32);
            }
            uint32_t bh[4][2], bl[4][2];
#pragma unroll
            for (int p = 0; p < 2; p++) {
                uint32_t r[4];
                ldsm4t(r, BhB[buf] + b_off[p] + ko*16*BSTR*2);
                bh[2*p][0] = r[0]; bh[2*p][1] = r[1];
                bh[2*p+1][0] = r[2]; bh[2*p+1][1] = r[3];
                ldsm4t(r, BlB[buf] + b_off[p] + ko*16*BSTR*2);
                bl[2*p][0] = r[0]; bl[2*p][1] = r[1];
                bl[2*p+1][0] = r[2]; bl[2*p+1][1] = r[3];
            }
            // product-major ordering: independent chains of 8 between reuse
#pragma unroll
            for (int mt = 0; mt < 2; mt++)
#pragma unroll
                for (int nt = 0; nt < 4; nt++) mma16816(acc[mt][nt], ah[mt], bh[nt]);
#pragma unroll
            for (int mt = 0; mt < 2; mt++)
#pragma unroll
                for (int nt = 0; nt < 4; nt++) mma16816(acc[mt][nt], ah[mt], bl[nt]);
#pragma unroll
            for (int mt = 0; mt < 2; mt++)
#pragma unroll
                for (int nt = 0; nt < 4; nt++) mma16816(acc[mt][nt], al_[mt], bh[nt]);
        }
    };

    const int nst = K >> 5;
    // preamble
    load_regs(0);
    store_stage(0, 0);
    if (nst > 1) load_regs(1);
    __syncthreads();

    for (int kt = 0; kt < nst; kt++) {
        const int buf = kt & 1;
        if (kt + 1 < nst) {
            store_stage(kt + 1, buf ^ 1);
            if (kt + 2 < nst) load_regs(kt + 2);
        }
        compute(buf);
        if (kt + 1 < nst) __syncthreads();
    }

    // ---- epilogue ----
    float colS[8], colQ[8];
#pragma unroll
    for (int i = 0; i < 8; i++) { colS[i] = 0.f; colQ[i] = 0.f; }

#pragma unroll
    for (int mt = 0; mt < 2; mt++) {
        int r0 = m0 + wm*32 + mt*16 + (lane >> 2);
        int r1 = r0 + 8;
        int j0 = 0, j1 = 0, p0 = 0, p1 = 0;
        if (MODE == 1) {
            j0 = g_idx[r0]; j1 = g_idx[r1];
            p0 = r0 >> 4;   p1 = r1 >> 4;
        }
#pragma unroll
        for (int nt = 0; nt < 4; nt++) {
            int cl = wn*32 + nt*8 + (lane & 3)*2;      // local col in [0,128)
            int c = n0 + cl;
            float v00 = acc[mt][nt][0] + sbias[cl],   v01 = acc[mt][nt][1] + sbias[cl+1];
            float v10 = acc[mt][nt][2] + sbias[cl],   v11 = acc[mt][nt][3] + sbias[cl+1];
            if (MODE == 1) {
                float2 q0 = *(const float2*)(g_q  + (size_t)p0*256 + c);
                float2 q1 = *(const float2*)(g_q  + (size_t)p1*256 + c);
                float2 k0 = *(const float2*)(g_kv + (size_t)j0*512 + c);
                float2 k1 = *(const float2*)(g_kv + (size_t)j1*512 + c);
                v00 = q0.x - k0.x + v00; v01 = q0.y - k0.y + v01;
                v10 = q1.x - k1.x + v10; v11 = q1.y - k1.y + v11;
            }
            *(float2*)(C + (size_t)r0*N + c) = make_float2(v00, v01);
            *(float2*)(C + (size_t)r1*N + c) = make_float2(v10, v11);
            if (MODE != 0) {
                colS[nt*2+0] += v00 + v10;  colS[nt*2+1] += v01 + v11;
                colQ[nt*2+0] += v00*v00 + v10*v10;
                colQ[nt*2+1] += v01*v01 + v11*v11;
            }
        }
    }
    if (MODE != 0) {
#pragma unroll
        for (int i = 0; i < 8; i++) {
#pragma unroll
            for (int off = 4; off <= 16; off <<= 1) {
                colS[i] += __shfl_xor_sync(0xffffffffu, colS[i], off);
                colQ[i] += __shfl_xor_sync(0xffffffffu, colQ[i], off);
            }
        }
        if (lane < 4) {
#pragma unroll
            for (int nt = 0; nt < 4; nt++) {
#pragma unroll
                for (int j = 0; j < 2; j++) {
                    int cl = wn*32 + nt*8 + lane*2 + j;
                    atomicAdd(&sstatS[cl], colS[nt*2+j]);
                    atomicAdd(&sstatQ[cl], colQ[nt*2+j]);
                }
            }
        }
        __syncthreads();
        if (tid < 128) {
            float* gS = (MODE == 1) ? g_s1 : g_s2;
            float* gQ = (MODE == 1) ? g_q1 : g_q2;
            atomicAdd(&gS[n0 + tid], sstatS[tid]);
            atomicAdd(&gQ[n0 + tid], sstatQ[tid]);
        }
    }
}

// ---------------- final: inline BN2 finalize + lrelu + softmax(K) + v-sum ------
__global__ void final_kernel(float* __restrict__ out,
                             const float* __restrict__ gw2, const float* __restrict__ bw2) {
    int n = blockIdx.x, c = threadIdx.x;
    __shared__ int sidx[KNN];
    if (c < KNN) sidx[c] = g_idx[n*KNN + c];
    __syncthreads();
    float inv = 1.f / (float)NK;
    float mm = g_s2[c] * inv;
    float vv = g_q2[c] * inv - mm*mm;
    float sc = gw2[c] * rsqrtf(vv + EPS);
    float sh = bw2[c] - mm*sc;
    float qv = g_q[(size_t)n*COUT + c];
    float z[KNN], w1v[KNN];
    float m = -FLT_MAX;
#pragma unroll
    for (int k = 0; k < KNN; k++) {
        float x = g_w2[((size_t)n*KNN + k)*COUT + c];
        w1v[k] = g_w1[((size_t)n*KNN + k)*COUT + c];
        x = x*sc + sh;
        x = (x >= 0.f) ? x : SLOPE*x;
        z[k] = x;
        m = fmaxf(m, x);
    }
    float den = 0.f, num = 0.f;
#pragma unroll
    for (int k = 0; k < KNN; k++) {
        float e = __expf(z[k] - m);
        const float* kvrow = g_kv + (size_t)sidx[k]*512;
        float v = kvrow[256 + c] + (w1v[k] - qv + kvrow[c]);
        den += e;
        num = fmaf(e, v, num);
    }
    out[(size_t)n*COUT + c] = num / den;
}

// ---------------- launch ----------------
extern "C" void kernel_launch(void* const* d_in, const int* in_sizes, int n_in,
                              void* d_out, int out_size) {
    const float* fea_i    = (const float*)d_in[0];
    const float* fea_last = (const float*)d_in[1];
    const float* xyz_i    = (const float*)d_in[2];
    const float* xyz_last = (const float*)d_in[3];
    const float* t_i      = (const float*)d_in[4];
    const float* t_last   = (const float*)d_in[5];
    const float* wp1 = (const float*)d_in[6];
    const float* bp1 = (const float*)d_in[7];
    const float* gp  = (const float*)d_in[8];
    const float* bp  = (const float*)d_in[9];
    const float* wp2 = (const float*)d_in[10];
    const float* bp2 = (const float*)d_in[11];
    const float* wq  = (const float*)d_in[12];
    const float* bq  = (const float*)d_in[13];
    const float* wk  = (const float*)d_in[14];
    const float* bk  = (const float*)d_in[15];
    const float* wv  = (const float*)d_in[16];
    const float* bv  = (const float*)d_in[17];
    const float* gw1 = (const float*)d_in[18];
    const float* bw1 = (const float*)d_in[19];
    const float* ww  = (const float*)d_in[20];
    const float* bw  = (const float*)d_in[21];
    const float* gw2 = (const float*)d_in[22];
    const float* bw2 = (const float*)d_in[23];
    float* out = (float*)d_out;

    void* p;
    cudaGetSymbolAddress(&p, g_q);   float* p_q   = (float*)p;
    cudaGetSymbolAddress(&p, g_kv);  float* p_kv  = (float*)p;
    cudaGetSymbolAddress(&p, g_bkv); float* p_bkv = (float*)p;
    cudaGetSymbolAddress(&p, g_bth); uint16_t* p_bth = (uint16_t*)p;
    cudaGetSymbolAddress(&p, g_btl); uint16_t* p_btl = (uint16_t*)p;
    cudaGetSymbolAddress(&p, g_w1);  float* p_w1  = (float*)p;
    cudaGetSymbolAddress(&p, g_w2);  float* p_w2  = (float*)p;

    static bool attr_done = false;
    if (!attr_done) {
        cudaFuncSetAttribute(mma_gemm<0>, cudaFuncAttributeMaxDynamicSharedMemorySize, DSMEM);
        cudaFuncSetAttribute(mma_gemm<1>, cudaFuncAttributeMaxDynamicSharedMemorySize, DSMEM);
        cudaFuncSetAttribute(mma_gemm<2>, cudaFuncAttributeMaxDynamicSharedMemorySize, DSMEM);
        attr_done = true;
    }

    // 0) prep (weight split + bias + stat zero + grid zero)
    prep_kernel<<<(TOTW + 255)/256, 256>>>(wq, wk, wv, wp2, ww, bk, bv);

    // 1) kNN: grid build -> grid query (with integrated exact fallback)
    grid_count_kernel<<<N_PTS/256, 256>>>(xyz_i);
    grid_scan_kernel<<<1, 512>>>();
    grid_scatter_kernel<<<N_PTS/256, 256>>>(xyz_i);
    knn_grid_kernel<<<N_PTS/QPB, 256>>>(xyz_last);

    // 2) projections
    mma_gemm<0><<<dim3(2, 64), 512, DSMEM>>>(fea_last, p_bth + OQ,  p_btl + OQ,  bq,    p_q,  N_PTS, 256, CIN,
                                             nullptr, nullptr, nullptr, nullptr, nullptr, nullptr, nullptr, nullptr);
    mma_gemm<0><<<dim3(4, 64), 512, DSMEM>>>(fea_i,    p_bth + OKV, p_btl + OKV, p_bkv, p_kv, N_PTS, 512, CIN,
                                             nullptr, nullptr, nullptr, nullptr, nullptr, nullptr, nullptr, nullptr);

    // 3) pe4 moments (analytic BN stats; finalize inlined in mma_gemm<1>)
    moments_kernel<<<64, 256>>>(xyz_i, xyz_last);

    // 4) pe GEMM (A generated) -> w1 = q - kf + pe, + BN1 stats
    mma_gemm<1><<<dim3(2, 1024), 512, DSMEM>>>(nullptr, p_bth + OP2, p_btl + OP2, bp2, p_w1, NK, 256, HDIM,
                                               xyz_i, xyz_last, t_i, t_last, wp1, bp1, gp, bp);

    // 5) w2 GEMM (BN1 finalize inlined) + BN2 stats
    mma_gemm<2><<<dim3(2, 1024), 512, DSMEM>>>(p_w1, p_bth + OW, p_btl + OW, bw, p_w2, NK, 256, CIN,
                                               nullptr, nullptr, nullptr, nullptr, nullptr, nullptr, gw1, bw1);

    // 6) softmax over K + weighted v-sum (BN2 finalize inlined)
    final_kernel<<<N_PTS, COUT>>>(out, gw2, bw2);
}

// round 10
// speedup vs baseline: 1.0552x; 1.0552x over previous
#include <cuda_runtime.h>
#include <cuda_bf16.h>
#include <cstdint>
#include <cfloat>

#define N_PTS 8192
#define KNN   16
#define CIN   256
#define COUT  256
#define NK    (N_PTS*KNN)       // 131072
#define HDIM  64
#define SLOPE 0.01f
#define EPS   1e-5f
#define QPB   8
#define ASTR  40                // A smem row stride in halves
#define BSTR  136               // B smem row stride in halves

// kNN grid params
#define GDIM  8
#define GCELLS (GDIM*GDIM*GDIM)   // 512
#define KRAD  0.25f
#define KRAD2 0.0625f

// weight-split buffer offsets (natural [K,N] layout, bf16 hi/lo)
#define OQ   0
#define OKV  65536              // 256*256
#define OP2  196608             // + 256*512
#define OW   212992             // + 64*256
#define TOTW 278528             // + 256*256

// ---------------- device scratch (static, allocation-free) ----------------
__device__ int      g_idx[NK];
__device__ float    g_q  [N_PTS*COUT];
__device__ float    g_kv [N_PTS*512];     // [kf | vf]
__device__ float    g_bkv[512];
__device__ uint16_t g_bth[TOTW];          // weights bf16 hi, [K,N]
__device__ uint16_t g_btl[TOTW];          // weights bf16 lo, [K,N]
__device__ float    g_w1 [NK*COUT];
__device__ float    g_w2 [NK*COUT];
__device__ float    g_m[9];               // pe4 moments
__device__ float    g_s1[COUT], g_q1[COUT];
__device__ float    g_s2[COUT], g_q2[COUT];
// grid structures
__device__ int      g_cellCnt[GCELLS];
__device__ int      g_cellFill[GCELLS];
__device__ int      g_cellStart[GCELLS+1];
__device__ float4   g_spts[N_PTS];
__device__ int      g_sidx[N_PTS];

// ---------------- PTX helpers ----------------
__device__ __forceinline__ uint32_t su32(const void* p) {
    return (uint32_t)__cvta_generic_to_shared(p);
}
__device__ __forceinline__ void ldsm4(uint32_t r[4], uint32_t a) {
    asm volatile("ldmatrix.sync.aligned.m8n8.x4.shared.b16 {%0,%1,%2,%3}, [%4];"
        : "=r"(r[0]), "=r"(r[1]), "=r"(r[2]), "=r"(r[3]) : "r"(a));
}
__device__ __forceinline__ void ldsm4t(uint32_t r[4], uint32_t a) {
    asm volatile("ldmatrix.sync.aligned.m8n8.x4.trans.shared.b16 {%0,%1,%2,%3}, [%4];"
        : "=r"(r[0]), "=r"(r[1]), "=r"(r[2]), "=r"(r[3]) : "r"(a));
}
__device__ __forceinline__ void mma16816(float c[4], const uint32_t a[4], const uint32_t b[2]) {
    asm volatile("mma.sync.aligned.m16n8k16.row.col.f32.bf16.bf16.f32 "
        "{%0,%1,%2,%3}, {%4,%5,%6,%7}, {%8,%9}, {%0,%1,%2,%3};"
        : "+f"(c[0]), "+f"(c[1]), "+f"(c[2]), "+f"(c[3])
        : "r"(a[0]), "r"(a[1]), "r"(a[2]), "r"(a[3]), "r"(b[0]), "r"(b[1]));
}
__device__ __forceinline__ void split1(float x, uint16_t& hi, uint16_t& lo) {
    __nv_bfloat16 h = __float2bfloat16_rn(x);
    __nv_bfloat16 l = __float2bfloat16_rn(x - __bfloat162float(h));
    hi = *(uint16_t*)&h; lo = *(uint16_t*)&l;
}
__device__ __forceinline__ void pack8(const float* v, uint4& H, uint4& L) {
    uint16_t h[8], l[8];
#pragma unroll
    for (int i = 0; i < 8; i++) split1(v[i], h[i], l[i]);
    H.x = (uint32_t)h[0] | ((uint32_t)h[1] << 16);
    H.y = (uint32_t)h[2] | ((uint32_t)h[3] << 16);
    H.z = (uint32_t)h[4] | ((uint32_t)h[5] << 16);
    H.w = (uint32_t)h[6] | ((uint32_t)h[7] << 16);
    L.x = (uint32_t)l[0] | ((uint32_t)l[1] << 16);
    L.y = (uint32_t)l[2] | ((uint32_t)l[3] << 16);
    L.z = (uint32_t)l[4] | ((uint32_t)l[5] << 16);
    L.w = (uint32_t)l[6] | ((uint32_t)l[7] << 16);
}

// ---------------- prep: weight split + bias concat + zero stats + grid zero ----
__global__ void prep_kernel(const float* __restrict__ wq,
                            const float* __restrict__ wk, const float* __restrict__ wv,
                            const float* __restrict__ wp2, const float* __restrict__ ww,
                            const float* __restrict__ bk, const float* __restrict__ bv) {
    int i = blockIdx.x * 256 + threadIdx.x;
    if (i < TOTW) {
        float val;
        if (i < OKV) {                       // wq [256,256]
            val = wq[i];
        } else if (i < OP2) {                // wkv [256,512]: row k = [wk_k | wv_k]
            int j = i - OKV, k = j >> 9, n = j & 511;
            val = (n < 256) ? wk[k*256 + n] : wv[k*256 + (n - 256)];
        } else if (i < OW) {                 // wp2 [64,256]
            val = wp2[i - OP2];
        } else {                             // ww [256,256]
            val = ww[i - OW];
        }
        uint16_t h, l;
        split1(val, h, l);
        g_bth[i] = h; g_btl[i] = l;
    }
    if (i < 512) {
        g_bkv[i] = (i < 256) ? bk[i] : bv[i - 256];
        g_cellCnt[i] = 0;
    }
    if (i < 9) g_m[i] = 0.f;
    if (i < COUT) { g_s1[i] = 0.f; g_q1[i] = 0.f; g_s2[i] = 0.f; g_q2[i] = 0.f; }
}

// ---------------- kNN: exact grid-accelerated, integrated fallback ----------------
__device__ __forceinline__ float norm3_ref(float x, float y, float z) {
    return __fadd_rn(__fadd_rn(__fmul_rn(x, x), __fmul_rn(y, y)), __fmul_rn(z, z));
}
__device__ __forceinline__ int gcell(float v) {
    int c = (int)(v * (float)GDIM);
    return c < 0 ? 0 : (c > GDIM-1 ? GDIM-1 : c);
}

__global__ void grid_count_kernel(const float* __restrict__ xyz_i) {
    int i = blockIdx.x * 256 + threadIdx.x;
    if (i >= N_PTS) return;
    int cx = gcell(xyz_i[i*3+0]);
    int cy = gcell(xyz_i[i*3+1]);
    int cz = gcell(xyz_i[i*3+2]);
    atomicAdd(&g_cellCnt[(cz*GDIM + cy)*GDIM + cx], 1);
}
__global__ void grid_scan_kernel() {
    __shared__ int s[GCELLS];
    int t = threadIdx.x;                  // 512
    int own = g_cellCnt[t];
    s[t] = own;
    __syncthreads();
    for (int off = 1; off < GCELLS; off <<= 1) {
        int u = 0;
        if (t >= off) u = s[t - off];
        __syncthreads();
        s[t] += u;
        __syncthreads();
    }
    g_cellStart[t] = s[t] - own;          // exclusive
    if (t == GCELLS-1) g_cellStart[GCELLS] = N_PTS;
    g_cellFill[t] = 0;
}
__global__ void grid_scatter_kernel(const float* __restrict__ xyz_i) {
    int i = blockIdx.x * 256 + threadIdx.x;
    if (i >= N_PTS) return;
    float x = xyz_i[i*3+0], y = xyz_i[i*3+1], z = xyz_i[i*3+2];
    int cell = (gcell(z)*GDIM + gcell(y))*GDIM + gcell(x);
    int pos = g_cellStart[cell] + atomicAdd(&g_cellFill[cell], 1);
    g_spts[pos] = make_float4(x, y, z, norm3_ref(x, y, z));
    g_sidx[pos] = i;
}

// warp per query: grid cells within KRAD; exact d2; lexicographic top-16;
// integrated exact fallback (full scan over sorted array) if radius insufficient.
__global__ void knn_grid_kernel(const float* __restrict__ xyz_last) {
    __shared__ float ld[QPB][KNN][32];
    __shared__ int   li[QPB][KNN][32];
    const int tid = threadIdx.x;
    const int w = tid >> 5, lane = tid & 31;
    const int q = blockIdx.x * QPB + w;
    const float qx = xyz_last[q*3+0];
    const float qy = xyz_last[q*3+1];
    const float qz = xyz_last[q*3+2];
    const float nq = norm3_ref(qx, qy, qz);
    const float cw = 1.f / (float)GDIM;

    float dist[KNN];
    int   idx [KNN];
#pragma unroll
    for (int j = 0; j < KNN; j++) { dist[j] = FLT_MAX; idx[j] = 0x7fffffff; }

    int zlo = (int)floorf((qz - KRAD) * (float)GDIM); if (zlo < 0) zlo = 0;
    int zhi = (int)floorf((qz + KRAD) * (float)GDIM); if (zhi > GDIM-1) zhi = GDIM-1;
    int ylo = (int)floorf((qy - KRAD) * (float)GDIM); if (ylo < 0) ylo = 0;
    int yhi = (int)floorf((qy + KRAD) * (float)GDIM); if (yhi > GDIM-1) yhi = GDIM-1;

    for (int z = zlo; z <= zhi; z++) {
        float dz = fmaxf(0.f, fmaxf((float)z * cw - qz, qz - (float)(z+1) * cw));
        float dz2 = dz * dz;
        for (int y = ylo; y <= yhi; y++) {
            float dy = fmaxf(0.f, fmaxf((float)y * cw - qy, qy - (float)(y+1) * cw));
            float dyz2 = dz2 + dy * dy;
            if (dyz2 > KRAD2) continue;
            float xr = sqrtf(KRAD2 - dyz2) + 1e-6f;
            int xlo = (int)floorf((qx - xr) * (float)GDIM); if (xlo < 0) xlo = 0;
            int xhi = (int)floorf((qx + xr) * (float)GDIM); if (xhi > GDIM-1) xhi = GDIM-1;
            int base = (z*GDIM + y)*GDIM;
            int s = g_cellStart[base + xlo];
            int e = g_cellStart[base + xhi + 1];
            for (int i = s + lane; i < e; i += 32) {
                float4 pv = g_spts[i];
                float t = __fmul_rn(qx, pv.x);
                t = __fmaf_rn(qy, pv.y, t);
                t = __fmaf_rn(qz, pv.z, t);
                float d2 = __fsub_rn(__fadd_rn(nq, pv.w), __fmul_rn(2.0f, t));
                int gi = g_sidx[i];
                bool ins = (d2 < dist[KNN-1]) || (d2 == dist[KNN-1] && gi < idx[KNN-1]);
                if (ins) {
                    dist[KNN-1] = d2;
                    idx[KNN-1]  = gi;
#pragma unroll
                    for (int j = KNN-1; j > 0; j--) {
                        float da = dist[j-1], db = dist[j];
                        int   ia = idx[j-1],  ib = idx[j];
                        bool sw = (db < da) || (db == da && ib < ia);
                        dist[j-1] = sw ? db : da;
                        dist[j]   = sw ? da : db;
                        idx[j-1]  = sw ? ib : ia;
                        idx[j]    = sw ? ia : ib;
                    }
                }
            }
        }
    }
#pragma unroll
    for (int j = 0; j < KNN; j++) { ld[w][j][lane] = dist[j]; li[w][j][lane] = idx[j]; }
    __syncwarp();

    int pos = 0;
    float last_v = FLT_MAX;
    for (int r = 0; r < KNN; r++) {
        float v = (pos < KNN) ? ld[w][pos][lane] : FLT_MAX;
        int  gi = (pos < KNN) ? li[w][pos][lane] : 0x7fffffff;
        int  owner = lane;
#pragma unroll
        for (int off = 16; off > 0; off >>= 1) {
            float v2  = __shfl_xor_sync(0xffffffffu, v, off);
            int   g2  = __shfl_xor_sync(0xffffffffu, gi, off);
            int   o2  = __shfl_xor_sync(0xffffffffu, owner, off);
            if (v2 < v || (v2 == v && g2 < gi)) { v = v2; gi = g2; owner = o2; }
        }
        if (lane == 0) g_idx[q*KNN + r] = gi;
        last_v = v;
        if (lane == owner) pos++;
    }
    // soundness: all non-enumerated points have d2 > KRAD2 (minus fp slack)
    if (!(last_v + 1e-4f < KRAD2)) {
        // exact fallback: full scan over sorted array (warp-local, rare)
#pragma unroll
        for (int j = 0; j < KNN; j++) { dist[j] = FLT_MAX; idx[j] = 0x7fffffff; }
        for (int i = lane; i < N_PTS; i += 32) {
            float4 pv = g_spts[i];
            float t = __fmul_rn(qx, pv.x);
            t = __fmaf_rn(qy, pv.y, t);
            t = __fmaf_rn(qz, pv.z, t);
            float d2 = __fsub_rn(__fadd_rn(nq, pv.w), __fmul_rn(2.0f, t));
            int gi = g_sidx[i];
            bool ins = (d2 < dist[KNN-1]) || (d2 == dist[KNN-1] && gi < idx[KNN-1]);
            if (ins) {
                dist[KNN-1] = d2;
                idx[KNN-1]  = gi;
#pragma unroll
                for (int j = KNN-1; j > 0; j--) {
                    float da = dist[j-1], db = dist[j];
                    int   ia = idx[j-1],  ib = idx[j];
                    bool sw = (db < da) || (db == da && ib < ia);
                    dist[j-1] = sw ? db : da;
                    dist[j]   = sw ? da : db;
                    idx[j-1]  = sw ? ib : ia;
                    idx[j]    = sw ? ia : ib;
                }
            }
        }
#pragma unroll
        for (int j = 0; j < KNN; j++) { ld[w][j][lane] = dist[j]; li[w][j][lane] = idx[j]; }
        __syncwarp();
        pos = 0;
        for (int r = 0; r < KNN; r++) {
            float v = (pos < KNN) ? ld[w][pos][lane] : FLT_MAX;
            int  gi = (pos < KNN) ? li[w][pos][lane] : 0x7fffffff;
            int  owner = lane;
#pragma unroll
            for (int off = 16; off > 0; off >>= 1) {
                float v2  = __shfl_xor_sync(0xffffffffu, v, off);
                int   g2  = __shfl_xor_sync(0xffffffffu, gi, off);
                int   o2  = __shfl_xor_sync(0xffffffffu, owner, off);
                if (v2 < v || (v2 == v && g2 < gi)) { v = v2; gi = g2; owner = o2; }
            }
            if (lane == 0) g_idx[q*KNN + r] = gi;
            if (lane == owner) pos++;
        }
    }
}

// ---------------- pe4 moments ----------------
__global__ void moments_kernel(const float* __restrict__ xyz_i,
                               const float* __restrict__ xyz_last) {
    float a0=0,a1=0,a2=0,a3=0,a4=0,a5=0,a6=0,a7=0,a8=0;
    for (int s = blockIdx.x * 256 + threadIdx.x; s < NK; s += gridDim.x * 256) {
        int n = s >> 4;
        int j = g_idx[s];
        float x = xyz_i[j*3+0] - xyz_last[n*3+0];
        float y = xyz_i[j*3+1] - xyz_last[n*3+1];
        float z = xyz_i[j*3+2] - xyz_last[n*3+2];
        a0 += x; a1 += y; a2 += z;
        a3 = fmaf(x,x,a3); a4 = fmaf(y,y,a4); a5 = fmaf(z,z,a5);
        a6 = fmaf(x,y,a6); a7 = fmaf(x,z,a7); a8 = fmaf(y,z,a8);
    }
    float v[9] = {a0,a1,a2,a3,a4,a5,a6,a7,a8};
#pragma unroll
    for (int i = 0; i < 9; i++) {
#pragma unroll
        for (int off = 16; off > 0; off >>= 1)
            v[i] += __shfl_xor_sync(0xffffffffu, v[i], off);
    }
    if ((threadIdx.x & 31) == 0) {
#pragma unroll
        for (int i = 0; i < 9; i++) atomicAdd(&g_m[i], v[i]);
    }
}

// ---------------- mma.sync GEMM (round-8 proven mainloop), 512 threads ----------
// MODE 0: plain; MODE 1: A generated from xyz (pe), BN-pe affine inline from g_m,
//         C := w1 = q - kf[idx] + pe, BN1 stats;
// MODE 2: f = lrelu(x*bn1) with bn1 affine inline from g_s1/g_q1, C := w2, BN2 stats
template<int MODE>
__global__ __launch_bounds__(512, 1)
void mma_gemm(const float* __restrict__ A,
              const uint16_t* __restrict__ Bth, const uint16_t* __restrict__ Btl,
              const float* __restrict__ bias, float* __restrict__ C,
              int M, int N, int K,
              const float* __restrict__ xyz_i, const float* __restrict__ xyz_last,
              const float* __restrict__ t_i, const float* __restrict__ t_last,
              const float* __restrict__ wp1, const float* __restrict__ bp1,
              const float* __restrict__ gma, const float* __restrict__ bta) {
    __shared__ __align__(16) uint16_t Ah[128*ASTR], Al[128*ASTR];
    __shared__ __align__(16) uint16_t Bh[32*BSTR], Bl[32*BSTR];
    __shared__ float spx[128], spy[128], spz[128];
    __shared__ float swp[256], sbp[64], sps[64], ssh[64];
    __shared__ float ssc[256], ssh2[256];
    __shared__ float sbias[128], sstatS[128], sstatQ[128];

    const int tid = threadIdx.x;
    const int lane = tid & 31, wid = tid >> 5;
    const int wm = wid >> 2, wn = wid & 3;          // 4x4 warp grid, 32x32 tiles
    const int m0 = blockIdx.y * 128, n0 = blockIdx.x * 128;

    float dtv = 0.f;
    if (MODE == 1) {
        if (tid < 128) {
            int m = m0 + tid;
            int n = m >> 4;
            int j = g_idx[m];
            spx[tid] = xyz_i[j*3+0] - xyz_last[n*3+0];
            spy[tid] = xyz_i[j*3+1] - xyz_last[n*3+1];
            spz[tid] = xyz_i[j*3+2] - xyz_last[n*3+2];
        }
        if (tid < 256) swp[tid] = wp1[tid];
        dtv = t_i[0] - t_last[0];
        if (tid < 64) {
            // inline finalize_pe: analytic BN over generated h
            float inv = 1.f / (float)NK;
            float mx = g_m[0]*inv, my = g_m[1]*inv, mz = g_m[2]*inv;
            float exx = g_m[3]*inv, eyy = g_m[4]*inv, ezz = g_m[5]*inv;
            float exy = g_m[6]*inv, exz = g_m[7]*inv, eyz = g_m[8]*inv;
            float w0 = wp1[tid], w1 = wp1[64+tid], w2 = wp1[128+tid], w3 = wp1[192+tid];
            float a  = bp1[tid] + w3*dtv;
            float lm = w0*mx + w1*my + w2*mz;
            float mean = a + lm;
            float e2 = a*a + 2.f*a*lm
                     + w0*w0*exx + w1*w1*eyy + w2*w2*ezz
                     + 2.f*(w0*w1*exy + w0*w2*exz + w1*w2*eyz);
            float var = e2 - mean*mean;
            float s = gma[tid] * rsqrtf(var + EPS);
            sps[tid] = s;
            ssh[tid] = bta[tid] - mean*s;
            sbp[tid] = bp1[tid];
        }
    }
    if (MODE == 2 && tid < 256) {
        // inline finalize BN1
        float inv = 1.f / (float)NK;
        float m = g_s1[tid] * inv;
        float v = g_q1[tid] * inv - m*m;
        float s = gma[tid] * rsqrtf(v + EPS);
        ssc[tid]  = s;
        ssh2[tid] = bta[tid] - m*s;
    }
    if (tid < 128) { sbias[tid] = bias[n0 + tid]; sstatS[tid] = 0.f; sstatQ[tid] = 0.f; }
    if (MODE == 1 || MODE == 2) __syncthreads();

    float acc[2][4][4];
#pragma unroll
    for (int i = 0; i < 2; i++)
#pragma unroll
        for (int j = 0; j < 4; j++)
#pragma unroll
            for (int e = 0; e < 4; e++) acc[i][j][e] = 0.f;

    const int arow = tid >> 2, ac = (tid & 3) * 8;     // A: 128 rows x 32 k
    const int brow = tid >> 4, bc = (tid & 15) * 8;    // B: 32 k-rows x 128 n

    // prefetch stage 0
    float4 a0r, a1r;
    uint4 bhr, blr;
    if (MODE != 1) {
        a0r = *(const float4*)(A + (size_t)(m0 + arow)*K + ac);
        a1r = *(const float4*)(A + (size_t)(m0 + arow)*K + ac + 4);
    }
    bhr = *(const uint4*)(Bth + (size_t)brow*N + n0 + bc);
    blr = *(const uint4*)(Btl + (size_t)brow*N + n0 + bc);

    const uint32_t AhB = su32(Ah), AlB = su32(Al), BhB = su32(Bh), BlB = su32(Bl);
    uint32_t a_off[2], b_off[2];
#pragma unroll
    for (int mt = 0; mt < 2; mt++)
        a_off[mt] = (uint32_t)(((wm*32 + mt*16 + (lane & 15))*ASTR + (lane >> 4)*8) * 2);
#pragma unroll
    for (int p = 0; p < 2; p++)
        b_off[p] = (uint32_t)(((lane & 15)*BSTR + wn*32 + p*16 + (lane >> 4)*8) * 2);

    const int nst = K >> 5;
    for (int kt = 0; kt < nst; kt++) {
        const int kb = kt * 32;
        if (MODE == 1) {
            float px = spx[arow], py = spy[arow], pz = spz[arow];
            float v[8];
#pragma unroll
            for (int e = 0; e < 8; e++) {
                int c = kb + ac + e;
                float hh = sbp[c];
                hh = fmaf(px,  swp[c],     hh);
                hh = fmaf(py,  swp[64+c],  hh);
                hh = fmaf(pz,  swp[128+c], hh);
                hh = fmaf(dtv, swp[192+c], hh);
                float x = fmaf(hh, sps[c], ssh[c]);
                v[e] = (x >= 0.f) ? x : SLOPE*x;
            }
            uint4 H, L;
            pack8(v, H, L);
            *(uint4*)&Ah[arow*ASTR + ac] = H;
            *(uint4*)&Al[arow*ASTR + ac] = L;
        } else {
            float v[8] = {a0r.x, a0r.y, a0r.z, a0r.w, a1r.x, a1r.y, a1r.z, a1r.w};
            if (MODE == 2) {
                int c = kb + ac;
#pragma unroll
                for (int e = 0; e < 8; e++) {
                    float x = fmaf(v[e], ssc[c+e], ssh2[c+e]);
                    v[e] = (x >= 0.f) ? x : SLOPE*x;
                }
            }
            uint4 H, L;
            pack8(v, H, L);
            *(uint4*)&Ah[arow*ASTR + ac] = H;
            *(uint4*)&Al[arow*ASTR + ac] = L;
        }
        *(uint4*)&Bh[brow*BSTR + bc] = bhr;
        *(uint4*)&Bl[brow*BSTR + bc] = blr;
        __syncthreads();

        if (kt + 1 < nst) {
            const int kn = kb + 32;
            if (MODE != 1) {
                a0r = *(const float4*)(A + (size_t)(m0 + arow)*K + kn + ac);
                a1r = *(const float4*)(A + (size_t)(m0 + arow)*K + kn + ac + 4);
            }
            bhr = *(const uint4*)(Bth + (size_t)(kn + brow)*N + n0 + bc);
            blr = *(const uint4*)(Btl + (size_t)(kn + brow)*N + n0 + bc);
        }

#pragma unroll
        for (int ko = 0; ko < 2; ko++) {
            uint32_t ah[2][4], al_[2][4];
#pragma unroll
            for (int mt = 0; mt < 2; mt++) {
                ldsm4(ah[mt],  AhB + a_off[mt] + ko*32);
                ldsm4(al_[mt], AlB + a_off[mt] + ko*32);
            }
            uint32_t bh[4][2], bl[4][2];
#pragma unroll
            for (int p = 0; p < 2; p++) {
                uint32_t r[4];
                ldsm4t(r, BhB + b_off[p] + ko*16*BSTR*2);
                bh[2*p][0] = r[0]; bh[2*p][1] = r[1];
                bh[2*p+1][0] = r[2]; bh[2*p+1][1] = r[3];
                ldsm4t(r, BlB + b_off[p] + ko*16*BSTR*2);
                bl[2*p][0] = r[0]; bl[2*p][1] = r[1];
                bl[2*p+1][0] = r[2]; bl[2*p+1][1] = r[3];
            }
#pragma unroll
            for (int mt = 0; mt < 2; mt++)
#pragma unroll
                for (int nt = 0; nt < 4; nt++) {
                    mma16816(acc[mt][nt], ah[mt],  bh[nt]);
                    mma16816(acc[mt][nt], ah[mt],  bl[nt]);
                    mma16816(acc[mt][nt], al_[mt], bh[nt]);
                }
        }
        __syncthreads();
    }

    // ---- epilogue ----
    float colS[8], colQ[8];
#pragma unroll
    for (int i = 0; i < 8; i++) { colS[i] = 0.f; colQ[i] = 0.f; }

#pragma unroll
    for (int mt = 0; mt < 2; mt++) {
        int r0 = m0 + wm*32 + mt*16 + (lane >> 2);
        int r1 = r0 + 8;
        int j0 = 0, j1 = 0, p0 = 0, p1 = 0;
        if (MODE == 1) {
            j0 = g_idx[r0]; j1 = g_idx[r1];
            p0 = r0 >> 4;   p1 = r1 >> 4;
        }
#pragma unroll
        for (int nt = 0; nt < 4; nt++) {
            int cl = wn*32 + nt*8 + (lane & 3)*2;      // local col in [0,128)
            int c = n0 + cl;
            float v00 = acc[mt][nt][0] + sbias[cl],   v01 = acc[mt][nt][1] + sbias[cl+1];
            float v10 = acc[mt][nt][2] + sbias[cl],   v11 = acc[mt][nt][3] + sbias[cl+1];
            if (MODE == 1) {
                float2 q0 = *(const float2*)(g_q  + (size_t)p0*256 + c);
                float2 q1 = *(const float2*)(g_q  + (size_t)p1*256 + c);
                float2 k0 = *(const float2*)(g_kv + (size_t)j0*512 + c);
                float2 k1 = *(const float2*)(g_kv + (size_t)j1*512 + c);
                v00 = q0.x - k0.x + v00; v01 = q0.y - k0.y + v01;
                v10 = q1.x - k1.x + v10; v11 = q1.y - k1.y + v11;
            }
            *(float2*)(C + (size_t)r0*N + c) = make_float2(v00, v01);
            *(float2*)(C + (size_t)r1*N + c) = make_float2(v10, v11);
            if (MODE != 0) {
                colS[nt*2+0] += v00 + v10;  colS[nt*2+1] += v01 + v11;
                colQ[nt*2+0] += v00*v00 + v10*v10;
                colQ[nt*2+1] += v01*v01 + v11*v11;
            }
        }
    }
    if (MODE != 0) {
#pragma unroll
        for (int i = 0; i < 8; i++) {
#pragma unroll
            for (int off = 4; off <= 16; off <<= 1) {
                colS[i] += __shfl_xor_sync(0xffffffffu, colS[i], off);
                colQ[i] += __shfl_xor_sync(0xffffffffu, colQ[i], off);
            }
        }
        if (lane < 4) {
#pragma unroll
            for (int nt = 0; nt < 4; nt++) {
#pragma unroll
                for (int j = 0; j < 2; j++) {
                    int cl = wn*32 + nt*8 + lane*2 + j;
                    atomicAdd(&sstatS[cl], colS[nt*2+j]);
                    atomicAdd(&sstatQ[cl], colQ[nt*2+j]);
                }
            }
        }
        __syncthreads();
        if (tid < 128) {
            float* gS = (MODE == 1) ? g_s1 : g_s2;
            float* gQ = (MODE == 1) ? g_q1 : g_q2;
            atomicAdd(&gS[n0 + tid], sstatS[tid]);
            atomicAdd(&gQ[n0 + tid], sstatQ[tid]);
        }
    }
}

// ---------------- final: inline BN2 finalize + lrelu + softmax(K) + v-sum ------
__global__ void final_kernel(float* __restrict__ out,
                             const float* __restrict__ gw2, const float* __restrict__ bw2) {
    int n = blockIdx.x, c = threadIdx.x;
    __shared__ int sidx[KNN];
    if (c < KNN) sidx[c] = g_idx[n*KNN + c];
    __syncthreads();
    float inv = 1.f / (float)NK;
    float mm = g_s2[c] * inv;
    float vv = g_q2[c] * inv - mm*mm;
    float sc = gw2[c] * rsqrtf(vv + EPS);
    float sh = bw2[c] - mm*sc;
    float qv = g_q[(size_t)n*COUT + c];
    float z[KNN], w1v[KNN];
    float m = -FLT_MAX;
#pragma unroll
    for (int k = 0; k < KNN; k++) {
        float x = g_w2[((size_t)n*KNN + k)*COUT + c];
        w1v[k] = g_w1[((size_t)n*KNN + k)*COUT + c];
        x = x*sc + sh;
        x = (x >= 0.f) ? x : SLOPE*x;
        z[k] = x;
        m = fmaxf(m, x);
    }
    float den = 0.f, num = 0.f;
#pragma unroll
    for (int k = 0; k < KNN; k++) {
        float e = __expf(z[k] - m);
        const float* kvrow = g_kv + (size_t)sidx[k]*512;
        float v = kvrow[256 + c] + (w1v[k] - qv + kvrow[c]);
        den += e;
        num = fmaf(e, v, num);
    }
    out[(size_t)n*COUT + c] = num / den;
}

// ---------------- launch ----------------
extern "C" void kernel_launch(void* const* d_in, const int* in_sizes, int n_in,
                              void* d_out, int out_size) {
    const float* fea_i    = (const float*)d_in[0];
    const float* fea_last = (const float*)d_in[1];
    const float* xyz_i    = (const float*)d_in[2];
    const float* xyz_last = (const float*)d_in[3];
    const float* t_i      = (const float*)d_in[4];
    const float* t_last   = (const float*)d_in[5];
    const float* wp1 = (const float*)d_in[6];
    const float* bp1 = (const float*)d_in[7];
    const float* gp  = (const float*)d_in[8];
    const float* bp  = (const float*)d_in[9];
    const float* wp2 = (const float*)d_in[10];
    const float* bp2 = (const float*)d_in[11];
    const float* wq  = (const float*)d_in[12];
    const float* bq  = (const float*)d_in[13];
    const float* wk  = (const float*)d_in[14];
    const float* bk  = (const float*)d_in[15];
    const float* wv  = (const float*)d_in[16];
    const float* bv  = (const float*)d_in[17];
    const float* gw1 = (const float*)d_in[18];
    const float* bw1 = (const float*)d_in[19];
    const float* ww  = (const float*)d_in[20];
    const float* bw  = (const float*)d_in[21];
    const float* gw2 = (const float*)d_in[22];
    const float* bw2 = (const float*)d_in[23];
    float* out = (float*)d_out;

    void* p;
    cudaGetSymbolAddress(&p, g_q);   float* p_q   = (float*)p;
    cudaGetSymbolAddress(&p, g_kv);  float* p_kv  = (float*)p;
    cudaGetSymbolAddress(&p, g_bkv); float* p_bkv = (float*)p;
    cudaGetSymbolAddress(&p, g_bth); uint16_t* p_bth = (uint16_t*)p;
    cudaGetSymbolAddress(&p, g_btl); uint16_t* p_btl = (uint16_t*)p;
    cudaGetSymbolAddress(&p, g_w1);  float* p_w1  = (float*)p;
    cudaGetSymbolAddress(&p, g_w2);  float* p_w2  = (float*)p;

    // 0) prep (weight split + bias + stat zero + grid zero)
    prep_kernel<<<(TOTW + 255)/256, 256>>>(wq, wk, wv, wp2, ww, bk, bv);

    // 1) kNN: grid build -> grid query (with integrated exact fallback)
    grid_count_kernel<<<N_PTS/256, 256>>>(xyz_i);
    grid_scan_kernel<<<1, 512>>>();
    grid_scatter_kernel<<<N_PTS/256, 256>>>(xyz_i);
    knn_grid_kernel<<<N_PTS/QPB, 256>>>(xyz_last);

    // 2) projections
    mma_gemm<0><<<dim3(2, 64), 512>>>(fea_last, p_bth + OQ,  p_btl + OQ,  bq,    p_q,  N_PTS, 256, CIN,
                                      nullptr, nullptr, nullptr, nullptr, nullptr, nullptr, nullptr, nullptr);
    mma_gemm<0><<<dim3(4, 64), 512>>>(fea_i,    p_bth + OKV, p_btl + OKV, p_bkv, p_kv, N_PTS, 512, CIN,
                                      nullptr, nullptr, nullptr, nullptr, nullptr, nullptr, nullptr, nullptr);

    // 3) pe4 moments (analytic BN stats; finalize inlined in mma_gemm<1>)
    moments_kernel<<<64, 256>>>(xyz_i, xyz_last);

    // 4) pe GEMM (A generated) -> w1 = q - kf + pe, + BN1 stats
    mma_gemm<1><<<dim3(2, 1024), 512>>>(nullptr, p_bth + OP2, p_btl + OP2, bp2, p_w1, NK, 256, HDIM,
                                        xyz_i, xyz_last, t_i, t_last, wp1, bp1, gp, bp);

    // 5) w2 GEMM (BN1 finalize inlined) + BN2 stats
    mma_gemm<2><<<dim3(2, 1024), 512>>>(p_w1, p_bth + OW, p_btl + OW, bw, p_w2, NK, 256, CIN,
                                        nullptr, nullptr, nullptr, nullptr, nullptr, nullptr, gw1, bw1);

    // 6) softmax over K + weighted v-sum (BN2 finalize inlined)
    final_kernel<<<N_PTS, COUT>>>(out, gw2, bw2);
}

// round 11
// speedup vs baseline: 1.0674x; 1.0116x over previous
#include <cuda_runtime.h>
#include <cuda_bf16.h>
#include <cstdint>
#include <cfloat>

#define N_PTS 8192
#define KNN   16
#define CIN   256
#define COUT  256
#define NK    (N_PTS*KNN)       // 131072
#define HDIM  64
#define SLOPE 0.01f
#define EPS   1e-5f
#define QPB   8
#define ASTR  40                // A smem row stride in halves
#define BSTR  136               // B smem row stride in halves

// kNN grid params
#define GDIM  8
#define GCELLS (GDIM*GDIM*GDIM)   // 512
#define KRAD  0.25f
#define KRAD2 0.0625f

// weight-split buffer offsets (natural [K,N] layout, bf16 hi/lo)
#define OQ   0
#define OKV  65536              // 256*256
#define OP2  196608             // + 256*512
#define OW   212992             // + 64*256
#define TOTW 278528             // + 256*256

// ---------------- device scratch (static, allocation-free) ----------------
__device__ int      g_idx[NK];
__device__ float    g_q  [N_PTS*COUT];
__device__ float    g_kv [N_PTS*512];     // [kf | vf]
__device__ float    g_u  [N_PTS*COUT];    // kf + vf (for final)
__device__ float    g_bkv[512];
__device__ uint16_t g_bth[TOTW];          // weights bf16 hi, [K,N]
__device__ uint16_t g_btl[TOTW];          // weights bf16 lo, [K,N]
__device__ float    g_w1 [NK*COUT];
__device__ float    g_w2 [NK*COUT];
__device__ float    g_m[9];               // pe4 moments
__device__ float    g_s1[COUT], g_q1[COUT];
__device__ float    g_s2[COUT], g_q2[COUT];
// grid structures
__device__ int      g_cellCnt[GCELLS];
__device__ int      g_cellFill[GCELLS];
__device__ int      g_cellStart[GCELLS+1];
__device__ float4   g_spts[N_PTS];
__device__ int      g_sidx[N_PTS];

// ---------------- PTX helpers ----------------
__device__ __forceinline__ uint32_t su32(const void* p) {
    return (uint32_t)__cvta_generic_to_shared(p);
}
__device__ __forceinline__ void ldsm4(uint32_t r[4], uint32_t a) {
    asm volatile("ldmatrix.sync.aligned.m8n8.x4.shared.b16 {%0,%1,%2,%3}, [%4];"
        : "=r"(r[0]), "=r"(r[1]), "=r"(r[2]), "=r"(r[3]) : "r"(a));
}
__device__ __forceinline__ void ldsm4t(uint32_t r[4], uint32_t a) {
    asm volatile("ldmatrix.sync.aligned.m8n8.x4.trans.shared.b16 {%0,%1,%2,%3}, [%4];"
        : "=r"(r[0]), "=r"(r[1]), "=r"(r[2]), "=r"(r[3]) : "r"(a));
}
__device__ __forceinline__ void mma16816(float c[4], const uint32_t a[4], const uint32_t b[2]) {
    asm volatile("mma.sync.aligned.m16n8k16.row.col.f32.bf16.bf16.f32 "
        "{%0,%1,%2,%3}, {%4,%5,%6,%7}, {%8,%9}, {%0,%1,%2,%3};"
        : "+f"(c[0]), "+f"(c[1]), "+f"(c[2]), "+f"(c[3])
        : "r"(a[0]), "r"(a[1]), "r"(a[2]), "r"(a[3]), "r"(b[0]), "r"(b[1]));
}
__device__ __forceinline__ void split1(float x, uint16_t& hi, uint16_t& lo) {
    __nv_bfloat16 h = __float2bfloat16_rn(x);
    __nv_bfloat16 l = __float2bfloat16_rn(x - __bfloat162float(h));
    hi = *(uint16_t*)&h; lo = *(uint16_t*)&l;
}
// vectorized: per 2 elements one cvt.rn.bf16x2.f32 for hi and one for lo
__device__ __forceinline__ void pack8(const float* v, uint4& H, uint4& L) {
    uint32_t* hp = (uint32_t*)&H;
    uint32_t* lp = (uint32_t*)&L;
#pragma unroll
    for (int i = 0; i < 4; i++) {
        float x0 = v[2*i], x1 = v[2*i+1];
        __nv_bfloat162 h2 = __floats2bfloat162_rn(x0, x1);
        float h0 = __low2float(h2), h1 = __high2float(h2);
        __nv_bfloat162 l2 = __floats2bfloat162_rn(x0 - h0, x1 - h1);
        hp[i] = *(uint32_t*)&h2;
        lp[i] = *(uint32_t*)&l2;
    }
}

// ---------------- prep: weight split + bias concat + zero stats + grid zero ----
__global__ void prep_kernel(const float* __restrict__ wq,
                            const float* __restrict__ wk, const float* __restrict__ wv,
                            const float* __restrict__ wp2, const float* __restrict__ ww,
                            const float* __restrict__ bk, const float* __restrict__ bv) {
    int i = blockIdx.x * 256 + threadIdx.x;
    if (i < TOTW) {
        float val;
        if (i < OKV) {                       // wq [256,256]
            val = wq[i];
        } else if (i < OP2) {                // wkv [256,512]: row k = [wk_k | wv_k]
            int j = i - OKV, k = j >> 9, n = j & 511;
            val = (n < 256) ? wk[k*256 + n] : wv[k*256 + (n - 256)];
        } else if (i < OW) {                 // wp2 [64,256]
            val = wp2[i - OP2];
        } else {                             // ww [256,256]
            val = ww[i - OW];
        }
        uint16_t h, l;
        split1(val, h, l);
        g_bth[i] = h; g_btl[i] = l;
    }
    if (i < 512) {
        g_bkv[i] = (i < 256) ? bk[i] : bv[i - 256];
        g_cellCnt[i] = 0;
    }
    if (i < 9) g_m[i] = 0.f;
    if (i < COUT) { g_s1[i] = 0.f; g_q1[i] = 0.f; g_s2[i] = 0.f; g_q2[i] = 0.f; }
}

// ---------------- u = kf + vf ----------------
__global__ void u_kernel() {
    int i = blockIdx.x * 256 + threadIdx.x;     // N_PTS*256
    int r = i >> 8, c = i & 255;
    g_u[i] = g_kv[(size_t)r*512 + c] + g_kv[(size_t)r*512 + 256 + c];
}

// ---------------- kNN: exact grid-accelerated, integrated fallback ----------------
__device__ __forceinline__ float norm3_ref(float x, float y, float z) {
    return __fadd_rn(__fadd_rn(__fmul_rn(x, x), __fmul_rn(y, y)), __fmul_rn(z, z));
}
__device__ __forceinline__ int gcell(float v) {
    int c = (int)(v * (float)GDIM);
    return c < 0 ? 0 : (c > GDIM-1 ? GDIM-1 : c);
}

__global__ void grid_count_kernel(const float* __restrict__ xyz_i) {
    int i = blockIdx.x * 256 + threadIdx.x;
    if (i >= N_PTS) return;
    int cx = gcell(xyz_i[i*3+0]);
    int cy = gcell(xyz_i[i*3+1]);
    int cz = gcell(xyz_i[i*3+2]);
    atomicAdd(&g_cellCnt[(cz*GDIM + cy)*GDIM + cx], 1);
}
__global__ void grid_scan_kernel() {
    __shared__ int s[GCELLS];
    int t = threadIdx.x;                  // 512
    int own = g_cellCnt[t];
    s[t] = own;
    __syncthreads();
    for (int off = 1; off < GCELLS; off <<= 1) {
        int u = 0;
        if (t >= off) u = s[t - off];
        __syncthreads();
        s[t] += u;
        __syncthreads();
    }
    g_cellStart[t] = s[t] - own;          // exclusive
    if (t == GCELLS-1) g_cellStart[GCELLS] = N_PTS;
    g_cellFill[t] = 0;
}
__global__ void grid_scatter_kernel(const float* __restrict__ xyz_i) {
    int i = blockIdx.x * 256 + threadIdx.x;
    if (i >= N_PTS) return;
    float x = xyz_i[i*3+0], y = xyz_i[i*3+1], z = xyz_i[i*3+2];
    int cell = (gcell(z)*GDIM + gcell(y))*GDIM + gcell(x);
    int pos = g_cellStart[cell] + atomicAdd(&g_cellFill[cell], 1);
    g_spts[pos] = make_float4(x, y, z, norm3_ref(x, y, z));
    g_sidx[pos] = i;
}

// warp per query: grid cells within KRAD; exact d2; lexicographic top-16;
// integrated exact fallback (full scan over sorted array) if radius insufficient.
__global__ void knn_grid_kernel(const float* __restrict__ xyz_last) {
    __shared__ float ld[QPB][KNN][32];
    __shared__ int   li[QPB][KNN][32];
    const int tid = threadIdx.x;
    const int w = tid >> 5, lane = tid & 31;
    const int q = blockIdx.x * QPB + w;
    const float qx = xyz_last[q*3+0];
    const float qy = xyz_last[q*3+1];
    const float qz = xyz_last[q*3+2];
    const float nq = norm3_ref(qx, qy, qz);
    const float cw = 1.f / (float)GDIM;

    float dist[KNN];
    int   idx [KNN];
#pragma unroll
    for (int j = 0; j < KNN; j++) { dist[j] = FLT_MAX; idx[j] = 0x7fffffff; }

    int zlo = (int)floorf((qz - KRAD) * (float)GDIM); if (zlo < 0) zlo = 0;
    int zhi = (int)floorf((qz + KRAD) * (float)GDIM); if (zhi > GDIM-1) zhi = GDIM-1;
    int ylo = (int)floorf((qy - KRAD) * (float)GDIM); if (ylo < 0) ylo = 0;
    int yhi = (int)floorf((qy + KRAD) * (float)GDIM); if (yhi > GDIM-1) yhi = GDIM-1;

    for (int z = zlo; z <= zhi; z++) {
        float dz = fmaxf(0.f, fmaxf((float)z * cw - qz, qz - (float)(z+1) * cw));
        float dz2 = dz * dz;
        for (int y = ylo; y <= yhi; y++) {
            float dy = fmaxf(0.f, fmaxf((float)y * cw - qy, qy - (float)(y+1) * cw));
            float dyz2 = dz2 + dy * dy;
            if (dyz2 > KRAD2) continue;
            float xr = sqrtf(KRAD2 - dyz2) + 1e-6f;
            int xlo = (int)floorf((qx - xr) * (float)GDIM); if (xlo < 0) xlo = 0;
            int xhi = (int)floorf((qx + xr) * (float)GDIM); if (xhi > GDIM-1) xhi = GDIM-1;
            int base = (z*GDIM + y)*GDIM;
            int s = g_cellStart[base + xlo];
            int e = g_cellStart[base + xhi + 1];
            for (int i = s + lane; i < e; i += 32) {
                float4 pv = g_spts[i];
                float t = __fmul_rn(qx, pv.x);
                t = __fmaf_rn(qy, pv.y, t);
                t = __fmaf_rn(qz, pv.z, t);
                float d2 = __fsub_rn(__fadd_rn(nq, pv.w), __fmul_rn(2.0f, t));
                int gi = g_sidx[i];
                bool ins = (d2 < dist[KNN-1]) || (d2 == dist[KNN-1] && gi < idx[KNN-1]);
                if (ins) {
                    dist[KNN-1] = d2;
                    idx[KNN-1]  = gi;
#pragma unroll
                    for (int j = KNN-1; j > 0; j--) {
                        float da = dist[j-1], db = dist[j];
                        int   ia = idx[j-1],  ib = idx[j];
                        bool sw = (db < da) || (db == da && ib < ia);
                        dist[j-1] = sw ? db : da;
                        dist[j]   = sw ? da : db;
                        idx[j-1]  = sw ? ib : ia;
                        idx[j]    = sw ? ia : ib;
                    }
                }
            }
        }
    }
#pragma unroll
    for (int j = 0; j < KNN; j++) { ld[w][j][lane] = dist[j]; li[w][j][lane] = idx[j]; }
    __syncwarp();

    int pos = 0;
    float last_v = FLT_MAX;
    for (int r = 0; r < KNN; r++) {
        float v = (pos < KNN) ? ld[w][pos][lane] : FLT_MAX;
        int  gi = (pos < KNN) ? li[w][pos][lane] : 0x7fffffff;
        int  owner = lane;
#pragma unroll
        for (int off = 16; off > 0; off >>= 1) {
            float v2  = __shfl_xor_sync(0xffffffffu, v, off);
            int   g2  = __shfl_xor_sync(0xffffffffu, gi, off);
            int   o2  = __shfl_xor_sync(0xffffffffu, owner, off);
            if (v2 < v || (v2 == v && g2 < gi)) { v = v2; gi = g2; owner = o2; }
        }
        if (lane == 0) g_idx[q*KNN + r] = gi;
        last_v = v;
        if (lane == owner) pos++;
    }
    // soundness: all non-enumerated points have d2 > KRAD2 (minus fp slack)
    if (!(last_v + 1e-4f < KRAD2)) {
        // exact fallback: full scan over sorted array (warp-local, rare)
#pragma unroll
        for (int j = 0; j < KNN; j++) { dist[j] = FLT_MAX; idx[j] = 0x7fffffff; }
        for (int i = lane; i < N_PTS; i += 32) {
            float4 pv = g_spts[i];
            float t = __fmul_rn(qx, pv.x);
            t = __fmaf_rn(qy, pv.y, t);
            t = __fmaf_rn(qz, pv.z, t);
            float d2 = __fsub_rn(__fadd_rn(nq, pv.w), __fmul_rn(2.0f, t));
            int gi = g_sidx[i];
            bool ins = (d2 < dist[KNN-1]) || (d2 == dist[KNN-1] && gi < idx[KNN-1]);
            if (ins) {
                dist[KNN-1] = d2;
                idx[KNN-1]  = gi;
#pragma unroll
                for (int j = KNN-1; j > 0; j--) {
                    float da = dist[j-1], db = dist[j];
                    int   ia = idx[j-1],  ib = idx[j];
                    bool sw = (db < da) || (db == da && ib < ia);
                    dist[j-1] = sw ? db : da;
                    dist[j]   = sw ? da : db;
                    idx[j-1]  = sw ? ib : ia;
                    idx[j]    = sw ? ia : ib;
                }
            }
        }
#pragma unroll
        for (int j = 0; j < KNN; j++) { ld[w][j][lane] = dist[j]; li[w][j][lane] = idx[j]; }
        __syncwarp();
        pos = 0;
        for (int r = 0; r < KNN; r++) {
            float v = (pos < KNN) ? ld[w][pos][lane] : FLT_MAX;
            int  gi = (pos < KNN) ? li[w][pos][lane] : 0x7fffffff;
            int  owner = lane;
#pragma unroll
            for (int off = 16; off > 0; off >>= 1) {
                float v2  = __shfl_xor_sync(0xffffffffu, v, off);
                int   g2  = __shfl_xor_sync(0xffffffffu, gi, off);
                int   o2  = __shfl_xor_sync(0xffffffffu, owner, off);
                if (v2 < v || (v2 == v && g2 < gi)) { v = v2; gi = g2; owner = o2; }
            }
            if (lane == 0) g_idx[q*KNN + r] = gi;
            if (lane == owner) pos++;
        }
    }
}

// ---------------- pe4 moments ----------------
__global__ void moments_kernel(const float* __restrict__ xyz_i,
                               const float* __restrict__ xyz_last) {
    float a0=0,a1=0,a2=0,a3=0,a4=0,a5=0,a6=0,a7=0,a8=0;
    for (int s = blockIdx.x * 256 + threadIdx.x; s < NK; s += gridDim.x * 256) {
        int n = s >> 4;
        int j = g_idx[s];
        float x = xyz_i[j*3+0] - xyz_last[n*3+0];
        float y = xyz_i[j*3+1] - xyz_last[n*3+1];
        float z = xyz_i[j*3+2] - xyz_last[n*3+2];
        a0 += x; a1 += y; a2 += z;
        a3 = fmaf(x,x,a3); a4 = fmaf(y,y,a4); a5 = fmaf(z,z,a5);
        a6 = fmaf(x,y,a6); a7 = fmaf(x,z,a7); a8 = fmaf(y,z,a8);
    }
    float v[9] = {a0,a1,a2,a3,a4,a5,a6,a7,a8};
#pragma unroll
    for (int i = 0; i < 9; i++) {
#pragma unroll
        for (int off = 16; off > 0; off >>= 1)
            v[i] += __shfl_xor_sync(0xffffffffu, v[i], off);
    }
    if ((threadIdx.x & 31) == 0) {
#pragma unroll
        for (int i = 0; i < 9; i++) atomicAdd(&g_m[i], v[i]);
    }
}

// ---------------- mma.sync GEMM (proven mainloop), 512 threads ----------
// MODE 0: plain; MODE 1: A generated from xyz (pe), BN-pe affine inline from g_m,
//         C := w1 = q - kf[idx] + pe, BN1 stats;
// MODE 2: f = lrelu(x*bn1) with bn1 affine inline from g_s1/g_q1, C := w2, BN2 stats
template<int MODE>
__global__ __launch_bounds__(512, 1)
void mma_gemm(const float* __restrict__ A,
              const uint16_t* __restrict__ Bth, const uint16_t* __restrict__ Btl,
              const float* __restrict__ bias, float* __restrict__ C,
              int M, int N, int K,
              const float* __restrict__ xyz_i, const float* __restrict__ xyz_last,
              const float* __restrict__ t_i, const float* __restrict__ t_last,
              const float* __restrict__ wp1, const float* __restrict__ bp1,
              const float* __restrict__ gma, const float* __restrict__ bta) {
    __shared__ __align__(16) uint16_t Ah[128*ASTR], Al[128*ASTR];
    __shared__ __align__(16) uint16_t Bh[32*BSTR], Bl[32*BSTR];
    __shared__ float spx[128], spy[128], spz[128];
    __shared__ float swp[256], sbp[64], sps[64], ssh[64];
    __shared__ float ssc[256], ssh2[256];
    __shared__ float sbias[128], sstatS[128], sstatQ[128];

    const int tid = threadIdx.x;
    const int lane = tid & 31, wid = tid >> 5;
    const int wm = wid >> 2, wn = wid & 3;          // 4x4 warp grid, 32x32 tiles
    const int m0 = blockIdx.y * 128, n0 = blockIdx.x * 128;

    float dtv = 0.f;
    if (MODE == 1) {
        if (tid < 128) {
            int m = m0 + tid;
            int n = m >> 4;
            int j = g_idx[m];
            spx[tid] = xyz_i[j*3+0] - xyz_last[n*3+0];
            spy[tid] = xyz_i[j*3+1] - xyz_last[n*3+1];
            spz[tid] = xyz_i[j*3+2] - xyz_last[n*3+2];
        }
        if (tid < 256) swp[tid] = wp1[tid];
        dtv = t_i[0] - t_last[0];
        if (tid < 64) {
            // inline finalize_pe: analytic BN over generated h
            float inv = 1.f / (float)NK;
            float mx = g_m[0]*inv, my = g_m[1]*inv, mz = g_m[2]*inv;
            float exx = g_m[3]*inv, eyy = g_m[4]*inv, ezz = g_m[5]*inv;
            float exy = g_m[6]*inv, exz = g_m[7]*inv, eyz = g_m[8]*inv;
            float w0 = wp1[tid], w1 = wp1[64+tid], w2 = wp1[128+tid], w3 = wp1[192+tid];
            float a  = bp1[tid] + w3*dtv;
            float lm = w0*mx + w1*my + w2*mz;
            float mean = a + lm;
            float e2 = a*a + 2.f*a*lm
                     + w0*w0*exx + w1*w1*eyy + w2*w2*ezz
                     + 2.f*(w0*w1*exy + w0*w2*exz + w1*w2*eyz);
            float var = e2 - mean*mean;
            float s = gma[tid] * rsqrtf(var + EPS);
            sps[tid] = s;
            ssh[tid] = bta[tid] - mean*s;
            sbp[tid] = bp1[tid];
        }
    }
    if (MODE == 2 && tid < 256) {
        // inline finalize BN1
        float inv = 1.f / (float)NK;
        float m = g_s1[tid] * inv;
        float v = g_q1[tid] * inv - m*m;
        float s = gma[tid] * rsqrtf(v + EPS);
        ssc[tid]  = s;
        ssh2[tid] = bta[tid] - m*s;
    }
    if (tid < 128) { sbias[tid] = bias[n0 + tid]; sstatS[tid] = 0.f; sstatQ[tid] = 0.f; }
    if (MODE == 1 || MODE == 2) __syncthreads();

    float acc[2][4][4];
#pragma unroll
    for (int i = 0; i < 2; i++)
#pragma unroll
        for (int j = 0; j < 4; j++)
#pragma unroll
            for (int e = 0; e < 4; e++) acc[i][j][e] = 0.f;

    const int arow = tid >> 2, ac = (tid & 3) * 8;     // A: 128 rows x 32 k
    const int brow = tid >> 4, bc = (tid & 15) * 8;    // B: 32 k-rows x 128 n

    // prefetch stage 0
    float4 a0r, a1r;
    uint4 bhr, blr;
    if (MODE != 1) {
        a0r = *(const float4*)(A + (size_t)(m0 + arow)*K + ac);
        a1r = *(const float4*)(A + (size_t)(m0 + arow)*K + ac + 4);
    }
    bhr = *(const uint4*)(Bth + (size_t)brow*N + n0 + bc);
    blr = *(const uint4*)(Btl + (size_t)brow*N + n0 + bc);

    const uint32_t AhB = su32(Ah), AlB = su32(Al), BhB = su32(Bh), BlB = su32(Bl);
    uint32_t a_off[2], b_off[2];
#pragma unroll
    for (int mt = 0; mt < 2; mt++)
        a_off[mt] = (uint32_t)(((wm*32 + mt*16 + (lane & 15))*ASTR + (lane >> 4)*8) * 2);
#pragma unroll
    for (int p = 0; p < 2; p++)
        b_off[p] = (uint32_t)(((lane & 15)*BSTR + wn*32 + p*16 + (lane >> 4)*8) * 2);

    const int nst = K >> 5;
    for (int kt = 0; kt < nst; kt++) {
        const int kb = kt * 32;
        if (MODE == 1) {
            float px = spx[arow], py = spy[arow], pz = spz[arow];
            float v[8];
#pragma unroll
            for (int e = 0; e < 8; e++) {
                int c = kb + ac + e;
                float hh = sbp[c];
                hh = fmaf(px,  swp[c],     hh);
                hh = fmaf(py,  swp[64+c],  hh);
                hh = fmaf(pz,  swp[128+c], hh);
                hh = fmaf(dtv, swp[192+c], hh);
                float x = fmaf(hh, sps[c], ssh[c]);
                v[e] = (x >= 0.f) ? x : SLOPE*x;
            }
            uint4 H, L;
            pack8(v, H, L);
            *(uint4*)&Ah[arow*ASTR + ac] = H;
            *(uint4*)&Al[arow*ASTR + ac] = L;
        } else {
            float v[8] = {a0r.x, a0r.y, a0r.z, a0r.w, a1r.x, a1r.y, a1r.z, a1r.w};
            if (MODE == 2) {
                int c = kb + ac;
#pragma unroll
                for (int e = 0; e < 8; e++) {
                    float x = fmaf(v[e], ssc[c+e], ssh2[c+e]);
                    v[e] = (x >= 0.f) ? x : SLOPE*x;
                }
            }
            uint4 H, L;
            pack8(v, H, L);
            *(uint4*)&Ah[arow*ASTR + ac] = H;
            *(uint4*)&Al[arow*ASTR + ac] = L;
        }
        *(uint4*)&Bh[brow*BSTR + bc] = bhr;
        *(uint4*)&Bl[brow*BSTR + bc] = blr;
        __syncthreads();

        if (kt + 1 < nst) {
            const int kn = kb + 32;
            if (MODE != 1) {
                a0r = *(const float4*)(A + (size_t)(m0 + arow)*K + kn + ac);
                a1r = *(const float4*)(A + (size_t)(m0 + arow)*K + kn + ac + 4);
            }
            bhr = *(const uint4*)(Bth + (size_t)(kn + brow)*N + n0 + bc);
            blr = *(const uint4*)(Btl + (size_t)(kn + brow)*N + n0 + bc);
        }

#pragma unroll
        for (int ko = 0; ko < 2; ko++) {
            uint32_t ah[2][4], al_[2][4];
#pragma unroll
            for (int mt = 0; mt < 2; mt++) {
                ldsm4(ah[mt],  AhB + a_off[mt] + ko*32);
                ldsm4(al_[mt], AlB + a_off[mt] + ko*32);
            }
            uint32_t bh[4][2], bl[4][2];
#pragma unroll
            for (int p = 0; p < 2; p++) {
                uint32_t r[4];
                ldsm4t(r, BhB + b_off[p] + ko*16*BSTR*2);
                bh[2*p][0] = r[0]; bh[2*p][1] = r[1];
                bh[2*p+1][0] = r[2]; bh[2*p+1][1] = r[3];
                ldsm4t(r, BlB + b_off[p] + ko*16*BSTR*2);
                bl[2*p][0] = r[0]; bl[2*p][1] = r[1];
                bl[2*p+1][0] = r[2]; bl[2*p+1][1] = r[3];
            }
#pragma unroll
            for (int mt = 0; mt < 2; mt++)
#pragma unroll
                for (int nt = 0; nt < 4; nt++) {
                    mma16816(acc[mt][nt], ah[mt],  bh[nt]);
                    mma16816(acc[mt][nt], ah[mt],  bl[nt]);
                    mma16816(acc[mt][nt], al_[mt], bh[nt]);
                }
        }
        __syncthreads();
    }

    // ---- epilogue ----
    float colS[8], colQ[8];
#pragma unroll
    for (int i = 0; i < 8; i++) { colS[i] = 0.f; colQ[i] = 0.f; }

#pragma unroll
    for (int mt = 0; mt < 2; mt++) {
        int r0 = m0 + wm*32 + mt*16 + (lane >> 2);
        int r1 = r0 + 8;
        int j0 = 0, j1 = 0, p0 = 0, p1 = 0;
        if (MODE == 1) {
            j0 = g_idx[r0]; j1 = g_idx[r1];
            p0 = r0 >> 4;   p1 = r1 >> 4;
        }
#pragma unroll
        for (int nt = 0; nt < 4; nt++) {
            int cl = wn*32 + nt*8 + (lane & 3)*2;      // local col in [0,128)
            int c = n0 + cl;
            float v00 = acc[mt][nt][0] + sbias[cl],   v01 = acc[mt][nt][1] + sbias[cl+1];
            float v10 = acc[mt][nt][2] + sbias[cl],   v11 = acc[mt][nt][3] + sbias[cl+1];
            if (MODE == 1) {
                float2 q0 = *(const float2*)(g_q  + (size_t)p0*256 + c);
                float2 q1 = *(const float2*)(g_q  + (size_t)p1*256 + c);
                float2 k0 = *(const float2*)(g_kv + (size_t)j0*512 + c);
                float2 k1 = *(const float2*)(g_kv + (size_t)j1*512 + c);
                v00 = q0.x - k0.x + v00; v01 = q0.y - k0.y + v01;
                v10 = q1.x - k1.x + v10; v11 = q1.y - k1.y + v11;
            }
            *(float2*)(C + (size_t)r0*N + c) = make_float2(v00, v01);
            *(float2*)(C + (size_t)r1*N + c) = make_float2(v10, v11);
            if (MODE != 0) {
                colS[nt*2+0] += v00 + v10;  colS[nt*2+1] += v01 + v11;
                colQ[nt*2+0] += v00*v00 + v10*v10;
                colQ[nt*2+1] += v01*v01 + v11*v11;
            }
        }
    }
    if (MODE != 0) {
#pragma unroll
        for (int i = 0; i < 8; i++) {
#pragma unroll
            for (int off = 4; off <= 16; off <<= 1) {
                colS[i] += __shfl_xor_sync(0xffffffffu, colS[i], off);
                colQ[i] += __shfl_xor_sync(0xffffffffu, colQ[i], off);
            }
        }
        if (lane < 4) {
#pragma unroll
            for (int nt = 0; nt < 4; nt++) {
#pragma unroll
                for (int j = 0; j < 2; j++) {
                    int cl = wn*32 + nt*8 + lane*2 + j;
                    atomicAdd(&sstatS[cl], colS[nt*2+j]);
                    atomicAdd(&sstatQ[cl], colQ[nt*2+j]);
                }
            }
        }
        __syncthreads();
        if (tid < 128) {
            float* gS = (MODE == 1) ? g_s1 : g_s2;
            float* gQ = (MODE == 1) ? g_q1 : g_q2;
            atomicAdd(&gS[n0 + tid], sstatS[tid]);
            atomicAdd(&gQ[n0 + tid], sstatQ[tid]);
        }
    }
}

// ---------------- final: inline BN2 finalize + lrelu + softmax(K) + v-sum ------
// v = vf[j] + pe = u[j] + (w1 - q),  u = kf + vf precomputed
__global__ void final_kernel(float* __restrict__ out,
                             const float* __restrict__ gw2, const float* __restrict__ bw2) {
    int n = blockIdx.x, c = threadIdx.x;
    __shared__ int sidx[KNN];
    if (c < KNN) sidx[c] = g_idx[n*KNN + c];
    __syncthreads();
    float inv = 1.f / (float)NK;
    float mm = g_s2[c] * inv;
    float vv = g_q2[c] * inv - mm*mm;
    float sc = gw2[c] * rsqrtf(vv + EPS);
    float sh = bw2[c] - mm*sc;
    float qv = g_q[(size_t)n*COUT + c];
    float z[KNN], w1v[KNN];
    float m = -FLT_MAX;
#pragma unroll
    for (int k = 0; k < KNN; k++) {
        float x = g_w2[((size_t)n*KNN + k)*COUT + c];
        w1v[k] = g_w1[((size_t)n*KNN + k)*COUT + c];
        x = x*sc + sh;
        x = (x >= 0.f) ? x : SLOPE*x;
        z[k] = x;
        m = fmaxf(m, x);
    }
    float den = 0.f, num = 0.f;
#pragma unroll
    for (int k = 0; k < KNN; k++) {
        float e = __expf(z[k] - m);
        float v = g_u[(size_t)sidx[k]*256 + c] + (w1v[k] - qv);
        den += e;
        num = fmaf(e, v, num);
    }
    out[(size_t)n*COUT + c] = num / den;
}

// ---------------- launch ----------------
extern "C" void kernel_launch(void* const* d_in, const int* in_sizes, int n_in,
                              void* d_out, int out_size) {
    const float* fea_i    = (const float*)d_in[0];
    const float* fea_last = (const float*)d_in[1];
    const float* xyz_i    = (const float*)d_in[2];
    const float* xyz_last = (const float*)d_in[3];
    const float* t_i      = (const float*)d_in[4];
    const float* t_last   = (const float*)d_in[5];
    const float* wp1 = (const float*)d_in[6];
    const float* bp1 = (const float*)d_in[7];
    const float* gp  = (const float*)d_in[8];
    const float* bp  = (const float*)d_in[9];
    const float* wp2 = (const float*)d_in[10];
    const float* bp2 = (const float*)d_in[11];
    const float* wq  = (const float*)d_in[12];
    const float* bq  = (const float*)d_in[13];
    const float* wk  = (const float*)d_in[14];
    const float* bk  = (const float*)d_in[15];
    const float* wv  = (const float*)d_in[16];
    const float* bv  = (const float*)d_in[17];
    const float* gw1 = (const float*)d_in[18];
    const float* bw1 = (const float*)d_in[19];
    const float* ww  = (const float*)d_in[20];
    const float* bw  = (const float*)d_in[21];
    const float* gw2 = (const float*)d_in[22];
    const float* bw2 = (const float*)d_in[23];
    float* out = (float*)d_out;

    void* p;
    cudaGetSymbolAddress(&p, g_q);   float* p_q   = (float*)p;
    cudaGetSymbolAddress(&p, g_kv);  float* p_kv  = (float*)p;
    cudaGetSymbolAddress(&p, g_bkv); float* p_bkv = (float*)p;
    cudaGetSymbolAddress(&p, g_bth); uint16_t* p_bth = (uint16_t*)p;
    cudaGetSymbolAddress(&p, g_btl); uint16_t* p_btl = (uint16_t*)p;
    cudaGetSymbolAddress(&p, g_w1);  float* p_w1  = (float*)p;
    cudaGetSymbolAddress(&p, g_w2);  float* p_w2  = (float*)p;

    // 0) prep (weight split + bias + stat zero + grid zero)
    prep_kernel<<<(TOTW + 255)/256, 256>>>(wq, wk, wv, wp2, ww, bk, bv);

    // 1) kNN: grid build -> grid query (with integrated exact fallback)
    grid_count_kernel<<<N_PTS/256, 256>>>(xyz_i);
    grid_scan_kernel<<<1, 512>>>();
    grid_scatter_kernel<<<N_PTS/256, 256>>>(xyz_i);
    knn_grid_kernel<<<N_PTS/QPB, 256>>>(xyz_last);

    // 2) projections
    mma_gemm<0><<<dim3(2, 64), 512>>>(fea_last, p_bth + OQ,  p_btl + OQ,  bq,    p_q,  N_PTS, 256, CIN,
                                      nullptr, nullptr, nullptr, nullptr, nullptr, nullptr, nullptr, nullptr);
    mma_gemm<0><<<dim3(4, 64), 512>>>(fea_i,    p_bth + OKV, p_btl + OKV, p_bkv, p_kv, N_PTS, 512, CIN,
                                      nullptr, nullptr, nullptr, nullptr, nullptr, nullptr, nullptr, nullptr);
    u_kernel<<<(N_PTS*256)/256, 256>>>();

    // 3) pe4 moments (analytic BN stats; finalize inlined in mma_gemm<1>)
    moments_kernel<<<64, 256>>>(xyz_i, xyz_last);

    // 4) pe GEMM (A generated) -> w1 = q - kf + pe, + BN1 stats
    mma_gemm<1><<<dim3(2, 1024), 512>>>(nullptr, p_bth + OP2, p_btl + OP2, bp2, p_w1, NK, 256, HDIM,
                                        xyz_i, xyz_last, t_i, t_last, wp1, bp1, gp, bp);

    // 5) w2 GEMM (BN1 finalize inlined) + BN2 stats
    mma_gemm<2><<<dim3(2, 1024), 512>>>(p_w1, p_bth + OW, p_btl + OW, bw, p_w2, NK, 256, CIN,
                                        nullptr, nullptr, nullptr, nullptr, nullptr, nullptr, gw1, bw1);

    // 6) softmax over K + weighted v-sum (BN2 finalize inlined)
    final_kernel<<<N_PTS, COUT>>>(out, gw2, bw2);
}

// round 12
// speedup vs baseline: 1.1209x; 1.0501x over previous
#include <cuda_runtime.h>
#include <cuda_bf16.h>
#include <cstdint>
#include <cfloat>

#define N_PTS 8192
#define KNN   16
#define CIN   256
#define COUT  256
#define NK    (N_PTS*KNN)       // 131072
#define HDIM  64
#define SLOPE 0.01f
#define EPS   1e-5f
#define QPB   8
#define ASTR  40                // A smem row stride in halves
#define BSTR  136               // B smem row stride in halves

// kNN grid params
#define GDIM  8
#define GCELLS (GDIM*GDIM*GDIM)   // 512
#define KRAD  0.25f
#define KRAD2 0.0625f

// weight-split buffer offsets (natural [K,N] layout, bf16 hi/lo)
#define OQ   0
#define OKV  65536              // 256*256
#define OP2  196608             // + 256*512
#define OW   212992             // + 64*256
#define TOTW 278528             // + 256*256

// ---------------- device scratch (static, allocation-free) ----------------
__device__ int      g_idx[NK];
__device__ float    g_q  [N_PTS*COUT];
__device__ float    g_kv [N_PTS*512];     // [kf | vf]
__device__ float    g_u  [N_PTS*COUT];    // kf + vf (for final)
__device__ float    g_bkv[512];
__device__ uint16_t g_bth[TOTW];          // weights bf16 hi, [K,N]
__device__ uint16_t g_btl[TOTW];          // weights bf16 lo, [K,N]
__device__ float    g_w1 [NK*COUT];
__device__ float    g_w2 [NK*COUT];
__device__ float    g_m[9];               // pe4 moments
__device__ float    g_s1[COUT], g_q1[COUT];
__device__ float    g_s2[COUT], g_q2[COUT];
// grid structures
__device__ int      g_cellCnt[GCELLS];
__device__ int      g_cellFill[GCELLS];
__device__ int      g_cellStart[GCELLS+1];
__device__ float4   g_spts[N_PTS];
__device__ int      g_sidx[N_PTS];

// ---------------- PTX helpers ----------------
__device__ __forceinline__ uint32_t su32(const void* p) {
    return (uint32_t)__cvta_generic_to_shared(p);
}
__device__ __forceinline__ void ldsm4(uint32_t r[4], uint32_t a) {
    asm volatile("ldmatrix.sync.aligned.m8n8.x4.shared.b16 {%0,%1,%2,%3}, [%4];"
        : "=r"(r[0]), "=r"(r[1]), "=r"(r[2]), "=r"(r[3]) : "r"(a));
}
__device__ __forceinline__ void ldsm4t(uint32_t r[4], uint32_t a) {
    asm volatile("ldmatrix.sync.aligned.m8n8.x4.trans.shared.b16 {%0,%1,%2,%3}, [%4];"
        : "=r"(r[0]), "=r"(r[1]), "=r"(r[2]), "=r"(r[3]) : "r"(a));
}
__device__ __forceinline__ void mma16816(float c[4], const uint32_t a[4], const uint32_t b[2]) {
    asm volatile("mma.sync.aligned.m16n8k16.row.col.f32.bf16.bf16.f32 "
        "{%0,%1,%2,%3}, {%4,%5,%6,%7}, {%8,%9}, {%0,%1,%2,%3};"
        : "+f"(c[0]), "+f"(c[1]), "+f"(c[2]), "+f"(c[3])
        : "r"(a[0]), "r"(a[1]), "r"(a[2]), "r"(a[3]), "r"(b[0]), "r"(b[1]));
}
__device__ __forceinline__ void split1(float x, uint16_t& hi, uint16_t& lo) {
    __nv_bfloat16 h = __float2bfloat16_rn(x);
    __nv_bfloat16 l = __float2bfloat16_rn(x - __bfloat162float(h));
    hi = *(uint16_t*)&h; lo = *(uint16_t*)&l;
}
// vectorized: per 2 elements one cvt.rn.bf16x2.f32 for hi and one for lo
__device__ __forceinline__ void pack8(const float* v, uint4& H, uint4& L) {
    uint32_t* hp = (uint32_t*)&H;
    uint32_t* lp = (uint32_t*)&L;
#pragma unroll
    for (int i = 0; i < 4; i++) {
        float x0 = v[2*i], x1 = v[2*i+1];
        __nv_bfloat162 h2 = __floats2bfloat162_rn(x0, x1);
        float h0 = __low2float(h2), h1 = __high2float(h2);
        __nv_bfloat162 l2 = __floats2bfloat162_rn(x0 - h0, x1 - h1);
        hp[i] = *(uint32_t*)&h2;
        lp[i] = *(uint32_t*)&l2;
    }
}

// ---------------- prep: weight split + bias concat + zero stats + grid zero ----
__global__ void prep_kernel(const float* __restrict__ wq,
                            const float* __restrict__ wk, const float* __restrict__ wv,
                            const float* __restrict__ wp2, const float* __restrict__ ww,
                            const float* __restrict__ bk, const float* __restrict__ bv) {
    int i = blockIdx.x * 256 + threadIdx.x;
    if (i < TOTW) {
        float val;
        if (i < OKV) {                       // wq [256,256]
            val = wq[i];
        } else if (i < OP2) {                // wkv [256,512]: row k = [wk_k | wv_k]
            int j = i - OKV, k = j >> 9, n = j & 511;
            val = (n < 256) ? wk[k*256 + n] : wv[k*256 + (n - 256)];
        } else if (i < OW) {                 // wp2 [64,256]
            val = wp2[i - OP2];
        } else {                             // ww [256,256]
            val = ww[i - OW];
        }
        uint16_t h, l;
        split1(val, h, l);
        g_bth[i] = h; g_btl[i] = l;
    }
    if (i < 512) {
        g_bkv[i] = (i < 256) ? bk[i] : bv[i - 256];
        g_cellCnt[i] = 0;
    }
    if (i < 9) g_m[i] = 0.f;
    if (i < COUT) { g_s1[i] = 0.f; g_q1[i] = 0.f; g_s2[i] = 0.f; g_q2[i] = 0.f; }
}

// ---------------- u = kf + vf ----------------
__global__ void u_kernel() {
    int i = blockIdx.x * 256 + threadIdx.x;     // N_PTS*256
    int r = i >> 8, c = i & 255;
    g_u[i] = g_kv[(size_t)r*512 + c] + g_kv[(size_t)r*512 + 256 + c];
}

// ---------------- kNN: exact grid-accelerated, integrated fallback ----------------
__device__ __forceinline__ float norm3_ref(float x, float y, float z) {
    return __fadd_rn(__fadd_rn(__fmul_rn(x, x), __fmul_rn(y, y)), __fmul_rn(z, z));
}
__device__ __forceinline__ int gcell(float v) {
    int c = (int)(v * (float)GDIM);
    return c < 0 ? 0 : (c > GDIM-1 ? GDIM-1 : c);
}

__global__ void grid_count_kernel(const float* __restrict__ xyz_i) {
    int i = blockIdx.x * 256 + threadIdx.x;
    if (i >= N_PTS) return;
    int cx = gcell(xyz_i[i*3+0]);
    int cy = gcell(xyz_i[i*3+1]);
    int cz = gcell(xyz_i[i*3+2]);
    atomicAdd(&g_cellCnt[(cz*GDIM + cy)*GDIM + cx], 1);
}
__global__ void grid_scan_kernel() {
    __shared__ int s[GCELLS];
    int t = threadIdx.x;                  // 512
    int own = g_cellCnt[t];
    s[t] = own;
    __syncthreads();
    for (int off = 1; off < GCELLS; off <<= 1) {
        int u = 0;
        if (t >= off) u = s[t - off];
        __syncthreads();
        s[t] += u;
        __syncthreads();
    }
    g_cellStart[t] = s[t] - own;          // exclusive
    if (t == GCELLS-1) g_cellStart[GCELLS] = N_PTS;
    g_cellFill[t] = 0;
}
__global__ void grid_scatter_kernel(const float* __restrict__ xyz_i) {
    int i = blockIdx.x * 256 + threadIdx.x;
    if (i >= N_PTS) return;
    float x = xyz_i[i*3+0], y = xyz_i[i*3+1], z = xyz_i[i*3+2];
    int cell = (gcell(z)*GDIM + gcell(y))*GDIM + gcell(x);
    int pos = g_cellStart[cell] + atomicAdd(&g_cellFill[cell], 1);
    g_spts[pos] = make_float4(x, y, z, norm3_ref(x, y, z));
    g_sidx[pos] = i;
}

// warp per query: grid cells within KRAD; exact d2; lexicographic top-16;
// integrated exact fallback (full scan over sorted array) if radius insufficient.
__global__ void knn_grid_kernel(const float* __restrict__ xyz_last) {
    __shared__ float ld[QPB][KNN][32];
    __shared__ int   li[QPB][KNN][32];
    const int tid = threadIdx.x;
    const int w = tid >> 5, lane = tid & 31;
    const int q = blockIdx.x * QPB + w;
    const float qx = xyz_last[q*3+0];
    const float qy = xyz_last[q*3+1];
    const float qz = xyz_last[q*3+2];
    const float nq = norm3_ref(qx, qy, qz);
    const float cw = 1.f / (float)GDIM;

    float dist[KNN];
    int   idx [KNN];
#pragma unroll
    for (int j = 0; j < KNN; j++) { dist[j] = FLT_MAX; idx[j] = 0x7fffffff; }

    int zlo = (int)floorf((qz - KRAD) * (float)GDIM); if (zlo < 0) zlo = 0;
    int zhi = (int)floorf((qz + KRAD) * (float)GDIM); if (zhi > GDIM-1) zhi = GDIM-1;
    int ylo = (int)floorf((qy - KRAD) * (float)GDIM); if (ylo < 0) ylo = 0;
    int yhi = (int)floorf((qy + KRAD) * (float)GDIM); if (yhi > GDIM-1) yhi = GDIM-1;

    for (int z = zlo; z <= zhi; z++) {
        float dz = fmaxf(0.f, fmaxf((float)z * cw - qz, qz - (float)(z+1) * cw));
        float dz2 = dz * dz;
        for (int y = ylo; y <= yhi; y++) {
            float dy = fmaxf(0.f, fmaxf((float)y * cw - qy, qy - (float)(y+1) * cw));
            float dyz2 = dz2 + dy * dy;
            if (dyz2 > KRAD2) continue;
            float xr = sqrtf(KRAD2 - dyz2) + 1e-6f;
            int xlo = (int)floorf((qx - xr) * (float)GDIM); if (xlo < 0) xlo = 0;
            int xhi = (int)floorf((qx + xr) * (float)GDIM); if (xhi > GDIM-1) xhi = GDIM-1;
            int base = (z*GDIM + y)*GDIM;
            int s = g_cellStart[base + xlo];
            int e = g_cellStart[base + xhi + 1];
            for (int i = s + lane; i < e; i += 32) {
                float4 pv = g_spts[i];
                float t = __fmul_rn(qx, pv.x);
                t = __fmaf_rn(qy, pv.y, t);
                t = __fmaf_rn(qz, pv.z, t);
                float d2 = __fsub_rn(__fadd_rn(nq, pv.w), __fmul_rn(2.0f, t));
                int gi = g_sidx[i];
                bool ins = (d2 < dist[KNN-1]) || (d2 == dist[KNN-1] && gi < idx[KNN-1]);
                if (ins) {
                    dist[KNN-1] = d2;
                    idx[KNN-1]  = gi;
#pragma unroll
                    for (int j = KNN-1; j > 0; j--) {
                        float da = dist[j-1], db = dist[j];
                        int   ia = idx[j-1],  ib = idx[j];
                        bool sw = (db < da) || (db == da && ib < ia);
                        dist[j-1] = sw ? db : da;
                        dist[j]   = sw ? da : db;
                        idx[j-1]  = sw ? ib : ia;
                        idx[j]    = sw ? ia : ib;
                    }
                }
            }
        }
    }
#pragma unroll
    for (int j = 0; j < KNN; j++) { ld[w][j][lane] = dist[j]; li[w][j][lane] = idx[j]; }
    __syncwarp();

    int pos = 0;
    float last_v = FLT_MAX;
    for (int r = 0; r < KNN; r++) {
        float v = (pos < KNN) ? ld[w][pos][lane] : FLT_MAX;
        int  gi = (pos < KNN) ? li[w][pos][lane] : 0x7fffffff;
        int  owner = lane;
#pragma unroll
        for (int off = 16; off > 0; off >>= 1) {
            float v2  = __shfl_xor_sync(0xffffffffu, v, off);
            int   g2  = __shfl_xor_sync(0xffffffffu, gi, off);
            int   o2  = __shfl_xor_sync(0xffffffffu, owner, off);
            if (v2 < v || (v2 == v && g2 < gi)) { v = v2; gi = g2; owner = o2; }
        }
        if (lane == 0) g_idx[q*KNN + r] = gi;
        last_v = v;
        if (lane == owner) pos++;
    }
    // soundness: all non-enumerated points have d2 > KRAD2 (minus fp slack)
    if (!(last_v + 1e-4f < KRAD2)) {
        // exact fallback: full scan over sorted array (warp-local, rare)
#pragma unroll
        for (int j = 0; j < KNN; j++) { dist[j] = FLT_MAX; idx[j] = 0x7fffffff; }
        for (int i = lane; i < N_PTS; i += 32) {
            float4 pv = g_spts[i];
            float t = __fmul_rn(qx, pv.x);
            t = __fmaf_rn(qy, pv.y, t);
            t = __fmaf_rn(qz, pv.z, t);
            float d2 = __fsub_rn(__fadd_rn(nq, pv.w), __fmul_rn(2.0f, t));
            int gi = g_sidx[i];
            bool ins = (d2 < dist[KNN-1]) || (d2 == dist[KNN-1] && gi < idx[KNN-1]);
            if (ins) {
                dist[KNN-1] = d2;
                idx[KNN-1]  = gi;
#pragma unroll
                for (int j = KNN-1; j > 0; j--) {
                    float da = dist[j-1], db = dist[j];
                    int   ia = idx[j-1],  ib = idx[j];
                    bool sw = (db < da) || (db == da && ib < ia);
                    dist[j-1] = sw ? db : da;
                    dist[j]   = sw ? da : db;
                    idx[j-1]  = sw ? ib : ia;
                    idx[j]    = sw ? ia : ib;
                }
            }
        }
#pragma unroll
        for (int j = 0; j < KNN; j++) { ld[w][j][lane] = dist[j]; li[w][j][lane] = idx[j]; }
        __syncwarp();
        pos = 0;
        for (int r = 0; r < KNN; r++) {
            float v = (pos < KNN) ? ld[w][pos][lane] : FLT_MAX;
            int  gi = (pos < KNN) ? li[w][pos][lane] : 0x7fffffff;
            int  owner = lane;
#pragma unroll
            for (int off = 16; off > 0; off >>= 1) {
                float v2  = __shfl_xor_sync(0xffffffffu, v, off);
                int   g2  = __shfl_xor_sync(0xffffffffu, gi, off);
                int   o2  = __shfl_xor_sync(0xffffffffu, owner, off);
                if (v2 < v || (v2 == v && g2 < gi)) { v = v2; gi = g2; owner = o2; }
            }
            if (lane == 0) g_idx[q*KNN + r] = gi;
            if (lane == owner) pos++;
        }
    }
}

// ---------------- pe4 moments ----------------
__global__ void moments_kernel(const float* __restrict__ xyz_i,
                               const float* __restrict__ xyz_last) {
    float a0=0,a1=0,a2=0,a3=0,a4=0,a5=0,a6=0,a7=0,a8=0;
    for (int s = blockIdx.x * 256 + threadIdx.x; s < NK; s += gridDim.x * 256) {
        int n = s >> 4;
        int j = g_idx[s];
        float x = xyz_i[j*3+0] - xyz_last[n*3+0];
        float y = xyz_i[j*3+1] - xyz_last[n*3+1];
        float z = xyz_i[j*3+2] - xyz_last[n*3+2];
        a0 += x; a1 += y; a2 += z;
        a3 = fmaf(x,x,a3); a4 = fmaf(y,y,a4); a5 = fmaf(z,z,a5);
        a6 = fmaf(x,y,a6); a7 = fmaf(x,z,a7); a8 = fmaf(y,z,a8);
    }
    float v[9] = {a0,a1,a2,a3,a4,a5,a6,a7,a8};
#pragma unroll
    for (int i = 0; i < 9; i++) {
#pragma unroll
        for (int off = 16; off > 0; off >>= 1)
            v[i] += __shfl_xor_sync(0xffffffffu, v[i], off);
    }
    if ((threadIdx.x & 31) == 0) {
#pragma unroll
        for (int i = 0; i < 9; i++) atomicAdd(&g_m[i], v[i]);
    }
}

// ---------------- mma.sync GEMM (proven mainloop), 512 threads ----------
// MODE 0: plain; MODE 1: A generated from xyz (pe), BN-pe affine inline from g_m,
//         C := w1 = q - kf[idx] + pe, BN1 stats;
// MODE 2: f = lrelu(x*bn1) with bn1 affine inline from g_s1/g_q1, C := w2, BN2 stats
template<int MODE>
__global__ __launch_bounds__(512, 1)
void mma_gemm(const float* __restrict__ A,
              const uint16_t* __restrict__ Bth, const uint16_t* __restrict__ Btl,
              const float* __restrict__ bias, float* __restrict__ C,
              int M, int N, int K,
              const float* __restrict__ xyz_i, const float* __restrict__ xyz_last,
              const float* __restrict__ t_i, const float* __restrict__ t_last,
              const float* __restrict__ wp1, const float* __restrict__ bp1,
              const float* __restrict__ gma, const float* __restrict__ bta) {
    __shared__ __align__(16) uint16_t Ah[128*ASTR], Al[128*ASTR];
    __shared__ __align__(16) uint16_t Bh[32*BSTR], Bl[32*BSTR];
    __shared__ float spx[128], spy[128], spz[128];
    __shared__ float swp[256], sbp[64], sps[64], ssh[64];
    __shared__ float ssc[256], ssh2[256];
    __shared__ float sbias[128], sstatS[128], sstatQ[128];

    const int tid = threadIdx.x;
    const int lane = tid & 31, wid = tid >> 5;
    const int wm = wid >> 2, wn = wid & 3;          // 4x4 warp grid, 32x32 tiles
    const int m0 = blockIdx.y * 128, n0 = blockIdx.x * 128;

    float dtv = 0.f;
    if (MODE == 1) {
        if (tid < 128) {
            int m = m0 + tid;
            int n = m >> 4;
            int j = g_idx[m];
            spx[tid] = xyz_i[j*3+0] - xyz_last[n*3+0];
            spy[tid] = xyz_i[j*3+1] - xyz_last[n*3+1];
            spz[tid] = xyz_i[j*3+2] - xyz_last[n*3+2];
        }
        if (tid < 256) swp[tid] = wp1[tid];
        dtv = t_i[0] - t_last[0];
        if (tid < 64) {
            // inline finalize_pe: analytic BN over generated h
            float inv = 1.f / (float)NK;
            float mx = g_m[0]*inv, my = g_m[1]*inv, mz = g_m[2]*inv;
            float exx = g_m[3]*inv, eyy = g_m[4]*inv, ezz = g_m[5]*inv;
            float exy = g_m[6]*inv, exz = g_m[7]*inv, eyz = g_m[8]*inv;
            float w0 = wp1[tid], w1 = wp1[64+tid], w2 = wp1[128+tid], w3 = wp1[192+tid];
            float a  = bp1[tid] + w3*dtv;
            float lm = w0*mx + w1*my + w2*mz;
            float mean = a + lm;
            float e2 = a*a + 2.f*a*lm
                     + w0*w0*exx + w1*w1*eyy + w2*w2*ezz
                     + 2.f*(w0*w1*exy + w0*w2*exz + w1*w2*eyz);
            float var = e2 - mean*mean;
            float s = gma[tid] * rsqrtf(var + EPS);
            sps[tid] = s;
            ssh[tid] = bta[tid] - mean*s;
            sbp[tid] = bp1[tid];
        }
    }
    if (MODE == 2 && tid < 256) {
        // inline finalize BN1
        float inv = 1.f / (float)NK;
        float m = g_s1[tid] * inv;
        float v = g_q1[tid] * inv - m*m;
        float s = gma[tid] * rsqrtf(v + EPS);
        ssc[tid]  = s;
        ssh2[tid] = bta[tid] - m*s;
    }
    if (tid < 128) { sbias[tid] = bias[n0 + tid]; sstatS[tid] = 0.f; sstatQ[tid] = 0.f; }
    if (MODE == 1 || MODE == 2) __syncthreads();

    float acc[2][4][4];
#pragma unroll
    for (int i = 0; i < 2; i++)
#pragma unroll
        for (int j = 0; j < 4; j++)
#pragma unroll
            for (int e = 0; e < 4; e++) acc[i][j][e] = 0.f;

    const int arow = tid >> 2, ac = (tid & 3) * 8;     // A: 128 rows x 32 k
    const int brow = tid >> 4, bc = (tid & 15) * 8;    // B: 32 k-rows x 128 n

    // prefetch stage 0
    float4 a0r, a1r;
    uint4 bhr, blr;
    if (MODE != 1) {
        a0r = *(const float4*)(A + (size_t)(m0 + arow)*K + ac);
        a1r = *(const float4*)(A + (size_t)(m0 + arow)*K + ac + 4);
    }
    bhr = *(const uint4*)(Bth + (size_t)brow*N + n0 + bc);
    blr = *(const uint4*)(Btl + (size_t)brow*N + n0 + bc);

    const uint32_t AhB = su32(Ah), AlB = su32(Al), BhB = su32(Bh), BlB = su32(Bl);
    uint32_t a_off[2], b_off[2];
#pragma unroll
    for (int mt = 0; mt < 2; mt++)
        a_off[mt] = (uint32_t)(((wm*32 + mt*16 + (lane & 15))*ASTR + (lane >> 4)*8) * 2);
#pragma unroll
    for (int p = 0; p < 2; p++)
        b_off[p] = (uint32_t)(((lane & 15)*BSTR + wn*32 + p*16 + (lane >> 4)*8) * 2);

    const int nst = K >> 5;
    for (int kt = 0; kt < nst; kt++) {
        const int kb = kt * 32;
        if (MODE == 1) {
            float px = spx[arow], py = spy[arow], pz = spz[arow];
            float v[8];
#pragma unroll
            for (int e = 0; e < 8; e++) {
                int c = kb + ac + e;
                float hh = sbp[c];
                hh = fmaf(px,  swp[c],     hh);
                hh = fmaf(py,  swp[64+c],  hh);
                hh = fmaf(pz,  swp[128+c], hh);
                hh = fmaf(dtv, swp[192+c], hh);
                float x = fmaf(hh, sps[c], ssh[c]);
                v[e] = (x >= 0.f) ? x : SLOPE*x;
            }
            uint4 H, L;
            pack8(v, H, L);
            *(uint4*)&Ah[arow*ASTR + ac] = H;
            *(uint4*)&Al[arow*ASTR + ac] = L;
        } else {
            float v[8] = {a0r.x, a0r.y, a0r.z, a0r.w, a1r.x, a1r.y, a1r.z, a1r.w};
            if (MODE == 2) {
                int c = kb + ac;
#pragma unroll
                for (int e = 0; e < 8; e++) {
                    float x = fmaf(v[e], ssc[c+e], ssh2[c+e]);
                    v[e] = (x >= 0.f) ? x : SLOPE*x;
                }
            }
            uint4 H, L;
            pack8(v, H, L);
            *(uint4*)&Ah[arow*ASTR + ac] = H;
            *(uint4*)&Al[arow*ASTR + ac] = L;
        }
        *(uint4*)&Bh[brow*BSTR + bc] = bhr;
        *(uint4*)&Bl[brow*BSTR + bc] = blr;
        __syncthreads();

        if (kt + 1 < nst) {
            const int kn = kb + 32;
            if (MODE != 1) {
                a0r = *(const float4*)(A + (size_t)(m0 + arow)*K + kn + ac);
                a1r = *(const float4*)(A + (size_t)(m0 + arow)*K + kn + ac + 4);
            }
            bhr = *(const uint4*)(Bth + (size_t)(kn + brow)*N + n0 + bc);
            blr = *(const uint4*)(Btl + (size_t)(kn + brow)*N + n0 + bc);
        }

#pragma unroll
        for (int ko = 0; ko < 2; ko++) {
            uint32_t ah[2][4], al_[2][4];
#pragma unroll
            for (int mt = 0; mt < 2; mt++) {
                ldsm4(ah[mt],  AhB + a_off[mt] + ko*32);
                ldsm4(al_[mt], AlB + a_off[mt] + ko*32);
            }
            uint32_t bh[4][2], bl[4][2];
#pragma unroll
            for (int p = 0; p < 2; p++) {
                uint32_t r[4];
                ldsm4t(r, BhB + b_off[p] + ko*16*BSTR*2);
                bh[2*p][0] = r[0]; bh[2*p][1] = r[1];
                bh[2*p+1][0] = r[2]; bh[2*p+1][1] = r[3];
                ldsm4t(r, BlB + b_off[p] + ko*16*BSTR*2);
                bl[2*p][0] = r[0]; bl[2*p][1] = r[1];
                bl[2*p+1][0] = r[2]; bl[2*p+1][1] = r[3];
            }
#pragma unroll
            for (int mt = 0; mt < 2; mt++)
#pragma unroll
                for (int nt = 0; nt < 4; nt++) {
                    mma16816(acc[mt][nt], ah[mt],  bh[nt]);
                    mma16816(acc[mt][nt], ah[mt],  bl[nt]);
                    mma16816(acc[mt][nt], al_[mt], bh[nt]);
                }
        }
        __syncthreads();
    }

    // ---- epilogue ----
    float colS[8], colQ[8];
#pragma unroll
    for (int i = 0; i < 8; i++) { colS[i] = 0.f; colQ[i] = 0.f; }

#pragma unroll
    for (int mt = 0; mt < 2; mt++) {
        int r0 = m0 + wm*32 + mt*16 + (lane >> 2);
        int r1 = r0 + 8;
        int j0 = 0, j1 = 0, p0 = 0, p1 = 0;
        if (MODE == 1) {
            j0 = g_idx[r0]; j1 = g_idx[r1];
            p0 = r0 >> 4;   p1 = r1 >> 4;
        }
#pragma unroll
        for (int nt = 0; nt < 4; nt++) {
            int cl = wn*32 + nt*8 + (lane & 3)*2;      // local col in [0,128)
            int c = n0 + cl;
            float v00 = acc[mt][nt][0] + sbias[cl],   v01 = acc[mt][nt][1] + sbias[cl+1];
            float v10 = acc[mt][nt][2] + sbias[cl],   v11 = acc[mt][nt][3] + sbias[cl+1];
            if (MODE == 1) {
                float2 q0 = *(const float2*)(g_q  + (size_t)p0*256 + c);
                float2 q1 = *(const float2*)(g_q  + (size_t)p1*256 + c);
                float2 k0 = *(const float2*)(g_kv + (size_t)j0*512 + c);
                float2 k1 = *(const float2*)(g_kv + (size_t)j1*512 + c);
                v00 = q0.x - k0.x + v00; v01 = q0.y - k0.y + v01;
                v10 = q1.x - k1.x + v10; v11 = q1.y - k1.y + v11;
            }
            *(float2*)(C + (size_t)r0*N + c) = make_float2(v00, v01);
            *(float2*)(C + (size_t)r1*N + c) = make_float2(v10, v11);
            if (MODE != 0) {
                colS[nt*2+0] += v00 + v10;  colS[nt*2+1] += v01 + v11;
                colQ[nt*2+0] += v00*v00 + v10*v10;
                colQ[nt*2+1] += v01*v01 + v11*v11;
            }
        }
    }
    if (MODE != 0) {
#pragma unroll
        for (int i = 0; i < 8; i++) {
#pragma unroll
            for (int off = 4; off <= 16; off <<= 1) {
                colS[i] += __shfl_xor_sync(0xffffffffu, colS[i], off);
                colQ[i] += __shfl_xor_sync(0xffffffffu, colQ[i], off);
            }
        }
        if (lane < 4) {
#pragma unroll
            for (int nt = 0; nt < 4; nt++) {
#pragma unroll
                for (int j = 0; j < 2; j++) {
                    int cl = wn*32 + nt*8 + lane*2 + j;
                    atomicAdd(&sstatS[cl], colS[nt*2+j]);
                    atomicAdd(&sstatQ[cl], colQ[nt*2+j]);
                }
            }
        }
        __syncthreads();
        if (tid < 128) {
            float* gS = (MODE == 1) ? g_s1 : g_s2;
            float* gQ = (MODE == 1) ? g_q1 : g_q2;
            atomicAdd(&gS[n0 + tid], sstatS[tid]);
            atomicAdd(&gQ[n0 + tid], sstatQ[tid]);
        }
    }
}

// ---------------- final: inline BN2 finalize + lrelu + softmax(K) + v-sum ------
// v = vf[j] + pe = u[j] + (w1 - q),  u = kf + vf precomputed
__global__ void final_kernel(float* __restrict__ out,
                             const float* __restrict__ gw2, const float* __restrict__ bw2) {
    int n = blockIdx.x, c = threadIdx.x;
    __shared__ int sidx[KNN];
    if (c < KNN) sidx[c] = g_idx[n*KNN + c];
    __syncthreads();
    float inv = 1.f / (float)NK;
    float mm = g_s2[c] * inv;
    float vv = g_q2[c] * inv - mm*mm;
    float sc = gw2[c] * rsqrtf(vv + EPS);
    float sh = bw2[c] - mm*sc;
    float qv = g_q[(size_t)n*COUT + c];
    float z[KNN], w1v[KNN];
    float m = -FLT_MAX;
#pragma unroll
    for (int k = 0; k < KNN; k++) {
        float x = g_w2[((size_t)n*KNN + k)*COUT + c];
        w1v[k] = g_w1[((size_t)n*KNN + k)*COUT + c];
        x = x*sc + sh;
        x = (x >= 0.f) ? x : SLOPE*x;
        z[k] = x;
        m = fmaxf(m, x);
    }
    float den = 0.f, num = 0.f;
#pragma unroll
    for (int k = 0; k < KNN; k++) {
        float e = __expf(z[k] - m);
        float v = g_u[(size_t)sidx[k]*256 + c] + (w1v[k] - qv);
        den += e;
        num = fmaf(e, v, num);
    }
    out[(size_t)n*COUT + c] = num / den;
}

// ---------------- launch (stream fork/join: kNN chain ∥ projection chain) ------
extern "C" void kernel_launch(void* const* d_in, const int* in_sizes, int n_in,
                              void* d_out, int out_size) {
    const float* fea_i    = (const float*)d_in[0];
    const float* fea_last = (const float*)d_in[1];
    const float* xyz_i    = (const float*)d_in[2];
    const float* xyz_last = (const float*)d_in[3];
    const float* t_i      = (const float*)d_in[4];
    const float* t_last   = (const float*)d_in[5];
    const float* wp1 = (const float*)d_in[6];
    const float* bp1 = (const float*)d_in[7];
    const float* gp  = (const float*)d_in[8];
    const float* bp  = (const float*)d_in[9];
    const float* wp2 = (const float*)d_in[10];
    const float* bp2 = (const float*)d_in[11];
    const float* wq  = (const float*)d_in[12];
    const float* bq  = (const float*)d_in[13];
    const float* wk  = (const float*)d_in[14];
    const float* bk  = (const float*)d_in[15];
    const float* wv  = (const float*)d_in[16];
    const float* bv  = (const float*)d_in[17];
    const float* gw1 = (const float*)d_in[18];
    const float* bw1 = (const float*)d_in[19];
    const float* ww  = (const float*)d_in[20];
    const float* bw  = (const float*)d_in[21];
    const float* gw2 = (const float*)d_in[22];
    const float* bw2 = (const float*)d_in[23];
    float* out = (float*)d_out;

    void* p;
    cudaGetSymbolAddress(&p, g_q);   float* p_q   = (float*)p;
    cudaGetSymbolAddress(&p, g_kv);  float* p_kv  = (float*)p;
    cudaGetSymbolAddress(&p, g_bkv); float* p_bkv = (float*)p;
    cudaGetSymbolAddress(&p, g_bth); uint16_t* p_bth = (uint16_t*)p;
    cudaGetSymbolAddress(&p, g_btl); uint16_t* p_btl = (uint16_t*)p;
    cudaGetSymbolAddress(&p, g_w1);  float* p_w1  = (float*)p;
    cudaGetSymbolAddress(&p, g_w2);  float* p_w2  = (float*)p;

    static cudaStream_t s2 = nullptr;
    static cudaEvent_t evFork = nullptr, evJoin = nullptr;
    if (s2 == nullptr) {
        cudaStreamCreateWithFlags(&s2, cudaStreamNonBlocking);
        cudaEventCreateWithFlags(&evFork, cudaEventDisableTiming);
        cudaEventCreateWithFlags(&evJoin, cudaEventDisableTiming);
    }

    // 0) prep (weight split + bias + stat zero + grid zero) on main stream
    prep_kernel<<<(TOTW + 255)/256, 256>>>(wq, wk, wv, wp2, ww, bk, bv);

    // fork: side stream s2 runs projections (depend only on prep)
    cudaEventRecord(evFork, 0);
    cudaStreamWaitEvent(s2, evFork, 0);
    mma_gemm<0><<<dim3(2, 64), 512, 0, s2>>>(fea_last, p_bth + OQ,  p_btl + OQ,  bq,    p_q,  N_PTS, 256, CIN,
                                             nullptr, nullptr, nullptr, nullptr, nullptr, nullptr, nullptr, nullptr);
    mma_gemm<0><<<dim3(4, 64), 512, 0, s2>>>(fea_i,    p_bth + OKV, p_btl + OKV, p_bkv, p_kv, N_PTS, 512, CIN,
                                             nullptr, nullptr, nullptr, nullptr, nullptr, nullptr, nullptr, nullptr);
    u_kernel<<<(N_PTS*256)/256, 256, 0, s2>>>();
    cudaEventRecord(evJoin, s2);

    // main stream: kNN chain + moments (independent of projections)
    grid_count_kernel<<<N_PTS/256, 256>>>(xyz_i);
    grid_scan_kernel<<<1, 512>>>();
    grid_scatter_kernel<<<N_PTS/256, 256>>>(xyz_i);
    knn_grid_kernel<<<N_PTS/QPB, 256>>>(xyz_last);
    moments_kernel<<<64, 256>>>(xyz_i, xyz_last);

    // join: mma<1> needs both chains
    cudaStreamWaitEvent(0, evJoin, 0);

    // 4) pe GEMM (A generated) -> w1 = q - kf + pe, + BN1 stats
    mma_gemm<1><<<dim3(2, 1024), 512>>>(nullptr, p_bth + OP2, p_btl + OP2, bp2, p_w1, NK, 256, HDIM,
                                        xyz_i, xyz_last, t_i, t_last, wp1, bp1, gp, bp);

    // 5) w2 GEMM (BN1 finalize inlined) + BN2 stats
    mma_gemm<2><<<dim3(2, 1024), 512>>>(p_w1, p_bth + OW, p_btl + OW, bw, p_w2, NK, 256, CIN,
                                        nullptr, nullptr, nullptr, nullptr, nullptr, nullptr, gw1, bw1);

    // 6) softmax over K + weighted v-sum (BN2 finalize inlined)
    final_kernel<<<N_PTS, COUT>>>(out, gw2, bw2);
}

// round 13
// speedup vs baseline: 1.1887x; 1.0605x over previous
#include <cuda_runtime.h>
#include <cuda_bf16.h>
#include <cstdint>
#include <cfloat>

#define N_PTS 8192
#define KNN   16
#define CIN   256
#define COUT  256
#define NK    (N_PTS*KNN)       // 131072
#define HDIM  64
#define SLOPE 0.01f
#define EPS   1e-5f
#define QPB   8
#define ASTR  40                // A smem row stride in halves
#define BSTR  136               // B smem row stride in halves

// kNN grid params
#define GDIM  8
#define GCELLS (GDIM*GDIM*GDIM)   // 512
#define KRAD  0.25f
#define KRAD2 0.0625f

// weight-split buffer offsets (natural [K,N] layout, bf16 hi/lo)
#define OQ   0
#define OKV  65536              // 256*256
#define OP2  196608             // + 256*512
#define OW   212992             // + 64*256
#define TOTW 278528             // + 256*256

// ---------------- device scratch (static, allocation-free) ----------------
__device__ int      g_idx[NK];
__device__ float    g_q  [N_PTS*COUT];
__device__ float    g_kv [N_PTS*512];     // [kf | vf]
__device__ float    g_u  [N_PTS*COUT];    // kf + vf (for final)
__device__ float    g_bkv[512];
__device__ uint16_t g_bth[TOTW];          // weights bf16 hi, [K,N]
__device__ uint16_t g_btl[TOTW];          // weights bf16 lo, [K,N]
__device__ float    g_w1 [NK*COUT];
__device__ float    g_w2 [NK*COUT];
__device__ float    g_m[9];               // pe4 moments
__device__ float    g_s1[COUT], g_q1[COUT];
__device__ float    g_s2[COUT], g_q2[COUT];
// grid structures
__device__ int      g_cellCnt[GCELLS];
__device__ int      g_cellFill[GCELLS];
__device__ int      g_cellStart[GCELLS+1];
__device__ float4   g_spts[N_PTS];
__device__ int      g_sidx[N_PTS];

// ---------------- PTX helpers ----------------
__device__ __forceinline__ uint32_t su32(const void* p) {
    return (uint32_t)__cvta_generic_to_shared(p);
}
__device__ __forceinline__ void ldsm4(uint32_t r[4], uint32_t a) {
    asm volatile("ldmatrix.sync.aligned.m8n8.x4.shared.b16 {%0,%1,%2,%3}, [%4];"
        : "=r"(r[0]), "=r"(r[1]), "=r"(r[2]), "=r"(r[3]) : "r"(a));
}
__device__ __forceinline__ void ldsm4t(uint32_t r[4], uint32_t a) {
    asm volatile("ldmatrix.sync.aligned.m8n8.x4.trans.shared.b16 {%0,%1,%2,%3}, [%4];"
        : "=r"(r[0]), "=r"(r[1]), "=r"(r[2]), "=r"(r[3]) : "r"(a));
}
__device__ __forceinline__ void mma16816(float c[4], const uint32_t a[4], const uint32_t b[2]) {
    asm volatile("mma.sync.aligned.m16n8k16.row.col.f32.bf16.bf16.f32 "
        "{%0,%1,%2,%3}, {%4,%5,%6,%7}, {%8,%9}, {%0,%1,%2,%3};"
        : "+f"(c[0]), "+f"(c[1]), "+f"(c[2]), "+f"(c[3])
        : "r"(a[0]), "r"(a[1]), "r"(a[2]), "r"(a[3]), "r"(b[0]), "r"(b[1]));
}
__device__ __forceinline__ void split1(float x, uint16_t& hi, uint16_t& lo) {
    __nv_bfloat16 h = __float2bfloat16_rn(x);
    __nv_bfloat16 l = __float2bfloat16_rn(x - __bfloat162float(h));
    hi = *(uint16_t*)&h; lo = *(uint16_t*)&l;
}
// vectorized: per 2 elements one cvt.rn.bf16x2.f32 for hi and one for lo
__device__ __forceinline__ void pack8(const float* v, uint4& H, uint4& L) {
    uint32_t* hp = (uint32_t*)&H;
    uint32_t* lp = (uint32_t*)&L;
#pragma unroll
    for (int i = 0; i < 4; i++) {
        float x0 = v[2*i], x1 = v[2*i+1];
        __nv_bfloat162 h2 = __floats2bfloat162_rn(x0, x1);
        float h0 = __low2float(h2), h1 = __high2float(h2);
        __nv_bfloat162 l2 = __floats2bfloat162_rn(x0 - h0, x1 - h1);
        hp[i] = *(uint32_t*)&h2;
        lp[i] = *(uint32_t*)&l2;
    }
}

// ---------------- prep: weight split + bias concat + zero stats + grid zero ----
__global__ void prep_kernel(const float* __restrict__ wq,
                            const float* __restrict__ wk, const float* __restrict__ wv,
                            const float* __restrict__ wp2, const float* __restrict__ ww,
                            const float* __restrict__ bk, const float* __restrict__ bv) {
    int i = blockIdx.x * 256 + threadIdx.x;
    if (i < TOTW) {
        float val;
        if (i < OKV) {                       // wq [256,256]
            val = wq[i];
        } else if (i < OP2) {                // wkv [256,512]: row k = [wk_k | wv_k]
            int j = i - OKV, k = j >> 9, n = j & 511;
            val = (n < 256) ? wk[k*256 + n] : wv[k*256 + (n - 256)];
        } else if (i < OW) {                 // wp2 [64,256]
            val = wp2[i - OP2];
        } else {                             // ww [256,256]
            val = ww[i - OW];
        }
        uint16_t h, l;
        split1(val, h, l);
        g_bth[i] = h; g_btl[i] = l;
    }
    if (i < 512) {
        g_bkv[i] = (i < 256) ? bk[i] : bv[i - 256];
        g_cellCnt[i] = 0;
    }
    if (i < 9) g_m[i] = 0.f;
    if (i < COUT) { g_s1[i] = 0.f; g_q1[i] = 0.f; g_s2[i] = 0.f; g_q2[i] = 0.f; }
}

// ---------------- u = kf + vf ----------------
__global__ void u_kernel() {
    int i = blockIdx.x * 256 + threadIdx.x;     // N_PTS*256
    int r = i >> 8, c = i & 255;
    g_u[i] = g_kv[(size_t)r*512 + c] + g_kv[(size_t)r*512 + 256 + c];
}

// ---------------- kNN: exact grid-accelerated, integrated fallback ----------------
__device__ __forceinline__ float norm3_ref(float x, float y, float z) {
    return __fadd_rn(__fadd_rn(__fmul_rn(x, x), __fmul_rn(y, y)), __fmul_rn(z, z));
}
__device__ __forceinline__ int gcell(float v) {
    int c = (int)(v * (float)GDIM);
    return c < 0 ? 0 : (c > GDIM-1 ? GDIM-1 : c);
}

__global__ void grid_count_kernel(const float* __restrict__ xyz_i) {
    int i = blockIdx.x * 256 + threadIdx.x;
    if (i >= N_PTS) return;
    int cx = gcell(xyz_i[i*3+0]);
    int cy = gcell(xyz_i[i*3+1]);
    int cz = gcell(xyz_i[i*3+2]);
    atomicAdd(&g_cellCnt[(cz*GDIM + cy)*GDIM + cx], 1);
}
__global__ void grid_scan_kernel() {
    __shared__ int s[GCELLS];
    int t = threadIdx.x;                  // 512
    int own = g_cellCnt[t];
    s[t] = own;
    __syncthreads();
    for (int off = 1; off < GCELLS; off <<= 1) {
        int u = 0;
        if (t >= off) u = s[t - off];
        __syncthreads();
        s[t] += u;
        __syncthreads();
    }
    g_cellStart[t] = s[t] - own;          // exclusive
    if (t == GCELLS-1) g_cellStart[GCELLS] = N_PTS;
    g_cellFill[t] = 0;
}
__global__ void grid_scatter_kernel(const float* __restrict__ xyz_i) {
    int i = blockIdx.x * 256 + threadIdx.x;
    if (i >= N_PTS) return;
    float x = xyz_i[i*3+0], y = xyz_i[i*3+1], z = xyz_i[i*3+2];
    int cell = (gcell(z)*GDIM + gcell(y))*GDIM + gcell(x);
    int pos = g_cellStart[cell] + atomicAdd(&g_cellFill[cell], 1);
    g_spts[pos] = make_float4(x, y, z, norm3_ref(x, y, z));
    g_sidx[pos] = i;
}

// warp per query: grid cells within KRAD; exact d2; lexicographic top-16;
// integrated exact fallback (full scan over sorted array) if radius insufficient.
__global__ void knn_grid_kernel(const float* __restrict__ xyz_last) {
    __shared__ float ld[QPB][KNN][32];
    __shared__ int   li[QPB][KNN][32];
    const int tid = threadIdx.x;
    const int w = tid >> 5, lane = tid & 31;
    const int q = blockIdx.x * QPB + w;
    const float qx = xyz_last[q*3+0];
    const float qy = xyz_last[q*3+1];
    const float qz = xyz_last[q*3+2];
    const float nq = norm3_ref(qx, qy, qz);
    const float cw = 1.f / (float)GDIM;

    float dist[KNN];
    int   idx [KNN];
#pragma unroll
    for (int j = 0; j < KNN; j++) { dist[j] = FLT_MAX; idx[j] = 0x7fffffff; }

    int zlo = (int)floorf((qz - KRAD) * (float)GDIM); if (zlo < 0) zlo = 0;
    int zhi = (int)floorf((qz + KRAD) * (float)GDIM); if (zhi > GDIM-1) zhi = GDIM-1;
    int ylo = (int)floorf((qy - KRAD) * (float)GDIM); if (ylo < 0) ylo = 0;
    int yhi = (int)floorf((qy + KRAD) * (float)GDIM); if (yhi > GDIM-1) yhi = GDIM-1;

    for (int z = zlo; z <= zhi; z++) {
        float dz = fmaxf(0.f, fmaxf((float)z * cw - qz, qz - (float)(z+1) * cw));
        float dz2 = dz * dz;
        for (int y = ylo; y <= yhi; y++) {
            float dy = fmaxf(0.f, fmaxf((float)y * cw - qy, qy - (float)(y+1) * cw));
            float dyz2 = dz2 + dy * dy;
            if (dyz2 > KRAD2) continue;
            float xr = sqrtf(KRAD2 - dyz2) + 1e-6f;
            int xlo = (int)floorf((qx - xr) * (float)GDIM); if (xlo < 0) xlo = 0;
            int xhi = (int)floorf((qx + xr) * (float)GDIM); if (xhi > GDIM-1) xhi = GDIM-1;
            int base = (z*GDIM + y)*GDIM;
            int s = g_cellStart[base + xlo];
            int e = g_cellStart[base + xhi + 1];
            for (int i = s + lane; i < e; i += 32) {
                float4 pv = g_spts[i];
                float t = __fmul_rn(qx, pv.x);
                t = __fmaf_rn(qy, pv.y, t);
                t = __fmaf_rn(qz, pv.z, t);
                float d2 = __fsub_rn(__fadd_rn(nq, pv.w), __fmul_rn(2.0f, t));
                int gi = g_sidx[i];
                bool ins = (d2 < dist[KNN-1]) || (d2 == dist[KNN-1] && gi < idx[KNN-1]);
                if (ins) {
                    dist[KNN-1] = d2;
                    idx[KNN-1]  = gi;
#pragma unroll
                    for (int j = KNN-1; j > 0; j--) {
                        float da = dist[j-1], db = dist[j];
                        int   ia = idx[j-1],  ib = idx[j];
                        bool sw = (db < da) || (db == da && ib < ia);
                        dist[j-1] = sw ? db : da;
                        dist[j]   = sw ? da : db;
                        idx[j-1]  = sw ? ib : ia;
                        idx[j]    = sw ? ia : ib;
                    }
                }
            }
        }
    }
#pragma unroll
    for (int j = 0; j < KNN; j++) { ld[w][j][lane] = dist[j]; li[w][j][lane] = idx[j]; }
    __syncwarp();

    int pos = 0;
    float last_v = FLT_MAX;
    for (int r = 0; r < KNN; r++) {
        float v = (pos < KNN) ? ld[w][pos][lane] : FLT_MAX;
        int  gi = (pos < KNN) ? li[w][pos][lane] : 0x7fffffff;
        int  owner = lane;
#pragma unroll
        for (int off = 16; off > 0; off >>= 1) {
            float v2  = __shfl_xor_sync(0xffffffffu, v, off);
            int   g2  = __shfl_xor_sync(0xffffffffu, gi, off);
            int   o2  = __shfl_xor_sync(0xffffffffu, owner, off);
            if (v2 < v || (v2 == v && g2 < gi)) { v = v2; gi = g2; owner = o2; }
        }
        if (lane == 0) g_idx[q*KNN + r] = gi;
        last_v = v;
        if (lane == owner) pos++;
    }
    // soundness: all non-enumerated points have d2 > KRAD2 (minus fp slack)
    if (!(last_v + 1e-4f < KRAD2)) {
        // exact fallback: full scan over sorted array (warp-local, rare)
#pragma unroll
        for (int j = 0; j < KNN; j++) { dist[j] = FLT_MAX; idx[j] = 0x7fffffff; }
        for (int i = lane; i < N_PTS; i += 32) {
            float4 pv = g_spts[i];
            float t = __fmul_rn(qx, pv.x);
            t = __fmaf_rn(qy, pv.y, t);
            t = __fmaf_rn(qz, pv.z, t);
            float d2 = __fsub_rn(__fadd_rn(nq, pv.w), __fmul_rn(2.0f, t));
            int gi = g_sidx[i];
            bool ins = (d2 < dist[KNN-1]) || (d2 == dist[KNN-1] && gi < idx[KNN-1]);
            if (ins) {
                dist[KNN-1] = d2;
                idx[KNN-1]  = gi;
#pragma unroll
                for (int j = KNN-1; j > 0; j--) {
                    float da = dist[j-1], db = dist[j];
                    int   ia = idx[j-1],  ib = idx[j];
                    bool sw = (db < da) || (db == da && ib < ia);
                    dist[j-1] = sw ? db : da;
                    dist[j]   = sw ? da : db;
                    idx[j-1]  = sw ? ib : ia;
                    idx[j]    = sw ? ia : ib;
                }
            }
        }
#pragma unroll
        for (int j = 0; j < KNN; j++) { ld[w][j][lane] = dist[j]; li[w][j][lane] = idx[j]; }
        __syncwarp();
        pos = 0;
        for (int r = 0; r < KNN; r++) {
            float v = (pos < KNN) ? ld[w][pos][lane] : FLT_MAX;
            int  gi = (pos < KNN) ? li[w][pos][lane] : 0x7fffffff;
            int  owner = lane;
#pragma unroll
            for (int off = 16; off > 0; off >>= 1) {
                float v2  = __shfl_xor_sync(0xffffffffu, v, off);
                int   g2  = __shfl_xor_sync(0xffffffffu, gi, off);
                int   o2  = __shfl_xor_sync(0xffffffffu, owner, off);
                if (v2 < v || (v2 == v && g2 < gi)) { v = v2; gi = g2; owner = o2; }
            }
            if (lane == 0) g_idx[q*KNN + r] = gi;
            if (lane == owner) pos++;
        }
    }
}

// ---------------- pe4 moments ----------------
__global__ void moments_kernel(const float* __restrict__ xyz_i,
                               const float* __restrict__ xyz_last) {
    float a0=0,a1=0,a2=0,a3=0,a4=0,a5=0,a6=0,a7=0,a8=0;
    for (int s = blockIdx.x * 256 + threadIdx.x; s < NK; s += gridDim.x * 256) {
        int n = s >> 4;
        int j = g_idx[s];
        float x = xyz_i[j*3+0] - xyz_last[n*3+0];
        float y = xyz_i[j*3+1] - xyz_last[n*3+1];
        float z = xyz_i[j*3+2] - xyz_last[n*3+2];
        a0 += x; a1 += y; a2 += z;
        a3 = fmaf(x,x,a3); a4 = fmaf(y,y,a4); a5 = fmaf(z,z,a5);
        a6 = fmaf(x,y,a6); a7 = fmaf(x,z,a7); a8 = fmaf(y,z,a8);
    }
    float v[9] = {a0,a1,a2,a3,a4,a5,a6,a7,a8};
#pragma unroll
    for (int i = 0; i < 9; i++) {
#pragma unroll
        for (int off = 16; off > 0; off >>= 1)
            v[i] += __shfl_xor_sync(0xffffffffu, v[i], off);
    }
    if ((threadIdx.x & 31) == 0) {
#pragma unroll
        for (int i = 0; i < 9; i++) atomicAdd(&g_m[i], v[i]);
    }
}

// ---------------- mma.sync GEMM: 64x128 CTA tile, 256 threads, 2 CTAs/SM ----------
// MODE 0: plain; MODE 1: A generated from xyz (pe), BN-pe affine inline from g_m,
//         C := w1 = q - kf[idx] + pe, BN1 stats;
// MODE 2: f = lrelu(x*bn1) with bn1 affine inline from g_s1/g_q1, C := w2, BN2 stats
template<int MODE>
__global__ __launch_bounds__(256, 2)
void mma_gemm(const float* __restrict__ A,
              const uint16_t* __restrict__ Bth, const uint16_t* __restrict__ Btl,
              const float* __restrict__ bias, float* __restrict__ C,
              int M, int N, int K,
              const float* __restrict__ xyz_i, const float* __restrict__ xyz_last,
              const float* __restrict__ t_i, const float* __restrict__ t_last,
              const float* __restrict__ wp1, const float* __restrict__ bp1,
              const float* __restrict__ gma, const float* __restrict__ bta) {
    __shared__ __align__(16) uint16_t Ah[64*ASTR], Al[64*ASTR];
    __shared__ __align__(16) uint16_t Bh[32*BSTR], Bl[32*BSTR];
    __shared__ float spx[64], spy[64], spz[64];
    __shared__ float swp[256], sbp[64], sps[64], ssh[64];
    __shared__ float ssc[256], ssh2[256];
    __shared__ float sbias[128], sstatS[128], sstatQ[128];

    const int tid = threadIdx.x;
    const int lane = tid & 31, wid = tid >> 5;
    const int wm = wid >> 2, wn = wid & 3;          // 2x4 warp grid, 32x32 tiles
    const int m0 = blockIdx.y * 64, n0 = blockIdx.x * 128;

    float dtv = 0.f;
    if (MODE == 1) {
        if (tid < 64) {
            int m = m0 + tid;
            int n = m >> 4;
            int j = g_idx[m];
            spx[tid] = xyz_i[j*3+0] - xyz_last[n*3+0];
            spy[tid] = xyz_i[j*3+1] - xyz_last[n*3+1];
            spz[tid] = xyz_i[j*3+2] - xyz_last[n*3+2];
        }
        swp[tid] = wp1[tid];
        dtv = t_i[0] - t_last[0];
        if (tid < 64) {
            // inline finalize_pe: analytic BN over generated h
            float inv = 1.f / (float)NK;
            float mx = g_m[0]*inv, my = g_m[1]*inv, mz = g_m[2]*inv;
            float exx = g_m[3]*inv, eyy = g_m[4]*inv, ezz = g_m[5]*inv;
            float exy = g_m[6]*inv, exz = g_m[7]*inv, eyz = g_m[8]*inv;
            float w0 = wp1[tid], w1 = wp1[64+tid], w2 = wp1[128+tid], w3 = wp1[192+tid];
            float a  = bp1[tid] + w3*dtv;
            float lm = w0*mx + w1*my + w2*mz;
            float mean = a + lm;
            float e2 = a*a + 2.f*a*lm
                     + w0*w0*exx + w1*w1*eyy + w2*w2*ezz
                     + 2.f*(w0*w1*exy + w0*w2*exz + w1*w2*eyz);
            float var = e2 - mean*mean;
            float s = gma[tid] * rsqrtf(var + EPS);
            sps[tid] = s;
            ssh[tid] = bta[tid] - mean*s;
            sbp[tid] = bp1[tid];
        }
    }
    if (MODE == 2) {
        // inline finalize BN1
        float inv = 1.f / (float)NK;
        float m = g_s1[tid] * inv;
        float v = g_q1[tid] * inv - m*m;
        float s = gma[tid] * rsqrtf(v + EPS);
        ssc[tid]  = s;
        ssh2[tid] = bta[tid] - m*s;
    }
    if (tid < 128) { sbias[tid] = bias[n0 + tid]; sstatS[tid] = 0.f; sstatQ[tid] = 0.f; }
    if (MODE == 1 || MODE == 2) __syncthreads();

    float acc[2][4][4];
#pragma unroll
    for (int i = 0; i < 2; i++)
#pragma unroll
        for (int j = 0; j < 4; j++)
#pragma unroll
            for (int e = 0; e < 4; e++) acc[i][j][e] = 0.f;

    const int arow = tid >> 2, ac = (tid & 3) * 8;     // A: 64 rows x 32 k
    const int brow = tid >> 4, bc = (tid & 15) * 8;    // B: rows brow, brow+16 x 128 n

    // prefetch stage 0
    float4 a0r, a1r;
    uint4 bhr[2], blr[2];
    if (MODE != 1) {
        a0r = *(const float4*)(A + (size_t)(m0 + arow)*K + ac);
        a1r = *(const float4*)(A + (size_t)(m0 + arow)*K + ac + 4);
    }
    bhr[0] = *(const uint4*)(Bth + (size_t)brow*N + n0 + bc);
    blr[0] = *(const uint4*)(Btl + (size_t)brow*N + n0 + bc);
    bhr[1] = *(const uint4*)(Bth + (size_t)(brow+16)*N + n0 + bc);
    blr[1] = *(const uint4*)(Btl + (size_t)(brow+16)*N + n0 + bc);

    const uint32_t AhB = su32(Ah), AlB = su32(Al), BhB = su32(Bh), BlB = su32(Bl);
    uint32_t a_off[2], b_off[2];
#pragma unroll
    for (int mt = 0; mt < 2; mt++)
        a_off[mt] = (uint32_t)(((wm*32 + mt*16 + (lane & 15))*ASTR + (lane >> 4)*8) * 2);
#pragma unroll
    for (int p = 0; p < 2; p++)
        b_off[p] = (uint32_t)(((lane & 15)*BSTR + wn*32 + p*16 + (lane >> 4)*8) * 2);

    const int nst = K >> 5;
    for (int kt = 0; kt < nst; kt++) {
        const int kb = kt * 32;
        if (MODE == 1) {
            float px = spx[arow], py = spy[arow], pz = spz[arow];
            float v[8];
#pragma unroll
            for (int e = 0; e < 8; e++) {
                int c = kb + ac + e;
                float hh = sbp[c];
                hh = fmaf(px,  swp[c],     hh);
                hh = fmaf(py,  swp[64+c],  hh);
                hh = fmaf(pz,  swp[128+c], hh);
                hh = fmaf(dtv, swp[192+c], hh);
                float x = fmaf(hh, sps[c], ssh[c]);
                v[e] = (x >= 0.f) ? x : SLOPE*x;
            }
            uint4 H, L;
            pack8(v, H, L);
            *(uint4*)&Ah[arow*ASTR + ac] = H;
            *(uint4*)&Al[arow*ASTR + ac] = L;
        } else {
            float v[8] = {a0r.x, a0r.y, a0r.z, a0r.w, a1r.x, a1r.y, a1r.z, a1r.w};
            if (MODE == 2) {
                int c = kb + ac;
#pragma unroll
                for (int e = 0; e < 8; e++) {
                    float x = fmaf(v[e], ssc[c+e], ssh2[c+e]);
                    v[e] = (x >= 0.f) ? x : SLOPE*x;
                }
            }
            uint4 H, L;
            pack8(v, H, L);
            *(uint4*)&Ah[arow*ASTR + ac] = H;
            *(uint4*)&Al[arow*ASTR + ac] = L;
        }
        *(uint4*)&Bh[brow*BSTR + bc] = bhr[0];
        *(uint4*)&Bl[brow*BSTR + bc] = blr[0];
        *(uint4*)&Bh[(brow+16)*BSTR + bc] = bhr[1];
        *(uint4*)&Bl[(brow+16)*BSTR + bc] = blr[1];
        __syncthreads();

        if (kt + 1 < nst) {
            const int kn = kb + 32;
            if (MODE != 1) {
                a0r = *(const float4*)(A + (size_t)(m0 + arow)*K + kn + ac);
                a1r = *(const float4*)(A + (size_t)(m0 + arow)*K + kn + ac + 4);
            }
            bhr[0] = *(const uint4*)(Bth + (size_t)(kn + brow)*N + n0 + bc);
            blr[0] = *(const uint4*)(Btl + (size_t)(kn + brow)*N + n0 + bc);
            bhr[1] = *(const uint4*)(Bth + (size_t)(kn + brow + 16)*N + n0 + bc);
            blr[1] = *(const uint4*)(Btl + (size_t)(kn + brow + 16)*N + n0 + bc);
        }

#pragma unroll
        for (int ko = 0; ko < 2; ko++) {
            uint32_t ah[2][4], al_[2][4];
#pragma unroll
            for (int mt = 0; mt < 2; mt++) {
                ldsm4(ah[mt],  AhB + a_off[mt] + ko*32);
                ldsm4(al_[mt], AlB + a_off[mt] + ko*32);
            }
            uint32_t bh[4][2], bl[4][2];
#pragma unroll
            for (int p = 0; p < 2; p++) {
                uint32_t r[4];
                ldsm4t(r, BhB + b_off[p] + ko*16*BSTR*2);
                bh[2*p][0] = r[0]; bh[2*p][1] = r[1];
                bh[2*p+1][0] = r[2]; bh[2*p+1][1] = r[3];
                ldsm4t(r, BlB + b_off[p] + ko*16*BSTR*2);
                bl[2*p][0] = r[0]; bl[2*p][1] = r[1];
                bl[2*p+1][0] = r[2]; bl[2*p+1][1] = r[3];
            }
#pragma unroll
            for (int mt = 0; mt < 2; mt++)
#pragma unroll
                for (int nt = 0; nt < 4; nt++) {
                    mma16816(acc[mt][nt], ah[mt],  bh[nt]);
                    mma16816(acc[mt][nt], ah[mt],  bl[nt]);
                    mma16816(acc[mt][nt], al_[mt], bh[nt]);
                }
        }
        __syncthreads();
    }

    // ---- epilogue ----
    float colS[8], colQ[8];
#pragma unroll
    for (int i = 0; i < 8; i++) { colS[i] = 0.f; colQ[i] = 0.f; }

#pragma unroll
    for (int mt = 0; mt < 2; mt++) {
        int r0 = m0 + wm*32 + mt*16 + (lane >> 2);
        int r1 = r0 + 8;
        int j0 = 0, j1 = 0, p0 = 0, p1 = 0;
        if (MODE == 1) {
            j0 = g_idx[r0]; j1 = g_idx[r1];
            p0 = r0 >> 4;   p1 = r1 >> 4;
        }
#pragma unroll
        for (int nt = 0; nt < 4; nt++) {
            int cl = wn*32 + nt*8 + (lane & 3)*2;      // local col in [0,128)
            int c = n0 + cl;
            float v00 = acc[mt][nt][0] + sbias[cl],   v01 = acc[mt][nt][1] + sbias[cl+1];
            float v10 = acc[mt][nt][2] + sbias[cl],   v11 = acc[mt][nt][3] + sbias[cl+1];
            if (MODE == 1) {
                float2 q0 = *(const float2*)(g_q  + (size_t)p0*256 + c);
                float2 q1 = *(const float2*)(g_q  + (size_t)p1*256 + c);
                float2 k0 = *(const float2*)(g_kv + (size_t)j0*512 + c);
                float2 k1 = *(const float2*)(g_kv + (size_t)j1*512 + c);
                v00 = q0.x - k0.x + v00; v01 = q0.y - k0.y + v01;
                v10 = q1.x - k1.x + v10; v11 = q1.y - k1.y + v11;
            }
            *(float2*)(C + (size_t)r0*N + c) = make_float2(v00, v01);
            *(float2*)(C + (size_t)r1*N + c) = make_float2(v10, v11);
            if (MODE != 0) {
                colS[nt*2+0] += v00 + v10;  colS[nt*2+1] += v01 + v11;
                colQ[nt*2+0] += v00*v00 + v10*v10;
                colQ[nt*2+1] += v01*v01 + v11*v11;
            }
        }
    }
    if (MODE != 0) {
#pragma unroll
        for (int i = 0; i < 8; i++) {
#pragma unroll
            for (int off = 4; off <= 16; off <<= 1) {
                colS[i] += __shfl_xor_sync(0xffffffffu, colS[i], off);
                colQ[i] += __shfl_xor_sync(0xffffffffu, colQ[i], off);
            }
        }
        if (lane < 4) {
#pragma unroll
            for (int nt = 0; nt < 4; nt++) {
#pragma unroll
                for (int j = 0; j < 2; j++) {
                    int cl = wn*32 + nt*8 + lane*2 + j;
                    atomicAdd(&sstatS[cl], colS[nt*2+j]);
                    atomicAdd(&sstatQ[cl], colQ[nt*2+j]);
                }
            }
        }
        __syncthreads();
        if (tid < 128) {
            float* gS = (MODE == 1) ? g_s1 : g_s2;
            float* gQ = (MODE == 1) ? g_q1 : g_q2;
            atomicAdd(&gS[n0 + tid], sstatS[tid]);
            atomicAdd(&gQ[n0 + tid], sstatQ[tid]);
        }
    }
}

// ---------------- final: inline BN2 finalize + lrelu + softmax(K) + v-sum ------
// v = vf[j] + pe = u[j] + (w1 - q),  u = kf + vf precomputed
__global__ void final_kernel(float* __restrict__ out,
                             const float* __restrict__ gw2, const float* __restrict__ bw2) {
    int n = blockIdx.x, c = threadIdx.x;
    __shared__ int sidx[KNN];
    if (c < KNN) sidx[c] = g_idx[n*KNN + c];
    __syncthreads();
    float inv = 1.f / (float)NK;
    float mm = g_s2[c] * inv;
    float vv = g_q2[c] * inv - mm*mm;
    float sc = gw2[c] * rsqrtf(vv + EPS);
    float sh = bw2[c] - mm*sc;
    float qv = g_q[(size_t)n*COUT + c];
    float z[KNN], w1v[KNN];
    float m = -FLT_MAX;
#pragma unroll
    for (int k = 0; k < KNN; k++) {
        float x = g_w2[((size_t)n*KNN + k)*COUT + c];
        w1v[k] = g_w1[((size_t)n*KNN + k)*COUT + c];
        x = x*sc + sh;
        x = (x >= 0.f) ? x : SLOPE*x;
        z[k] = x;
        m = fmaxf(m, x);
    }
    float den = 0.f, num = 0.f;
#pragma unroll
    for (int k = 0; k < KNN; k++) {
        float e = __expf(z[k] - m);
        float v = g_u[(size_t)sidx[k]*256 + c] + (w1v[k] - qv);
        den += e;
        num = fmaf(e, v, num);
    }
    out[(size_t)n*COUT + c] = num / den;
}

// ---------------- launch (stream fork/join: kNN chain ∥ projection chain) ------
extern "C" void kernel_launch(void* const* d_in, const int* in_sizes, int n_in,
                              void* d_out, int out_size) {
    const float* fea_i    = (const float*)d_in[0];
    const float* fea_last = (const float*)d_in[1];
    const float* xyz_i    = (const float*)d_in[2];
    const float* xyz_last = (const float*)d_in[3];
    const float* t_i      = (const float*)d_in[4];
    const float* t_last   = (const float*)d_in[5];
    const float* wp1 = (const float*)d_in[6];
    const float* bp1 = (const float*)d_in[7];
    const float* gp  = (const float*)d_in[8];
    const float* bp  = (const float*)d_in[9];
    const float* wp2 = (const float*)d_in[10];
    const float* bp2 = (const float*)d_in[11];
    const float* wq  = (const float*)d_in[12];
    const float* bq  = (const float*)d_in[13];
    const float* wk  = (const float*)d_in[14];
    const float* bk  = (const float*)d_in[15];
    const float* wv  = (const float*)d_in[16];
    const float* bv  = (const float*)d_in[17];
    const float* gw1 = (const float*)d_in[18];
    const float* bw1 = (const float*)d_in[19];
    const float* ww  = (const float*)d_in[20];
    const float* bw  = (const float*)d_in[21];
    const float* gw2 = (const float*)d_in[22];
    const float* bw2 = (const float*)d_in[23];
    float* out = (float*)d_out;

    void* p;
    cudaGetSymbolAddress(&p, g_q);   float* p_q   = (float*)p;
    cudaGetSymbolAddress(&p, g_kv);  float* p_kv  = (float*)p;
    cudaGetSymbolAddress(&p, g_bkv); float* p_bkv = (float*)p;
    cudaGetSymbolAddress(&p, g_bth); uint16_t* p_bth = (uint16_t*)p;
    cudaGetSymbolAddress(&p, g_btl); uint16_t* p_btl = (uint16_t*)p;
    cudaGetSymbolAddress(&p, g_w1);  float* p_w1  = (float*)p;
    cudaGetSymbolAddress(&p, g_w2);  float* p_w2  = (float*)p;

    static cudaStream_t s2 = nullptr;
    static cudaEvent_t evFork = nullptr, evJoin = nullptr;
    if (s2 == nullptr) {
        cudaStreamCreateWithFlags(&s2, cudaStreamNonBlocking);
        cudaEventCreateWithFlags(&evFork, cudaEventDisableTiming);
        cudaEventCreateWithFlags(&evJoin, cudaEventDisableTiming);
    }

    // 0) prep (weight split + bias + stat zero + grid zero) on main stream
    prep_kernel<<<(TOTW + 255)/256, 256>>>(wq, wk, wv, wp2, ww, bk, bv);

    // fork: side stream s2 runs projections (depend only on prep)
    cudaEventRecord(evFork, 0);
    cudaStreamWaitEvent(s2, evFork, 0);
    mma_gemm<0><<<dim3(2, 128), 256, 0, s2>>>(fea_last, p_bth + OQ,  p_btl + OQ,  bq,    p_q,  N_PTS, 256, CIN,
                                              nullptr, nullptr, nullptr, nullptr, nullptr, nullptr, nullptr, nullptr);
    mma_gemm<0><<<dim3(4, 128), 256, 0, s2>>>(fea_i,    p_bth + OKV, p_btl + OKV, p_bkv, p_kv, N_PTS, 512, CIN,
                                              nullptr, nullptr, nullptr, nullptr, nullptr, nullptr, nullptr, nullptr);
    u_kernel<<<(N_PTS*256)/256, 256, 0, s2>>>();
    cudaEventRecord(evJoin, s2);

    // main stream: kNN chain + moments (independent of projections)
    grid_count_kernel<<<N_PTS/256, 256>>>(xyz_i);
    grid_scan_kernel<<<1, 512>>>();
    grid_scatter_kernel<<<N_PTS/256, 256>>>(xyz_i);
    knn_grid_kernel<<<N_PTS/QPB, 256>>>(xyz_last);
    moments_kernel<<<64, 256>>>(xyz_i, xyz_last);

    // join: mma<1> needs both chains
    cudaStreamWaitEvent(0, evJoin, 0);

    // 4) pe GEMM (A generated) -> w1 = q - kf + pe, + BN1 stats
    mma_gemm<1><<<dim3(2, 2048), 256>>>(nullptr, p_bth + OP2, p_btl + OP2, bp2, p_w1, NK, 256, HDIM,
                                        xyz_i, xyz_last, t_i, t_last, wp1, bp1, gp, bp);

    // 5) w2 GEMM (BN1 finalize inlined) + BN2 stats
    mma_gemm<2><<<dim3(2, 2048), 256>>>(p_w1, p_bth + OW, p_btl + OW, bw, p_w2, NK, 256, CIN,
                                        nullptr, nullptr, nullptr, nullptr, nullptr, nullptr, gw1, bw1);

    // 6) softmax over K + weighted v-sum (BN2 finalize inlined)
    final_kernel<<<N_PTS, COUT>>>(out, gw2, bw2);
}

// round 14
// speedup vs baseline: 1.2152x; 1.0223x over previous
#include <cuda_runtime.h>
#include <cuda_bf16.h>
#include <cstdint>
#include <cfloat>

#define N_PTS 8192
#define KNN   16
#define CIN   256
#define COUT  256
#define NK    (N_PTS*KNN)       // 131072
#define HDIM  64
#define SLOPE 0.01f
#define EPS   1e-5f
#define QPB   8
#define ASTR  40                // A smem row stride in halves
#define BSTR  136               // B smem row stride in halves
#define ABYTES (64*ASTR*2)      // 5120: one A tile buffer
#define BBYTES (32*BSTR*2)      // 8704: one B tile buffer

// kNN grid params
#define GDIM  8
#define GCELLS (GDIM*GDIM*GDIM)   // 512
#define KRAD  0.25f
#define KRAD2 0.0625f

// weight-split buffer offsets (natural [K,N] layout, bf16 hi/lo)
#define OQ   0
#define OKV  65536              // 256*256
#define OP2  196608             // + 256*512
#define OW   212992             // + 64*256
#define TOTW 278528             // + 256*256

// ---------------- device scratch (static, allocation-free) ----------------
__device__ int      g_idx[NK];
__device__ float    g_q  [N_PTS*COUT];
__device__ float    g_kv [N_PTS*512];     // [kf | vf]
__device__ float    g_u  [N_PTS*COUT];    // kf + vf (for final)
__device__ float    g_bkv[512];
__device__ uint16_t g_bth[TOTW];          // weights bf16 hi, [K,N]
__device__ uint16_t g_btl[TOTW];          // weights bf16 lo, [K,N]
__device__ float    g_w1 [NK*COUT];
__device__ float    g_w2 [NK*COUT];
__device__ float    g_m[9];               // pe4 moments
__device__ float    g_s1[COUT], g_q1[COUT];
__device__ float    g_s2[COUT], g_q2[COUT];
// grid structures
__device__ int      g_cellCnt[GCELLS];
__device__ int      g_cellFill[GCELLS];
__device__ int      g_cellStart[GCELLS+1];
__device__ float4   g_spts[N_PTS];
__device__ int      g_sidx[N_PTS];

// ---------------- PTX helpers ----------------
__device__ __forceinline__ uint32_t su32(const void* p) {
    return (uint32_t)__cvta_generic_to_shared(p);
}
__device__ __forceinline__ void ldsm4(uint32_t r[4], uint32_t a) {
    asm volatile("ldmatrix.sync.aligned.m8n8.x4.shared.b16 {%0,%1,%2,%3}, [%4];"
        : "=r"(r[0]), "=r"(r[1]), "=r"(r[2]), "=r"(r[3]) : "r"(a));
}
__device__ __forceinline__ void ldsm4t(uint32_t r[4], uint32_t a) {
    asm volatile("ldmatrix.sync.aligned.m8n8.x4.trans.shared.b16 {%0,%1,%2,%3}, [%4];"
        : "=r"(r[0]), "=r"(r[1]), "=r"(r[2]), "=r"(r[3]) : "r"(a));
}
__device__ __forceinline__ void mma16816(float c[4], const uint32_t a[4], const uint32_t b[2]) {
    asm volatile("mma.sync.aligned.m16n8k16.row.col.f32.bf16.bf16.f32 "
        "{%0,%1,%2,%3}, {%4,%5,%6,%7}, {%8,%9}, {%0,%1,%2,%3};"
        : "+f"(c[0]), "+f"(c[1]), "+f"(c[2]), "+f"(c[3])
        : "r"(a[0]), "r"(a[1]), "r"(a[2]), "r"(a[3]), "r"(b[0]), "r"(b[1]));
}
__device__ __forceinline__ void split1(float x, uint16_t& hi, uint16_t& lo) {
    __nv_bfloat16 h = __float2bfloat16_rn(x);
    __nv_bfloat16 l = __float2bfloat16_rn(x - __bfloat162float(h));
    hi = *(uint16_t*)&h; lo = *(uint16_t*)&l;
}
// vectorized: per 2 elements one cvt.rn.bf16x2.f32 for hi and one for lo
__device__ __forceinline__ void pack8(const float* v, uint4& H, uint4& L) {
    uint32_t* hp = (uint32_t*)&H;
    uint32_t* lp = (uint32_t*)&L;
#pragma unroll
    for (int i = 0; i < 4; i++) {
        float x0 = v[2*i], x1 = v[2*i+1];
        __nv_bfloat162 h2 = __floats2bfloat162_rn(x0, x1);
        float h0 = __low2float(h2), h1 = __high2float(h2);
        __nv_bfloat162 l2 = __floats2bfloat162_rn(x0 - h0, x1 - h1);
        hp[i] = *(uint32_t*)&h2;
        lp[i] = *(uint32_t*)&l2;
    }
}

// ---------------- prep: weight split + bias concat + zero stats + grid zero ----
__global__ void prep_kernel(const float* __restrict__ wq,
                            const float* __restrict__ wk, const float* __restrict__ wv,
                            const float* __restrict__ wp2, const float* __restrict__ ww,
                            const float* __restrict__ bk, const float* __restrict__ bv) {
    int i = blockIdx.x * 256 + threadIdx.x;
    if (i < TOTW) {
        float val;
        if (i < OKV) {                       // wq [256,256]
            val = wq[i];
        } else if (i < OP2) {                // wkv [256,512]: row k = [wk_k | wv_k]
            int j = i - OKV, k = j >> 9, n = j & 511;
            val = (n < 256) ? wk[k*256 + n] : wv[k*256 + (n - 256)];
        } else if (i < OW) {                 // wp2 [64,256]
            val = wp2[i - OP2];
        } else {                             // ww [256,256]
            val = ww[i - OW];
        }
        uint16_t h, l;
        split1(val, h, l);
        g_bth[i] = h; g_btl[i] = l;
    }
    if (i < 512) {
        g_bkv[i] = (i < 256) ? bk[i] : bv[i - 256];
        g_cellCnt[i] = 0;
    }
    if (i < 9) g_m[i] = 0.f;
    if (i < COUT) { g_s1[i] = 0.f; g_q1[i] = 0.f; g_s2[i] = 0.f; g_q2[i] = 0.f; }
}

// ---------------- u = kf + vf ----------------
__global__ void u_kernel() {
    int i = blockIdx.x * 256 + threadIdx.x;     // N_PTS*256
    int r = i >> 8, c = i & 255;
    g_u[i] = g_kv[(size_t)r*512 + c] + g_kv[(size_t)r*512 + 256 + c];
}

// ---------------- kNN: exact grid-accelerated, integrated fallback ----------------
__device__ __forceinline__ float norm3_ref(float x, float y, float z) {
    return __fadd_rn(__fadd_rn(__fmul_rn(x, x), __fmul_rn(y, y)), __fmul_rn(z, z));
}
__device__ __forceinline__ int gcell(float v) {
    int c = (int)(v * (float)GDIM);
    return c < 0 ? 0 : (c > GDIM-1 ? GDIM-1 : c);
}

__global__ void grid_count_kernel(const float* __restrict__ xyz_i) {
    int i = blockIdx.x * 256 + threadIdx.x;
    if (i >= N_PTS) return;
    int cx = gcell(xyz_i[i*3+0]);
    int cy = gcell(xyz_i[i*3+1]);
    int cz = gcell(xyz_i[i*3+2]);
    atomicAdd(&g_cellCnt[(cz*GDIM + cy)*GDIM + cx], 1);
}
__global__ void grid_scan_kernel() {
    __shared__ int s[GCELLS];
    int t = threadIdx.x;                  // 512
    int own = g_cellCnt[t];
    s[t] = own;
    __syncthreads();
    for (int off = 1; off < GCELLS; off <<= 1) {
        int u = 0;
        if (t >= off) u = s[t - off];
        __syncthreads();
        s[t] += u;
        __syncthreads();
    }
    g_cellStart[t] = s[t] - own;          // exclusive
    if (t == GCELLS-1) g_cellStart[GCELLS] = N_PTS;
    g_cellFill[t] = 0;
}
__global__ void grid_scatter_kernel(const float* __restrict__ xyz_i) {
    int i = blockIdx.x * 256 + threadIdx.x;
    if (i >= N_PTS) return;
    float x = xyz_i[i*3+0], y = xyz_i[i*3+1], z = xyz_i[i*3+2];
    int cell = (gcell(z)*GDIM + gcell(y))*GDIM + gcell(x);
    int pos = g_cellStart[cell] + atomicAdd(&g_cellFill[cell], 1);
    g_spts[pos] = make_float4(x, y, z, norm3_ref(x, y, z));
    g_sidx[pos] = i;
}

// warp per query: grid cells within KRAD; exact d2; lexicographic top-16;
// integrated exact fallback (full scan over sorted array) if radius insufficient.
__global__ void knn_grid_kernel(const float* __restrict__ xyz_last) {
    __shared__ float ld[QPB][KNN][32];
    __shared__ int   li[QPB][KNN][32];
    const int tid = threadIdx.x;
    const int w = tid >> 5, lane = tid & 31;
    const int q = blockIdx.x * QPB + w;
    const float qx = xyz_last[q*3+0];
    const float qy = xyz_last[q*3+1];
    const float qz = xyz_last[q*3+2];
    const float nq = norm3_ref(qx, qy, qz);
    const float cw = 1.f / (float)GDIM;

    float dist[KNN];
    int   idx [KNN];
#pragma unroll
    for (int j = 0; j < KNN; j++) { dist[j] = FLT_MAX; idx[j] = 0x7fffffff; }

    int zlo = (int)floorf((qz - KRAD) * (float)GDIM); if (zlo < 0) zlo = 0;
    int zhi = (int)floorf((qz + KRAD) * (float)GDIM); if (zhi > GDIM-1) zhi = GDIM-1;
    int ylo = (int)floorf((qy - KRAD) * (float)GDIM); if (ylo < 0) ylo = 0;
    int yhi = (int)floorf((qy + KRAD) * (float)GDIM); if (yhi > GDIM-1) yhi = GDIM-1;

    for (int z = zlo; z <= zhi; z++) {
        float dz = fmaxf(0.f, fmaxf((float)z * cw - qz, qz - (float)(z+1) * cw));
        float dz2 = dz * dz;
        for (int y = ylo; y <= yhi; y++) {
            float dy = fmaxf(0.f, fmaxf((float)y * cw - qy, qy - (float)(y+1) * cw));
            float dyz2 = dz2 + dy * dy;
            if (dyz2 > KRAD2) continue;
            float xr = sqrtf(KRAD2 - dyz2) + 1e-6f;
            int xlo = (int)floorf((qx - xr) * (float)GDIM); if (xlo < 0) xlo = 0;
            int xhi = (int)floorf((qx + xr) * (float)GDIM); if (xhi > GDIM-1) xhi = GDIM-1;
            int base = (z*GDIM + y)*GDIM;
            int s = g_cellStart[base + xlo];
            int e = g_cellStart[base + xhi + 1];
            for (int i = s + lane; i < e; i += 32) {
                float4 pv = g_spts[i];
                float t = __fmul_rn(qx, pv.x);
                t = __fmaf_rn(qy, pv.y, t);
                t = __fmaf_rn(qz, pv.z, t);
                float d2 = __fsub_rn(__fadd_rn(nq, pv.w), __fmul_rn(2.0f, t));
                int gi = g_sidx[i];
                bool ins = (d2 < dist[KNN-1]) || (d2 == dist[KNN-1] && gi < idx[KNN-1]);
                if (ins) {
                    dist[KNN-1] = d2;
                    idx[KNN-1]  = gi;
#pragma unroll
                    for (int j = KNN-1; j > 0; j--) {
                        float da = dist[j-1], db = dist[j];
                        int   ia = idx[j-1],  ib = idx[j];
                        bool sw = (db < da) || (db == da && ib < ia);
                        dist[j-1] = sw ? db : da;
                        dist[j]   = sw ? da : db;
                        idx[j-1]  = sw ? ib : ia;
                        idx[j]    = sw ? ia : ib;
                    }
                }
            }
        }
    }
#pragma unroll
    for (int j = 0; j < KNN; j++) { ld[w][j][lane] = dist[j]; li[w][j][lane] = idx[j]; }
    __syncwarp();

    int pos = 0;
    float last_v = FLT_MAX;
    for (int r = 0; r < KNN; r++) {
        float v = (pos < KNN) ? ld[w][pos][lane] : FLT_MAX;
        int  gi = (pos < KNN) ? li[w][pos][lane] : 0x7fffffff;
        int  owner = lane;
#pragma unroll
        for (int off = 16; off > 0; off >>= 1) {
            float v2  = __shfl_xor_sync(0xffffffffu, v, off);
            int   g2  = __shfl_xor_sync(0xffffffffu, gi, off);
            int   o2  = __shfl_xor_sync(0xffffffffu, owner, off);
            if (v2 < v || (v2 == v && g2 < gi)) { v = v2; gi = g2; owner = o2; }
        }
        if (lane == 0) g_idx[q*KNN + r] = gi;
        last_v = v;
        if (lane == owner) pos++;
    }
    // soundness: all non-enumerated points have d2 > KRAD2 (minus fp slack)
    if (!(last_v + 1e-4f < KRAD2)) {
        // exact fallback: full scan over sorted array (warp-local, rare)
#pragma unroll
        for (int j = 0; j < KNN; j++) { dist[j] = FLT_MAX; idx[j] = 0x7fffffff; }
        for (int i = lane; i < N_PTS; i += 32) {
            float4 pv = g_spts[i];
            float t = __fmul_rn(qx, pv.x);
            t = __fmaf_rn(qy, pv.y, t);
            t = __fmaf_rn(qz, pv.z, t);
            float d2 = __fsub_rn(__fadd_rn(nq, pv.w), __fmul_rn(2.0f, t));
            int gi = g_sidx[i];
            bool ins = (d2 < dist[KNN-1]) || (d2 == dist[KNN-1] && gi < idx[KNN-1]);
            if (ins) {
                dist[KNN-1] = d2;
                idx[KNN-1]  = gi;
#pragma unroll
                for (int j = KNN-1; j > 0; j--) {
                    float da = dist[j-1], db = dist[j];
                    int   ia = idx[j-1],  ib = idx[j];
                    bool sw = (db < da) || (db == da && ib < ia);
                    dist[j-1] = sw ? db : da;
                    dist[j]   = sw ? da : db;
                    idx[j-1]  = sw ? ib : ia;
                    idx[j]    = sw ? ia : ib;
                }
            }
        }
#pragma unroll
        for (int j = 0; j < KNN; j++) { ld[w][j][lane] = dist[j]; li[w][j][lane] = idx[j]; }
        __syncwarp();
        pos = 0;
        for (int r = 0; r < KNN; r++) {
            float v = (pos < KNN) ? ld[w][pos][lane] : FLT_MAX;
            int  gi = (pos < KNN) ? li[w][pos][lane] : 0x7fffffff;
            int  owner = lane;
#pragma unroll
            for (int off = 16; off > 0; off >>= 1) {
                float v2  = __shfl_xor_sync(0xffffffffu, v, off);
                int   g2  = __shfl_xor_sync(0xffffffffu, gi, off);
                int   o2  = __shfl_xor_sync(0xffffffffu, owner, off);
                if (v2 < v || (v2 == v && g2 < gi)) { v = v2; gi = g2; owner = o2; }
            }
            if (lane == 0) g_idx[q*KNN + r] = gi;
            if (lane == owner) pos++;
        }
    }
}

// ---------------- pe4 moments ----------------
__global__ void moments_kernel(const float* __restrict__ xyz_i,
                               const float* __restrict__ xyz_last) {
    float a0=0,a1=0,a2=0,a3=0,a4=0,a5=0,a6=0,a7=0,a8=0;
    for (int s = blockIdx.x * 256 + threadIdx.x; s < NK; s += gridDim.x * 256) {
        int n = s >> 4;
        int j = g_idx[s];
        float x = xyz_i[j*3+0] - xyz_last[n*3+0];
        float y = xyz_i[j*3+1] - xyz_last[n*3+1];
        float z = xyz_i[j*3+2] - xyz_last[n*3+2];
        a0 += x; a1 += y; a2 += z;
        a3 = fmaf(x,x,a3); a4 = fmaf(y,y,a4); a5 = fmaf(z,z,a5);
        a6 = fmaf(x,y,a6); a7 = fmaf(x,z,a7); a8 = fmaf(y,z,a8);
    }
    float v[9] = {a0,a1,a2,a3,a4,a5,a6,a7,a8};
#pragma unroll
    for (int i = 0; i < 9; i++) {
#pragma unroll
        for (int off = 16; off > 0; off >>= 1)
            v[i] += __shfl_xor_sync(0xffffffffu, v[i], off);
    }
    if ((threadIdx.x & 31) == 0) {
#pragma unroll
        for (int i = 0; i < 9; i++) atomicAdd(&g_m[i], v[i]);
    }
}

// ---------------- mma.sync GEMM: 64x128 tile, 256 thr, 2 CTAs/SM, double-buffered ----
// MODE 0: plain; MODE 1: A generated from xyz (pe), BN-pe affine inline from g_m,
//         C := w1 = q - kf[idx] + pe, BN1 stats;
// MODE 2: f = lrelu(x*bn1) with bn1 affine inline from g_s1/g_q1, C := w2, BN2 stats
template<int MODE>
__global__ __launch_bounds__(256, 2)
void mma_gemm(const float* __restrict__ A,
              const uint16_t* __restrict__ Bth, const uint16_t* __restrict__ Btl,
              const float* __restrict__ bias, float* __restrict__ C,
              int M, int N, int K,
              const float* __restrict__ xyz_i, const float* __restrict__ xyz_last,
              const float* __restrict__ t_i, const float* __restrict__ t_last,
              const float* __restrict__ wp1, const float* __restrict__ bp1,
              const float* __restrict__ gma, const float* __restrict__ bta) {
    __shared__ __align__(16) uint16_t Ah[2*64*ASTR], Al[2*64*ASTR];
    __shared__ __align__(16) uint16_t Bh[2*32*BSTR], Bl[2*32*BSTR];
    __shared__ float spx[64], spy[64], spz[64];
    __shared__ float swp[256], sbp[64], sps[64], ssh[64];
    __shared__ float ssc[256], ssh2[256];
    __shared__ float sbias[128], sstatS[128], sstatQ[128];

    const int tid = threadIdx.x;
    const int lane = tid & 31, wid = tid >> 5;
    const int wm = wid >> 2, wn = wid & 3;          // 2x4 warp grid, 32x32 tiles
    const int m0 = blockIdx.y * 64, n0 = blockIdx.x * 128;

    float dtv = 0.f;
    if (MODE == 1) {
        if (tid < 64) {
            int m = m0 + tid;
            int n = m >> 4;
            int j = g_idx[m];
            spx[tid] = xyz_i[j*3+0] - xyz_last[n*3+0];
            spy[tid] = xyz_i[j*3+1] - xyz_last[n*3+1];
            spz[tid] = xyz_i[j*3+2] - xyz_last[n*3+2];
        }
        swp[tid] = wp1[tid];
        dtv = t_i[0] - t_last[0];
        if (tid < 64) {
            // inline finalize_pe: analytic BN over generated h
            float inv = 1.f / (float)NK;
            float mx = g_m[0]*inv, my = g_m[1]*inv, mz = g_m[2]*inv;
            float exx = g_m[3]*inv, eyy = g_m[4]*inv, ezz = g_m[5]*inv;
            float exy = g_m[6]*inv, exz = g_m[7]*inv, eyz = g_m[8]*inv;
            float w0 = wp1[tid], w1 = wp1[64+tid], w2 = wp1[128+tid], w3 = wp1[192+tid];
            float a  = bp1[tid] + w3*dtv;
            float lm = w0*mx + w1*my + w2*mz;
            float mean = a + lm;
            float e2 = a*a + 2.f*a*lm
                     + w0*w0*exx + w1*w1*eyy + w2*w2*ezz
                     + 2.f*(w0*w1*exy + w0*w2*exz + w1*w2*eyz);
            float var = e2 - mean*mean;
            float s = gma[tid] * rsqrtf(var + EPS);
            sps[tid] = s;
            ssh[tid] = bta[tid] - mean*s;
            sbp[tid] = bp1[tid];
        }
    }
    if (MODE == 2) {
        // inline finalize BN1
        float inv = 1.f / (float)NK;
        float m = g_s1[tid] * inv;
        float v = g_q1[tid] * inv - m*m;
        float s = gma[tid] * rsqrtf(v + EPS);
        ssc[tid]  = s;
        ssh2[tid] = bta[tid] - m*s;
    }
    if (tid < 128) { sbias[tid] = bias[n0 + tid]; sstatS[tid] = 0.f; sstatQ[tid] = 0.f; }
    if (MODE == 1 || MODE == 2) __syncthreads();

    float acc[2][4][4];
#pragma unroll
    for (int i = 0; i < 2; i++)
#pragma unroll
        for (int j = 0; j < 4; j++)
#pragma unroll
            for (int e = 0; e < 4; e++) acc[i][j][e] = 0.f;

    const int arow = tid >> 2, ac = (tid & 3) * 8;     // A: 64 rows x 32 k
    const int brow = tid >> 4, bc = (tid & 15) * 8;    // B: rows brow, brow+16 x 128 n

    float4 a0r, a1r;
    uint4 bhr[2], blr[2];
    const uint32_t AhB = su32(Ah), AlB = su32(Al), BhB = su32(Bh), BlB = su32(Bl);
    uint32_t a_off[2], b_off[2];
#pragma unroll
    for (int mt = 0; mt < 2; mt++)
        a_off[mt] = (uint32_t)(((wm*32 + mt*16 + (lane & 15))*ASTR + (lane >> 4)*8) * 2);
#pragma unroll
    for (int p = 0; p < 2; p++)
        b_off[p] = (uint32_t)(((lane & 15)*BSTR + wn*32 + p*16 + (lane >> 4)*8) * 2);

    const int nst = K >> 5;

    // ---- preamble: load stage 0 regs, store to buf 0, prefetch stage 1 regs ----
    if (MODE != 1) {
        a0r = *(const float4*)(A + (size_t)(m0 + arow)*K + ac);
        a1r = *(const float4*)(A + (size_t)(m0 + arow)*K + ac + 4);
    }
    bhr[0] = *(const uint4*)(Bth + (size_t)brow*N + n0 + bc);
    blr[0] = *(const uint4*)(Btl + (size_t)brow*N + n0 + bc);
    bhr[1] = *(const uint4*)(Bth + (size_t)(brow+16)*N + n0 + bc);
    blr[1] = *(const uint4*)(Btl + (size_t)(brow+16)*N + n0 + bc);

    for (int kt = 0; kt < nst; kt++) {
        const int kb = kt * 32;
        const int sb = (kt & 1);             // store buffer for THIS stage
        // ---- store stage kt into buf sb (regs were loaded for stage kt) ----
        {
            float v[8];
            if (MODE == 1) {
                float px = spx[arow], py = spy[arow], pz = spz[arow];
#pragma unroll
                for (int e = 0; e < 8; e++) {
                    int c = kb + ac + e;
                    float hh = sbp[c];
                    hh = fmaf(px,  swp[c],     hh);
                    hh = fmaf(py,  swp[64+c],  hh);
                    hh = fmaf(pz,  swp[128+c], hh);
                    hh = fmaf(dtv, swp[192+c], hh);
                    float x = fmaf(hh, sps[c], ssh[c]);
                    v[e] = (x >= 0.f) ? x : SLOPE*x;
                }
            } else {
                v[0]=a0r.x; v[1]=a0r.y; v[2]=a0r.z; v[3]=a0r.w;
                v[4]=a1r.x; v[5]=a1r.y; v[6]=a1r.z; v[7]=a1r.w;
                if (MODE == 2) {
                    int c = kb + ac;
#pragma unroll
                    for (int e = 0; e < 8; e++) {
                        float x = fmaf(v[e], ssc[c+e], ssh2[c+e]);
                        v[e] = (x >= 0.f) ? x : SLOPE*x;
                    }
                }
            }
            uint4 H, L;
            pack8(v, H, L);
            int aidx = sb*(64*ASTR) + arow*ASTR + ac;
            *(uint4*)&Ah[aidx] = H;
            *(uint4*)&Al[aidx] = L;
            int bidx = sb*(32*BSTR) + brow*BSTR + bc;
            *(uint4*)&Bh[bidx] = bhr[0];
            *(uint4*)&Bl[bidx] = blr[0];
            *(uint4*)&Bh[bidx + 16*BSTR] = bhr[1];
            *(uint4*)&Bl[bidx + 16*BSTR] = blr[1];
        }
        // ---- prefetch regs for stage kt+1 (overlaps with barrier/compute) ----
        if (kt + 1 < nst) {
            const int kn = kb + 32;
            if (MODE != 1) {
                a0r = *(const float4*)(A + (size_t)(m0 + arow)*K + kn + ac);
                a1r = *(const float4*)(A + (size_t)(m0 + arow)*K + kn + ac + 4);
            }
            bhr[0] = *(const uint4*)(Bth + (size_t)(kn + brow)*N + n0 + bc);
            blr[0] = *(const uint4*)(Btl + (size_t)(kn + brow)*N + n0 + bc);
            bhr[1] = *(const uint4*)(Bth + (size_t)(kn + brow + 16)*N + n0 + bc);
            blr[1] = *(const uint4*)(Btl + (size_t)(kn + brow + 16)*N + n0 + bc);
        }
        __syncthreads();      // buf sb now full for all threads

        // ---- compute stage kt from buf sb ----
        const uint32_t ab = (uint32_t)(sb * ABYTES);
        const uint32_t bb = (uint32_t)(sb * BBYTES);
#pragma unroll
        for (int ko = 0; ko < 2; ko++) {
            uint32_t ah[2][4], al_[2][4];
#pragma unroll
            for (int mt = 0; mt < 2; mt++) {
                ldsm4(ah[mt],  AhB + ab + a_off[mt] + ko*32);
                ldsm4(al_[mt], AlB + ab + a_off[mt] + ko*32);
            }
            uint32_t bh[4][2], bl[4][2];
#pragma unroll
            for (int p = 0; p < 2; p++) {
                uint32_t r[4];
                ldsm4t(r, BhB + bb + b_off[p] + ko*16*BSTR*2);
                bh[2*p][0] = r[0]; bh[2*p][1] = r[1];
                bh[2*p+1][0] = r[2]; bh[2*p+1][1] = r[3];
                ldsm4t(r, BlB + bb + b_off[p] + ko*16*BSTR*2);
                bl[2*p][0] = r[0]; bl[2*p][1] = r[1];
                bl[2*p+1][0] = r[2]; bl[2*p+1][1] = r[3];
            }
#pragma unroll
            for (int mt = 0; mt < 2; mt++)
#pragma unroll
                for (int nt = 0; nt < 4; nt++) {
                    mma16816(acc[mt][nt], ah[mt],  bh[nt]);
                    mma16816(acc[mt][nt], ah[mt],  bl[nt]);
                    mma16816(acc[mt][nt], al_[mt], bh[nt]);
                }
        }
        // no trailing sync: next iteration stores into the OTHER buffer,
        // which all threads finished reading before the previous barrier.
    }

    // ---- epilogue ----
    float colS[8], colQ[8];
#pragma unroll
    for (int i = 0; i < 8; i++) { colS[i] = 0.f; colQ[i] = 0.f; }

#pragma unroll
    for (int mt = 0; mt < 2; mt++) {
        int r0 = m0 + wm*32 + mt*16 + (lane >> 2);
        int r1 = r0 + 8;
        int j0 = 0, j1 = 0, p0 = 0, p1 = 0;
        if (MODE == 1) {
            j0 = g_idx[r0]; j1 = g_idx[r1];
            p0 = r0 >> 4;   p1 = r1 >> 4;
        }
#pragma unroll
        for (int nt = 0; nt < 4; nt++) {
            int cl = wn*32 + nt*8 + (lane & 3)*2;      // local col in [0,128)
            int c = n0 + cl;
            float v00 = acc[mt][nt][0] + sbias[cl],   v01 = acc[mt][nt][1] + sbias[cl+1];
            float v10 = acc[mt][nt][2] + sbias[cl],   v11 = acc[mt][nt][3] + sbias[cl+1];
            if (MODE == 1) {
                float2 q0 = *(const float2*)(g_q  + (size_t)p0*256 + c);
                float2 q1 = *(const float2*)(g_q  + (size_t)p1*256 + c);
                float2 k0 = *(const float2*)(g_kv + (size_t)j0*512 + c);
                float2 k1 = *(const float2*)(g_kv + (size_t)j1*512 + c);
                v00 = q0.x - k0.x + v00; v01 = q0.y - k0.y + v01;
                v10 = q1.x - k1.x + v10; v11 = q1.y - k1.y + v11;
            }
            *(float2*)(C + (size_t)r0*N + c) = make_float2(v00, v01);
            *(float2*)(C + (size_t)r1*N + c) = make_float2(v10, v11);
            if (MODE != 0) {
                colS[nt*2+0] += v00 + v10;  colS[nt*2+1] += v01 + v11;
                colQ[nt*2+0] += v00*v00 + v10*v10;
                colQ[nt*2+1] += v01*v01 + v11*v11;
            }
        }
    }
    if (MODE != 0) {
#pragma unroll
        for (int i = 0; i < 8; i++) {
#pragma unroll
            for (int off = 4; off <= 16; off <<= 1) {
                colS[i] += __shfl_xor_sync(0xffffffffu, colS[i], off);
                colQ[i] += __shfl_xor_sync(0xffffffffu, colQ[i], off);
            }
        }
        if (lane < 4) {
#pragma unroll
            for (int nt = 0; nt < 4; nt++) {
#pragma unroll
                for (int j = 0; j < 2; j++) {
                    int cl = wn*32 + nt*8 + lane*2 + j;
                    atomicAdd(&sstatS[cl], colS[nt*2+j]);
                    atomicAdd(&sstatQ[cl], colQ[nt*2+j]);
                }
            }
        }
        __syncthreads();
        if (tid < 128) {
            float* gS = (MODE == 1) ? g_s1 : g_s2;
            float* gQ = (MODE == 1) ? g_q1 : g_q2;
            atomicAdd(&gS[n0 + tid], sstatS[tid]);
            atomicAdd(&gQ[n0 + tid], sstatQ[tid]);
        }
    }
}

// ---------------- final: inline BN2 finalize + lrelu + softmax(K) + v-sum ------
// v = vf[j] + pe = u[j] + (w1 - q),  u = kf + vf precomputed
__global__ void final_kernel(float* __restrict__ out,
                             const float* __restrict__ gw2, const float* __restrict__ bw2) {
    int n = blockIdx.x, c = threadIdx.x;
    __shared__ int sidx[KNN];
    if (c < KNN) sidx[c] = g_idx[n*KNN + c];
    __syncthreads();
    float inv = 1.f / (float)NK;
    float mm = g_s2[c] * inv;
    float vv = g_q2[c] * inv - mm*mm;
    float sc = gw2[c] * rsqrtf(vv + EPS);
    float sh = bw2[c] - mm*sc;
    float qv = g_q[(size_t)n*COUT + c];
    float z[KNN], w1v[KNN];
    float m = -FLT_MAX;
#pragma unroll
    for (int k = 0; k < KNN; k++) {
        float x = g_w2[((size_t)n*KNN + k)*COUT + c];
        w1v[k] = g_w1[((size_t)n*KNN + k)*COUT + c];
        x = x*sc + sh;
        x = (x >= 0.f) ? x : SLOPE*x;
        z[k] = x;
        m = fmaxf(m, x);
    }
    float den = 0.f, num = 0.f;
#pragma unroll
    for (int k = 0; k < KNN; k++) {
        float e = __expf(z[k] - m);
        float v = g_u[(size_t)sidx[k]*256 + c] + (w1v[k] - qv);
        den += e;
        num = fmaf(e, v, num);
    }
    out[(size_t)n*COUT + c] = num / den;
}

// ---------------- launch (stream fork/join: kNN chain ∥ projection chain) ------
extern "C" void kernel_launch(void* const* d_in, const int* in_sizes, int n_in,
                              void* d_out, int out_size) {
    const float* fea_i    = (const float*)d_in[0];
    const float* fea_last = (const float*)d_in[1];
    const float* xyz_i    = (const float*)d_in[2];
    const float* xyz_last = (const float*)d_in[3];
    const float* t_i      = (const float*)d_in[4];
    const float* t_last   = (const float*)d_in[5];
    const float* wp1 = (const float*)d_in[6];
    const float* bp1 = (const float*)d_in[7];
    const float* gp  = (const float*)d_in[8];
    const float* bp  = (const float*)d_in[9];
    const float* wp2 = (const float*)d_in[10];
    const float* bp2 = (const float*)d_in[11];
    const float* wq  = (const float*)d_in[12];
    const float* bq  = (const float*)d_in[13];
    const float* wk  = (const float*)d_in[14];
    const float* bk  = (const float*)d_in[15];
    const float* wv  = (const float*)d_in[16];
    const float* bv  = (const float*)d_in[17];
    const float* gw1 = (const float*)d_in[18];
    const float* bw1 = (const float*)d_in[19];
    const float* ww  = (const float*)d_in[20];
    const float* bw  = (const float*)d_in[21];
    const float* gw2 = (const float*)d_in[22];
    const float* bw2 = (const float*)d_in[23];
    float* out = (float*)d_out;

    void* p;
    cudaGetSymbolAddress(&p, g_q);   float* p_q   = (float*)p;
    cudaGetSymbolAddress(&p, g_kv);  float* p_kv  = (float*)p;
    cudaGetSymbolAddress(&p, g_bkv); float* p_bkv = (float*)p;
    cudaGetSymbolAddress(&p, g_bth); uint16_t* p_bth = (uint16_t*)p;
    cudaGetSymbolAddress(&p, g_btl); uint16_t* p_btl = (uint16_t*)p;
    cudaGetSymbolAddress(&p, g_w1);  float* p_w1  = (float*)p;
    cudaGetSymbolAddress(&p, g_w2);  float* p_w2  = (float*)p;

    static cudaStream_t s2 = nullptr;
    static cudaEvent_t evFork = nullptr, evJoin = nullptr;
    if (s2 == nullptr) {
        cudaStreamCreateWithFlags(&s2, cudaStreamNonBlocking);
        cudaEventCreateWithFlags(&evFork, cudaEventDisableTiming);
        cudaEventCreateWithFlags(&evJoin, cudaEventDisableTiming);
    }

    // 0) prep (weight split + bias + stat zero + grid zero) on main stream
    prep_kernel<<<(TOTW + 255)/256, 256>>>(wq, wk, wv, wp2, ww, bk, bv);

    // fork: side stream s2 runs projections (depend only on prep)
    cudaEventRecord(evFork, 0);
    cudaStreamWaitEvent(s2, evFork, 0);
    mma_gemm<0><<<dim3(2, 128), 256, 0, s2>>>(fea_last, p_bth + OQ,  p_btl + OQ,  bq,    p_q,  N_PTS, 256, CIN,
                                              nullptr, nullptr, nullptr, nullptr, nullptr, nullptr, nullptr, nullptr);
    mma_gemm<0><<<dim3(4, 128), 256, 0, s2>>>(fea_i,    p_bth + OKV, p_btl + OKV, p_bkv, p_kv, N_PTS, 512, CIN,
                                              nullptr, nullptr, nullptr, nullptr, nullptr, nullptr, nullptr, nullptr);
    u_kernel<<<(N_PTS*256)/256, 256, 0, s2>>>();
    cudaEventRecord(evJoin, s2);

    // main stream: kNN chain + moments (independent of projections)
    grid_count_kernel<<<N_PTS/256, 256>>>(xyz_i);
    grid_scan_kernel<<<1, 512>>>();
    grid_scatter_kernel<<<N_PTS/256, 256>>>(xyz_i);
    knn_grid_kernel<<<N_PTS/QPB, 256>>>(xyz_last);
    moments_kernel<<<64, 256>>>(xyz_i, xyz_last);

    // join: mma<1> needs both chains
    cudaStreamWaitEvent(0, evJoin, 0);

    // 4) pe GEMM (A generated) -> w1 = q - kf + pe, + BN1 stats
    mma_gemm<1><<<dim3(2, 2048), 256>>>(nullptr, p_bth + OP2, p_btl + OP2, bp2, p_w1, NK, 256, HDIM,
                                        xyz_i, xyz_last, t_i, t_last, wp1, bp1, gp, bp);

    // 5) w2 GEMM (BN1 finalize inlined) + BN2 stats
    mma_gemm<2><<<dim3(2, 2048), 256>>>(p_w1, p_bth + OW, p_btl + OW, bw, p_w2, NK, 256, CIN,
                                        nullptr, nullptr, nullptr, nullptr, nullptr, nullptr, gw1, bw1);

    // 6) softmax over K + weighted v-sum (BN2 finalize inlined)
    final_kernel<<<N_PTS, COUT>>>(out, gw2, bw2);
}

// round 15
// speedup vs baseline: 1.2852x; 1.0576x over previous
#include <cuda_runtime.h>
#include <cuda_bf16.h>
#include <cuda_fp16.h>
#include <cstdint>
#include <cfloat>

#define N_PTS 8192
#define KNN   16
#define CIN   256
#define COUT  256
#define NK    (N_PTS*KNN)       // 131072
#define HDIM  64
#define SLOPE 0.01f
#define EPS   1e-5f
#define QPB   8
#define ASTR  40                // A smem row stride in halves
#define BSTR  136               // B smem row stride in halves
#define ABYTES (64*ASTR*2)      // 5120: one A tile buffer
#define BBYTES (32*BSTR*2)      // 8704: one B tile buffer

// kNN grid params
#define GDIM  8
#define GCELLS (GDIM*GDIM*GDIM)   // 512
#define KRAD  0.25f
#define KRAD2 0.0625f

// bf16 weight-split offsets (natural [K,N] layout) — used by projections
#define OQ   0
#define OKV  65536              // 256*256
#define TOTW 196608             // + 256*512
// fp16 weight-split offsets — used by mma<1>/mma<2>
#define FP2  0                  // wp2 [64,256]
#define FW   16384              // ww  [256,256]
#define TOTF 81920

// ---------------- device scratch (static, allocation-free) ----------------
__device__ int      g_idx[NK];
__device__ float    g_q  [N_PTS*COUT];
__device__ float    g_kv [N_PTS*512];     // [kf | vf]
__device__ float    g_u  [N_PTS*COUT];    // kf + vf (for final)
__device__ float    g_bkv[512];
__device__ uint16_t g_bth[TOTW];          // proj weights bf16 hi, [K,N]
__device__ uint16_t g_btl[TOTW];          // proj weights bf16 lo, [K,N]
__device__ uint16_t g_fh[TOTF];           // wp2|ww fp16 hi, [K,N]
__device__ uint16_t g_fl[TOTF];           // wp2|ww fp16 lo, [K,N]
__device__ float    g_w1 [NK*COUT];
__device__ float    g_w2 [NK*COUT];
__device__ float    g_m[9];               // pe4 moments
__device__ float    g_s1[COUT], g_q1[COUT];
__device__ float    g_s2[COUT], g_q2[COUT];
// grid structures
__device__ int      g_cellCnt[GCELLS];
__device__ int      g_cellFill[GCELLS];
__device__ int      g_cellStart[GCELLS+1];
__device__ float4   g_spts[N_PTS];
__device__ int      g_sidx[N_PTS];

// ---------------- PTX helpers ----------------
__device__ __forceinline__ uint32_t su32(const void* p) {
    return (uint32_t)__cvta_generic_to_shared(p);
}
__device__ __forceinline__ void ldsm4(uint32_t r[4], uint32_t a) {
    asm volatile("ldmatrix.sync.aligned.m8n8.x4.shared.b16 {%0,%1,%2,%3}, [%4];"
        : "=r"(r[0]), "=r"(r[1]), "=r"(r[2]), "=r"(r[3]) : "r"(a));
}
__device__ __forceinline__ void ldsm4t(uint32_t r[4], uint32_t a) {
    asm volatile("ldmatrix.sync.aligned.m8n8.x4.trans.shared.b16 {%0,%1,%2,%3}, [%4];"
        : "=r"(r[0]), "=r"(r[1]), "=r"(r[2]), "=r"(r[3]) : "r"(a));
}
__device__ __forceinline__ void mma16816(float c[4], const uint32_t a[4], const uint32_t b[2]) {
    asm volatile("mma.sync.aligned.m16n8k16.row.col.f32.bf16.bf16.f32 "
        "{%0,%1,%2,%3}, {%4,%5,%6,%7}, {%8,%9}, {%0,%1,%2,%3};"
        : "+f"(c[0]), "+f"(c[1]), "+f"(c[2]), "+f"(c[3])
        : "r"(a[0]), "r"(a[1]), "r"(a[2]), "r"(a[3]), "r"(b[0]), "r"(b[1]));
}
__device__ __forceinline__ void mma16816h(float c[4], const uint32_t a[4], const uint32_t b[2]) {
    asm volatile("mma.sync.aligned.m16n8k16.row.col.f32.f16.f16.f32 "
        "{%0,%1,%2,%3}, {%4,%5,%6,%7}, {%8,%9}, {%0,%1,%2,%3};"
        : "+f"(c[0]), "+f"(c[1]), "+f"(c[2]), "+f"(c[3])
        : "r"(a[0]), "r"(a[1]), "r"(a[2]), "r"(a[3]), "r"(b[0]), "r"(b[1]));
}
__device__ __forceinline__ void split1(float x, uint16_t& hi, uint16_t& lo) {
    __nv_bfloat16 h = __float2bfloat16_rn(x);
    __nv_bfloat16 l = __float2bfloat16_rn(x - __bfloat162float(h));
    hi = *(uint16_t*)&h; lo = *(uint16_t*)&l;
}
// bf16 hi/lo pack of 8 floats
__device__ __forceinline__ void pack8(const float* v, uint4& H, uint4& L) {
    uint32_t* hp = (uint32_t*)&H;
    uint32_t* lp = (uint32_t*)&L;
#pragma unroll
    for (int i = 0; i < 4; i++) {
        float x0 = v[2*i], x1 = v[2*i+1];
        __nv_bfloat162 h2 = __floats2bfloat162_rn(x0, x1);
        float h0 = __low2float(h2), h1 = __high2float(h2);
        __nv_bfloat162 l2 = __floats2bfloat162_rn(x0 - h0, x1 - h1);
        hp[i] = *(uint32_t*)&h2;
        lp[i] = *(uint32_t*)&l2;
    }
}
// plain fp16 pack of 8 floats
__device__ __forceinline__ void pack8h(const float* v, uint4& H) {
    uint32_t* hp = (uint32_t*)&H;
#pragma unroll
    for (int i = 0; i < 4; i++) {
        __half2 h2 = __floats2half2_rn(v[2*i], v[2*i+1]);
        hp[i] = *(uint32_t*)&h2;
    }
}

// ---------------- prep: weight splits + bias concat + zero stats + grid zero ----
__global__ void prep_kernel(const float* __restrict__ wq,
                            const float* __restrict__ wk, const float* __restrict__ wv,
                            const float* __restrict__ wp2, const float* __restrict__ ww,
                            const float* __restrict__ bk, const float* __restrict__ bv) {
    int i = blockIdx.x * 256 + threadIdx.x;
    if (i < TOTW) {                          // bf16 split: wq, wkv (projections)
        float val;
        if (i < OKV) {                       // wq [256,256]
            val = wq[i];
        } else {                             // wkv [256,512]: row k = [wk_k | wv_k]
            int j = i - OKV, k = j >> 9, n = j & 511;
            val = (n < 256) ? wk[k*256 + n] : wv[k*256 + (n - 256)];
        }
        uint16_t h, l;
        split1(val, h, l);
        g_bth[i] = h; g_btl[i] = l;
    }
    if (i < TOTF) {                          // fp16 split: wp2, ww (w-path)
        float val = (i < FW) ? wp2[i] : ww[i - FW];
        __half h = __float2half_rn(val);
        __half l = __float2half_rn(val - __half2float(h));
        g_fh[i] = *(uint16_t*)&h;
        g_fl[i] = *(uint16_t*)&l;
    }
    if (i < 512) {
        g_bkv[i] = (i < 256) ? bk[i] : bv[i - 256];
        g_cellCnt[i] = 0;
    }
    if (i < 9) g_m[i] = 0.f;
    if (i < COUT) { g_s1[i] = 0.f; g_q1[i] = 0.f; g_s2[i] = 0.f; g_q2[i] = 0.f; }
}

// ---------------- u = kf + vf ----------------
__global__ void u_kernel() {
    int i = blockIdx.x * 256 + threadIdx.x;     // N_PTS*256
    int r = i >> 8, c = i & 255;
    g_u[i] = g_kv[(size_t)r*512 + c] + g_kv[(size_t)r*512 + 256 + c];
}

// ---------------- kNN: exact grid-accelerated, integrated fallback ----------------
__device__ __forceinline__ float norm3_ref(float x, float y, float z) {
    return __fadd_rn(__fadd_rn(__fmul_rn(x, x), __fmul_rn(y, y)), __fmul_rn(z, z));
}
__device__ __forceinline__ int gcell(float v) {
    int c = (int)(v * (float)GDIM);
    return c < 0 ? 0 : (c > GDIM-1 ? GDIM-1 : c);
}

__global__ void grid_count_kernel(const float* __restrict__ xyz_i) {
    int i = blockIdx.x * 256 + threadIdx.x;
    if (i >= N_PTS) return;
    int cx = gcell(xyz_i[i*3+0]);
    int cy = gcell(xyz_i[i*3+1]);
    int cz = gcell(xyz_i[i*3+2]);
    atomicAdd(&g_cellCnt[(cz*GDIM + cy)*GDIM + cx], 1);
}
__global__ void grid_scan_kernel() {
    __shared__ int s[GCELLS];
    int t = threadIdx.x;                  // 512
    int own = g_cellCnt[t];
    s[t] = own;
    __syncthreads();
    for (int off = 1; off < GCELLS; off <<= 1) {
        int u = 0;
        if (t >= off) u = s[t - off];
        __syncthreads();
        s[t] += u;
        __syncthreads();
    }
    g_cellStart[t] = s[t] - own;          // exclusive
    if (t == GCELLS-1) g_cellStart[GCELLS] = N_PTS;
    g_cellFill[t] = 0;
}
__global__ void grid_scatter_kernel(const float* __restrict__ xyz_i) {
    int i = blockIdx.x * 256 + threadIdx.x;
    if (i >= N_PTS) return;
    float x = xyz_i[i*3+0], y = xyz_i[i*3+1], z = xyz_i[i*3+2];
    int cell = (gcell(z)*GDIM + gcell(y))*GDIM + gcell(x);
    int pos = g_cellStart[cell] + atomicAdd(&g_cellFill[cell], 1);
    g_spts[pos] = make_float4(x, y, z, norm3_ref(x, y, z));
    g_sidx[pos] = i;
}

// warp per query: grid cells within KRAD; exact d2; lexicographic top-16;
// integrated exact fallback (full scan over sorted array) if radius insufficient.
__global__ void knn_grid_kernel(const float* __restrict__ xyz_last) {
    __shared__ float ld[QPB][KNN][32];
    __shared__ int   li[QPB][KNN][32];
    const int tid = threadIdx.x;
    const int w = tid >> 5, lane = tid & 31;
    const int q = blockIdx.x * QPB + w;
    const float qx = xyz_last[q*3+0];
    const float qy = xyz_last[q*3+1];
    const float qz = xyz_last[q*3+2];
    const float nq = norm3_ref(qx, qy, qz);
    const float cw = 1.f / (float)GDIM;

    float dist[KNN];
    int   idx [KNN];
#pragma unroll
    for (int j = 0; j < KNN; j++) { dist[j] = FLT_MAX; idx[j] = 0x7fffffff; }

    int zlo = (int)floorf((qz - KRAD) * (float)GDIM); if (zlo < 0) zlo = 0;
    int zhi = (int)floorf((qz + KRAD) * (float)GDIM); if (zhi > GDIM-1) zhi = GDIM-1;
    int ylo = (int)floorf((qy - KRAD) * (float)GDIM); if (ylo < 0) ylo = 0;
    int yhi = (int)floorf((qy + KRAD) * (float)GDIM); if (yhi > GDIM-1) yhi = GDIM-1;

    for (int z = zlo; z <= zhi; z++) {
        float dz = fmaxf(0.f, fmaxf((float)z * cw - qz, qz - (float)(z+1) * cw));
        float dz2 = dz * dz;
        for (int y = ylo; y <= yhi; y++) {
            float dy = fmaxf(0.f, fmaxf((float)y * cw - qy, qy - (float)(y+1) * cw));
            float dyz2 = dz2 + dy * dy;
            if (dyz2 > KRAD2) continue;
            float xr = sqrtf(KRAD2 - dyz2) + 1e-6f;
            int xlo = (int)floorf((qx - xr) * (float)GDIM); if (xlo < 0) xlo = 0;
            int xhi = (int)floorf((qx + xr) * (float)GDIM); if (xhi > GDIM-1) xhi = GDIM-1;
            int base = (z*GDIM + y)*GDIM;
            int s = g_cellStart[base + xlo];
            int e = g_cellStart[base + xhi + 1];
            for (int i = s + lane; i < e; i += 32) {
                float4 pv = g_spts[i];
                float t = __fmul_rn(qx, pv.x);
                t = __fmaf_rn(qy, pv.y, t);
                t = __fmaf_rn(qz, pv.z, t);
                float d2 = __fsub_rn(__fadd_rn(nq, pv.w), __fmul_rn(2.0f, t));
                int gi = g_sidx[i];
                bool ins = (d2 < dist[KNN-1]) || (d2 == dist[KNN-1] && gi < idx[KNN-1]);
                if (ins) {
                    dist[KNN-1] = d2;
                    idx[KNN-1]  = gi;
#pragma unroll
                    for (int j = KNN-1; j > 0; j--) {
                        float da = dist[j-1], db = dist[j];
                        int   ia = idx[j-1],  ib = idx[j];
                        bool sw = (db < da) || (db == da && ib < ia);
                        dist[j-1] = sw ? db : da;
                        dist[j]   = sw ? da : db;
                        idx[j-1]  = sw ? ib : ia;
                        idx[j]    = sw ? ia : ib;
                    }
                }
            }
        }
    }
#pragma unroll
    for (int j = 0; j < KNN; j++) { ld[w][j][lane] = dist[j]; li[w][j][lane] = idx[j]; }
    __syncwarp();

    int pos = 0;
    float last_v = FLT_MAX;
    for (int r = 0; r < KNN; r++) {
        float v = (pos < KNN) ? ld[w][pos][lane] : FLT_MAX;
        int  gi = (pos < KNN) ? li[w][pos][lane] : 0x7fffffff;
        int  owner = lane;
#pragma unroll
        for (int off = 16; off > 0; off >>= 1) {
            float v2  = __shfl_xor_sync(0xffffffffu, v, off);
            int   g2  = __shfl_xor_sync(0xffffffffu, gi, off);
            int   o2  = __shfl_xor_sync(0xffffffffu, owner, off);
            if (v2 < v || (v2 == v && g2 < gi)) { v = v2; gi = g2; owner = o2; }
        }
        if (lane == 0) g_idx[q*KNN + r] = gi;
        last_v = v;
        if (lane == owner) pos++;
    }
    // soundness: all non-enumerated points have d2 > KRAD2 (minus fp slack)
    if (!(last_v + 1e-4f < KRAD2)) {
        // exact fallback: full scan over sorted array (warp-local, rare)
#pragma unroll
        for (int j = 0; j < KNN; j++) { dist[j] = FLT_MAX; idx[j] = 0x7fffffff; }
        for (int i = lane; i < N_PTS; i += 32) {
            float4 pv = g_spts[i];
            float t = __fmul_rn(qx, pv.x);
            t = __fmaf_rn(qy, pv.y, t);
            t = __fmaf_rn(qz, pv.z, t);
            float d2 = __fsub_rn(__fadd_rn(nq, pv.w), __fmul_rn(2.0f, t));
            int gi = g_sidx[i];
            bool ins = (d2 < dist[KNN-1]) || (d2 == dist[KNN-1] && gi < idx[KNN-1]);
            if (ins) {
                dist[KNN-1] = d2;
                idx[KNN-1]  = gi;
#pragma unroll
                for (int j = KNN-1; j > 0; j--) {
                    float da = dist[j-1], db = dist[j];
                    int   ia = idx[j-1],  ib = idx[j];
                    bool sw = (db < da) || (db == da && ib < ia);
                    dist[j-1] = sw ? db : da;
                    dist[j]   = sw ? da : db;
                    idx[j-1]  = sw ? ib : ia;
                    idx[j]    = sw ? ia : ib;
                }
            }
        }
#pragma unroll
        for (int j = 0; j < KNN; j++) { ld[w][j][lane] = dist[j]; li[w][j][lane] = idx[j]; }
        __syncwarp();
        pos = 0;
        for (int r = 0; r < KNN; r++) {
            float v = (pos < KNN) ? ld[w][pos][lane] : FLT_MAX;
            int  gi = (pos < KNN) ? li[w][pos][lane] : 0x7fffffff;
            int  owner = lane;
#pragma unroll
            for (int off = 16; off > 0; off >>= 1) {
                float v2  = __shfl_xor_sync(0xffffffffu, v, off);
                int   g2  = __shfl_xor_sync(0xffffffffu, gi, off);
                int   o2  = __shfl_xor_sync(0xffffffffu, owner, off);
                if (v2 < v || (v2 == v && g2 < gi)) { v = v2; gi = g2; owner = o2; }
            }
            if (lane == 0) g_idx[q*KNN + r] = gi;
            if (lane == owner) pos++;
        }
    }
}

// ---------------- pe4 moments ----------------
__global__ void moments_kernel(const float* __restrict__ xyz_i,
                               const float* __restrict__ xyz_last) {
    float a0=0,a1=0,a2=0,a3=0,a4=0,a5=0,a6=0,a7=0,a8=0;
    for (int s = blockIdx.x * 256 + threadIdx.x; s < NK; s += gridDim.x * 256) {
        int n = s >> 4;
        int j = g_idx[s];
        float x = xyz_i[j*3+0] - xyz_last[n*3+0];
        float y = xyz_i[j*3+1] - xyz_last[n*3+1];
        float z = xyz_i[j*3+2] - xyz_last[n*3+2];
        a0 += x; a1 += y; a2 += z;
        a3 = fmaf(x,x,a3); a4 = fmaf(y,y,a4); a5 = fmaf(z,z,a5);
        a6 = fmaf(x,y,a6); a7 = fmaf(x,z,a7); a8 = fmaf(y,z,a8);
    }
    float v[9] = {a0,a1,a2,a3,a4,a5,a6,a7,a8};
#pragma unroll
    for (int i = 0; i < 9; i++) {
#pragma unroll
        for (int off = 16; off > 0; off >>= 1)
            v[i] += __shfl_xor_sync(0xffffffffu, v[i], off);
    }
    if ((threadIdx.x & 31) == 0) {
#pragma unroll
        for (int i = 0; i < 9; i++) atomicAdd(&g_m[i], v[i]);
    }
}

// ---------------- mma.sync GEMM: 64x128 tile, 256 thr, 2 CTAs/SM, double-buffered ----
// MODE 0: plain, bf16 3-product (projections — full precision, hidden in fork)
// MODE 1: A generated from xyz (pe), fp16 A + fp16-split B, 2-product;
//         C := w1 = q - kf[idx] + pe, BN1 stats
// MODE 2: A = lrelu(w1*bn1), fp16 A + fp16-split B, 2-product; C := w2, BN2 stats
template<int MODE>
__global__ __launch_bounds__(256, 2)
void mma_gemm(const float* __restrict__ A,
              const uint16_t* __restrict__ Bth, const uint16_t* __restrict__ Btl,
              const float* __restrict__ bias, float* __restrict__ C,
              int M, int N, int K,
              const float* __restrict__ xyz_i, const float* __restrict__ xyz_last,
              const float* __restrict__ t_i, const float* __restrict__ t_last,
              const float* __restrict__ wp1, const float* __restrict__ bp1,
              const float* __restrict__ gma, const float* __restrict__ bta) {
    constexpr bool USE16 = (MODE == 1 || MODE == 2);
    __shared__ __align__(16) uint16_t Ah[2*64*ASTR], Al[2*64*ASTR];
    __shared__ __align__(16) uint16_t Bh[2*32*BSTR], Bl[2*32*BSTR];
    __shared__ float spx[64], spy[64], spz[64];
    __shared__ float swp[256], sbp[64], sps[64], ssh[64];
    __shared__ float ssc[256], ssh2[256];
    __shared__ float sbias[128], sstatS[128], sstatQ[128];

    const int tid = threadIdx.x;
    const int lane = tid & 31, wid = tid >> 5;
    const int wm = wid >> 2, wn = wid & 3;          // 2x4 warp grid, 32x32 tiles
    const int m0 = blockIdx.y * 64, n0 = blockIdx.x * 128;

    float dtv = 0.f;
    if (MODE == 1) {
        if (tid < 64) {
            int m = m0 + tid;
            int n = m >> 4;
            int j = g_idx[m];
            spx[tid] = xyz_i[j*3+0] - xyz_last[n*3+0];
            spy[tid] = xyz_i[j*3+1] - xyz_last[n*3+1];
            spz[tid] = xyz_i[j*3+2] - xyz_last[n*3+2];
        }
        swp[tid] = wp1[tid];
        dtv = t_i[0] - t_last[0];
        if (tid < 64) {
            // inline finalize_pe: analytic BN over generated h
            float inv = 1.f / (float)NK;
            float mx = g_m[0]*inv, my = g_m[1]*inv, mz = g_m[2]*inv;
            float exx = g_m[3]*inv, eyy = g_m[4]*inv, ezz = g_m[5]*inv;
            float exy = g_m[6]*inv, exz = g_m[7]*inv, eyz = g_m[8]*inv;
            float w0 = wp1[tid], w1 = wp1[64+tid], w2 = wp1[128+tid], w3 = wp1[192+tid];
            float a  = bp1[tid] + w3*dtv;
            float lm = w0*mx + w1*my + w2*mz;
            float mean = a + lm;
            float e2 = a*a + 2.f*a*lm
                     + w0*w0*exx + w1*w1*eyy + w2*w2*ezz
                     + 2.f*(w0*w1*exy + w0*w2*exz + w1*w2*eyz);
            float var = e2 - mean*mean;
            float s = gma[tid] * rsqrtf(var + EPS);
            sps[tid] = s;
            ssh[tid] = bta[tid] - mean*s;
            sbp[tid] = bp1[tid];
        }
    }
    if (MODE == 2) {
        // inline finalize BN1
        float inv = 1.f / (float)NK;
        float m = g_s1[tid] * inv;
        float v = g_q1[tid] * inv - m*m;
        float s = gma[tid] * rsqrtf(v + EPS);
        ssc[tid]  = s;
        ssh2[tid] = bta[tid] - m*s;
    }
    if (tid < 128) { sbias[tid] = bias[n0 + tid]; sstatS[tid] = 0.f; sstatQ[tid] = 0.f; }
    if (MODE == 1 || MODE == 2) __syncthreads();

    float acc[2][4][4];
#pragma unroll
    for (int i = 0; i < 2; i++)
#pragma unroll
        for (int j = 0; j < 4; j++)
#pragma unroll
            for (int e = 0; e < 4; e++) acc[i][j][e] = 0.f;

    const int arow = tid >> 2, ac = (tid & 3) * 8;     // A: 64 rows x 32 k
    const int brow = tid >> 4, bc = (tid & 15) * 8;    // B: rows brow, brow+16 x 128 n

    float4 a0r, a1r;
    uint4 bhr[2], blr[2];
    const uint32_t AhB = su32(Ah), AlB = su32(Al), BhB = su32(Bh), BlB = su32(Bl);
    uint32_t a_off[2], b_off[2];
#pragma unroll
    for (int mt = 0; mt < 2; mt++)
        a_off[mt] = (uint32_t)(((wm*32 + mt*16 + (lane & 15))*ASTR + (lane >> 4)*8) * 2);
#pragma unroll
    for (int p = 0; p < 2; p++)
        b_off[p] = (uint32_t)(((lane & 15)*BSTR + wn*32 + p*16 + (lane >> 4)*8) * 2);

    const int nst = K >> 5;

    // ---- preamble: load stage 0 regs ----
    if (MODE != 1) {
        a0r = *(const float4*)(A + (size_t)(m0 + arow)*K + ac);
        a1r = *(const float4*)(A + (size_t)(m0 + arow)*K + ac + 4);
    }
    bhr[0] = *(const uint4*)(Bth + (size_t)brow*N + n0 + bc);
    blr[0] = *(const uint4*)(Btl + (size_t)brow*N + n0 + bc);
    bhr[1] = *(const uint4*)(Bth + (size_t)(brow+16)*N + n0 + bc);
    blr[1] = *(const uint4*)(Btl + (size_t)(brow+16)*N + n0 + bc);

    for (int kt = 0; kt < nst; kt++) {
        const int kb = kt * 32;
        const int sb = (kt & 1);             // store buffer for THIS stage
        // ---- store stage kt into buf sb ----
        {
            float v[8];
            if (MODE == 1) {
                float px = spx[arow], py = spy[arow], pz = spz[arow];
#pragma unroll
                for (int e = 0; e < 8; e++) {
                    int c = kb + ac + e;
                    float hh = sbp[c];
                    hh = fmaf(px,  swp[c],     hh);
                    hh = fmaf(py,  swp[64+c],  hh);
                    hh = fmaf(pz,  swp[128+c], hh);
                    hh = fmaf(dtv, swp[192+c], hh);
                    float x = fmaf(hh, sps[c], ssh[c]);
                    v[e] = (x >= 0.f) ? x : SLOPE*x;
                }
            } else {
                v[0]=a0r.x; v[1]=a0r.y; v[2]=a0r.z; v[3]=a0r.w;
                v[4]=a1r.x; v[5]=a1r.y; v[6]=a1r.z; v[7]=a1r.w;
                if (MODE == 2) {
                    int c = kb + ac;
#pragma unroll
                    for (int e = 0; e < 8; e++) {
                        float x = fmaf(v[e], ssc[c+e], ssh2[c+e]);
                        v[e] = (x >= 0.f) ? x : SLOPE*x;
                    }
                }
            }
            int aidx = sb*(64*ASTR) + arow*ASTR + ac;
            if (USE16) {
                uint4 H;
                pack8h(v, H);
                *(uint4*)&Ah[aidx] = H;
            } else {
                uint4 H, L;
                pack8(v, H, L);
                *(uint4*)&Ah[aidx] = H;
                *(uint4*)&Al[aidx] = L;
            }
            int bidx = sb*(32*BSTR) + brow*BSTR + bc;
            *(uint4*)&Bh[bidx] = bhr[0];
            *(uint4*)&Bl[bidx] = blr[0];
            *(uint4*)&Bh[bidx + 16*BSTR] = bhr[1];
            *(uint4*)&Bl[bidx + 16*BSTR] = blr[1];
        }
        // ---- prefetch regs for stage kt+1 ----
        if (kt + 1 < nst) {
            const int kn = kb + 32;
            if (MODE != 1) {
                a0r = *(const float4*)(A + (size_t)(m0 + arow)*K + kn + ac);
                a1r = *(const float4*)(A + (size_t)(m0 + arow)*K + kn + ac + 4);
            }
            bhr[0] = *(const uint4*)(Bth + (size_t)(kn + brow)*N + n0 + bc);
            blr[0] = *(const uint4*)(Btl + (size_t)(kn + brow)*N + n0 + bc);
            bhr[1] = *(const uint4*)(Bth + (size_t)(kn + brow + 16)*N + n0 + bc);
            blr[1] = *(const uint4*)(Btl + (size_t)(kn + brow + 16)*N + n0 + bc);
        }
        __syncthreads();      // buf sb now full for all threads

        // ---- compute stage kt from buf sb ----
        const uint32_t ab = (uint32_t)(sb * ABYTES);
        const uint32_t bb = (uint32_t)(sb * BBYTES);
#pragma unroll
        for (int ko = 0; ko < 2; ko++) {
            uint32_t ah[2][4];
#pragma unroll
            for (int mt = 0; mt < 2; mt++)
                ldsm4(ah[mt],  AhB + ab + a_off[mt] + ko*32);
            uint32_t bh[4][2], bl[4][2];
#pragma unroll
            for (int p = 0; p < 2; p++) {
                uint32_t r[4];
                ldsm4t(r, BhB + bb + b_off[p] + ko*16*BSTR*2);
                bh[2*p][0] = r[0]; bh[2*p][1] = r[1];
                bh[2*p+1][0] = r[2]; bh[2*p+1][1] = r[3];
                ldsm4t(r, BlB + bb + b_off[p] + ko*16*BSTR*2);
                bl[2*p][0] = r[0]; bl[2*p][1] = r[1];
                bl[2*p+1][0] = r[2]; bl[2*p+1][1] = r[3];
            }
            if (USE16) {
#pragma unroll
                for (int mt = 0; mt < 2; mt++)
#pragma unroll
                    for (int nt = 0; nt < 4; nt++) {
                        mma16816h(acc[mt][nt], ah[mt], bh[nt]);
                        mma16816h(acc[mt][nt], ah[mt], bl[nt]);
                    }
            } else {
                uint32_t al_[2][4];
#pragma unroll
                for (int mt = 0; mt < 2; mt++)
                    ldsm4(al_[mt], AlB + ab + a_off[mt] + ko*32);
#pragma unroll
                for (int mt = 0; mt < 2; mt++)
#pragma unroll
                    for (int nt = 0; nt < 4; nt++) {
                        mma16816(acc[mt][nt], ah[mt],  bh[nt]);
                        mma16816(acc[mt][nt], ah[mt],  bl[nt]);
                        mma16816(acc[mt][nt], al_[mt], bh[nt]);
                    }
            }
        }
    }

    // ---- epilogue ----
    float colS[8], colQ[8];
#pragma unroll
    for (int i = 0; i < 8; i++) { colS[i] = 0.f; colQ[i] = 0.f; }

#pragma unroll
    for (int mt = 0; mt < 2; mt++) {
        int r0 = m0 + wm*32 + mt*16 + (lane >> 2);
        int r1 = r0 + 8;
        int j0 = 0, j1 = 0, p0 = 0, p1 = 0;
        if (MODE == 1) {
            j0 = g_idx[r0]; j1 = g_idx[r1];
            p0 = r0 >> 4;   p1 = r1 >> 4;
        }
#pragma unroll
        for (int nt = 0; nt < 4; nt++) {
            int cl = wn*32 + nt*8 + (lane & 3)*2;      // local col in [0,128)
            int c = n0 + cl;
            float v00 = acc[mt][nt][0] + sbias[cl],   v01 = acc[mt][nt][1] + sbias[cl+1];
            float v10 = acc[mt][nt][2] + sbias[cl],   v11 = acc[mt][nt][3] + sbias[cl+1];
            if (MODE == 1) {
                float2 q0 = *(const float2*)(g_q  + (size_t)p0*256 + c);
                float2 q1 = *(const float2*)(g_q  + (size_t)p1*256 + c);
                float2 k0 = *(const float2*)(g_kv + (size_t)j0*512 + c);
                float2 k1 = *(const float2*)(g_kv + (size_t)j1*512 + c);
                v00 = q0.x - k0.x + v00; v01 = q0.y - k0.y + v01;
                v10 = q1.x - k1.x + v10; v11 = q1.y - k1.y + v11;
            }
            *(float2*)(C + (size_t)r0*N + c) = make_float2(v00, v01);
            *(float2*)(C + (size_t)r1*N + c) = make_float2(v10, v11);
            if (MODE != 0) {
                colS[nt*2+0] += v00 + v10;  colS[nt*2+1] += v01 + v11;
                colQ[nt*2+0] += v00*v00 + v10*v10;
                colQ[nt*2+1] += v01*v01 + v11*v11;
            }
        }
    }
    if (MODE != 0) {
#pragma unroll
        for (int i = 0; i < 8; i++) {
#pragma unroll
            for (int off = 4; off <= 16; off <<= 1) {
                colS[i] += __shfl_xor_sync(0xffffffffu, colS[i], off);
                colQ[i] += __shfl_xor_sync(0xffffffffu, colQ[i], off);
            }
        }
        if (lane < 4) {
#pragma unroll
            for (int nt = 0; nt < 4; nt++) {
#pragma unroll
                for (int j = 0; j < 2; j++) {
                    int cl = wn*32 + nt*8 + lane*2 + j;
                    atomicAdd(&sstatS[cl], colS[nt*2+j]);
                    atomicAdd(&sstatQ[cl], colQ[nt*2+j]);
                }
            }
        }
        __syncthreads();
        if (tid < 128) {
            float* gS = (MODE == 1) ? g_s1 : g_s2;
            float* gQ = (MODE == 1) ? g_q1 : g_q2;
            atomicAdd(&gS[n0 + tid], sstatS[tid]);
            atomicAdd(&gQ[n0 + tid], sstatQ[tid]);
        }
    }
}

// ---------------- final: inline BN2 finalize + lrelu + softmax(K) + v-sum ------
// v = vf[j] + pe = u[j] + (w1 - q),  u = kf + vf precomputed
__global__ void final_kernel(float* __restrict__ out,
                             const float* __restrict__ gw2, const float* __restrict__ bw2) {
    int n = blockIdx.x, c = threadIdx.x;
    __shared__ int sidx[KNN];
    if (c < KNN) sidx[c] = g_idx[n*KNN + c];
    __syncthreads();
    float inv = 1.f / (float)NK;
    float mm = g_s2[c] * inv;
    float vv = g_q2[c] * inv - mm*mm;
    float sc = gw2[c] * rsqrtf(vv + EPS);
    float sh = bw2[c] - mm*sc;
    float qv = g_q[(size_t)n*COUT + c];
    float z[KNN], w1v[KNN];
    float m = -FLT_MAX;
#pragma unroll
    for (int k = 0; k < KNN; k++) {
        float x = g_w2[((size_t)n*KNN + k)*COUT + c];
        w1v[k] = g_w1[((size_t)n*KNN + k)*COUT + c];
        x = x*sc + sh;
        x = (x >= 0.f) ? x : SLOPE*x;
        z[k] = x;
        m = fmaxf(m, x);
    }
    float den = 0.f, num = 0.f;
#pragma unroll
    for (int k = 0; k < KNN; k++) {
        float e = __expf(z[k] - m);
        float v = g_u[(size_t)sidx[k]*256 + c] + (w1v[k] - qv);
        den += e;
        num = fmaf(e, v, num);
    }
    out[(size_t)n*COUT + c] = num / den;
}

// ---------------- launch (stream fork/join: kNN chain ∥ projection chain) ------
extern "C" void kernel_launch(void* const* d_in, const int* in_sizes, int n_in,
                              void* d_out, int out_size) {
    const float* fea_i    = (const float*)d_in[0];
    const float* fea_last = (const float*)d_in[1];
    const float* xyz_i    = (const float*)d_in[2];
    const float* xyz_last = (const float*)d_in[3];
    const float* t_i      = (const float*)d_in[4];
    const float* t_last   = (const float*)d_in[5];
    const float* wp1 = (const float*)d_in[6];
    const float* bp1 = (const float*)d_in[7];
    const float* gp  = (const float*)d_in[8];
    const float* bp  = (const float*)d_in[9];
    const float* wp2 = (const float*)d_in[10];
    const float* bp2 = (const float*)d_in[11];
    const float* wq  = (const float*)d_in[12];
    const float* bq  = (const float*)d_in[13];
    const float* wk  = (const float*)d_in[14];
    const float* bk  = (const float*)d_in[15];
    const float* wv  = (const float*)d_in[16];
    const float* bv  = (const float*)d_in[17];
    const float* gw1 = (const float*)d_in[18];
    const float* bw1 = (const float*)d_in[19];
    const float* ww  = (const float*)d_in[20];
    const float* bw  = (const float*)d_in[21];
    const float* gw2 = (const float*)d_in[22];
    const float* bw2 = (const float*)d_in[23];
    float* out = (float*)d_out;

    void* p;
    cudaGetSymbolAddress(&p, g_q);   float* p_q   = (float*)p;
    cudaGetSymbolAddress(&p, g_kv);  float* p_kv  = (float*)p;
    cudaGetSymbolAddress(&p, g_bkv); float* p_bkv = (float*)p;
    cudaGetSymbolAddress(&p, g_bth); uint16_t* p_bth = (uint16_t*)p;
    cudaGetSymbolAddress(&p, g_btl); uint16_t* p_btl = (uint16_t*)p;
    cudaGetSymbolAddress(&p, g_fh);  uint16_t* p_fh  = (uint16_t*)p;
    cudaGetSymbolAddress(&p, g_fl);  uint16_t* p_fl  = (uint16_t*)p;
    cudaGetSymbolAddress(&p, g_w1);  float* p_w1  = (float*)p;
    cudaGetSymbolAddress(&p, g_w2);  float* p_w2  = (float*)p;

    static cudaStream_t s2 = nullptr;
    static cudaEvent_t evFork = nullptr, evJoin = nullptr;
    if (s2 == nullptr) {
        cudaStreamCreateWithFlags(&s2, cudaStreamNonBlocking);
        cudaEventCreateWithFlags(&evFork, cudaEventDisableTiming);
        cudaEventCreateWithFlags(&evJoin, cudaEventDisableTiming);
    }

    // 0) prep (weight splits + bias + stat zero + grid zero) on main stream
    prep_kernel<<<(TOTW + 255)/256, 256>>>(wq, wk, wv, wp2, ww, bk, bv);

    // fork: side stream s2 runs projections (depend only on prep)
    cudaEventRecord(evFork, 0);
    cudaStreamWaitEvent(s2, evFork, 0);
    mma_gemm<0><<<dim3(2, 128), 256, 0, s2>>>(fea_last, p_bth + OQ,  p_btl + OQ,  bq,    p_q,  N_PTS, 256, CIN,
                                              nullptr, nullptr, nullptr, nullptr, nullptr, nullptr, nullptr, nullptr);
    mma_gemm<0><<<dim3(4, 128), 256, 0, s2>>>(fea_i,    p_bth + OKV, p_btl + OKV, p_bkv, p_kv, N_PTS, 512, CIN,
                                              nullptr, nullptr, nullptr, nullptr, nullptr, nullptr, nullptr, nullptr);
    u_kernel<<<(N_PTS*256)/256, 256, 0, s2>>>();
    cudaEventRecord(evJoin, s2);

    // main stream: kNN chain + moments (independent of projections)
    grid_count_kernel<<<N_PTS/256, 256>>>(xyz_i);
    grid_scan_kernel<<<1, 512>>>();
    grid_scatter_kernel<<<N_PTS/256, 256>>>(xyz_i);
    knn_grid_kernel<<<N_PTS/QPB, 256>>>(xyz_last);
    moments_kernel<<<64, 256>>>(xyz_i, xyz_last);

    // join: mma<1> needs both chains
    cudaStreamWaitEvent(0, evJoin, 0);

    // 4) pe GEMM (A generated, fp16 2-product) -> w1 = q - kf + pe, + BN1 stats
    mma_gemm<1><<<dim3(2, 2048), 256>>>(nullptr, p_fh + FP2, p_fl + FP2, bp2, p_w1, NK, 256, HDIM,
                                        xyz_i, xyz_last, t_i, t_last, wp1, bp1, gp, bp);

    // 5) w2 GEMM (fp16 2-product, BN1 finalize inlined) + BN2 stats
    mma_gemm<2><<<dim3(2, 2048), 256>>>(p_w1, p_fh + FW, p_fl + FW, bw, p_w2, NK, 256, CIN,
                                        nullptr, nullptr, nullptr, nullptr, nullptr, nullptr, gw1, bw1);

    // 6) softmax over K + weighted v-sum (BN2 finalize inlined)
    final_kernel<<<N_PTS, COUT>>>(out, gw2, bw2);
}

// round 16
// speedup vs baseline: 1.3423x; 1.0444x over previous
#include <cuda_runtime.h>
#include <cuda_bf16.h>
#include <cuda_fp16.h>
#include <cstdint>
#include <cfloat>

#define N_PTS 8192
#define KNN   16
#define CIN   256
#define COUT  256
#define NK    (N_PTS*KNN)       // 131072
#define HDIM  64
#define SLOPE 0.01f
#define EPS   1e-5f
#define QPB   8
#define ASTR  40                // A smem row stride in halves
#define BSTR  136               // B smem row stride in halves
#define ABYTES (64*ASTR*2)      // 5120: one A tile buffer
#define BBYTES (32*BSTR*2)      // 8704: one B tile buffer

// kNN grid params
#define GDIM  8
#define GCELLS (GDIM*GDIM*GDIM)   // 512
#define KRAD  0.25f
#define KRAD2 0.0625f

// bf16 weight-split offsets (natural [K,N] layout) — used by projections
#define OQ   0
#define OKV  65536              // 256*256
#define TOTW 196608             // + 256*512
// fp16 weight-split offsets — used by mma<1>/mma<2>
#define FP2  0                  // wp2 [64,256]
#define FW   16384              // ww  [256,256]
#define TOTF 81920

// ---------------- device scratch (static, allocation-free) ----------------
__device__ int      g_idx[NK];
__device__ float    g_q  [N_PTS*COUT];
__device__ float    g_kv [N_PTS*512];     // [kf | vf]
__device__ float    g_u  [N_PTS*COUT];    // kf + vf (for final)
__device__ float    g_bkv[512];
__device__ uint16_t g_bth[TOTW];          // proj weights bf16 hi, [K,N]
__device__ uint16_t g_btl[TOTW];          // proj weights bf16 lo, [K,N]
__device__ uint16_t g_fh[TOTF];           // wp2|ww fp16 hi, [K,N]
__device__ uint16_t g_fl[TOTF];           // wp2|ww fp16 lo, [K,N]
__device__ __half   g_w1h[NK*COUT];       // w1 fp16 (64 MB)
__device__ __half   g_w2h[NK*COUT];       // w2 fp16 (64 MB)
__device__ float    g_m[9];               // pe4 moments
__device__ float    g_s1[COUT], g_q1[COUT];
__device__ float    g_s2[COUT], g_q2[COUT];
// grid structures
__device__ int      g_cellCnt[GCELLS];
__device__ int      g_cellFill[GCELLS];
__device__ int      g_cellStart[GCELLS+1];
__device__ float4   g_spts[N_PTS];
__device__ int      g_sidx[N_PTS];

// ---------------- PTX helpers ----------------
__device__ __forceinline__ uint32_t su32(const void* p) {
    return (uint32_t)__cvta_generic_to_shared(p);
}
__device__ __forceinline__ void ldsm4(uint32_t r[4], uint32_t a) {
    asm volatile("ldmatrix.sync.aligned.m8n8.x4.shared.b16 {%0,%1,%2,%3}, [%4];"
        : "=r"(r[0]), "=r"(r[1]), "=r"(r[2]), "=r"(r[3]) : "r"(a));
}
__device__ __forceinline__ void ldsm4t(uint32_t r[4], uint32_t a) {
    asm volatile("ldmatrix.sync.aligned.m8n8.x4.trans.shared.b16 {%0,%1,%2,%3}, [%4];"
        : "=r"(r[0]), "=r"(r[1]), "=r"(r[2]), "=r"(r[3]) : "r"(a));
}
__device__ __forceinline__ void mma16816(float c[4], const uint32_t a[4], const uint32_t b[2]) {
    asm volatile("mma.sync.aligned.m16n8k16.row.col.f32.bf16.bf16.f32 "
        "{%0,%1,%2,%3}, {%4,%5,%6,%7}, {%8,%9}, {%0,%1,%2,%3};"
        : "+f"(c[0]), "+f"(c[1]), "+f"(c[2]), "+f"(c[3])
        : "r"(a[0]), "r"(a[1]), "r"(a[2]), "r"(a[3]), "r"(b[0]), "r"(b[1]));
}
__device__ __forceinline__ void mma16816h(float c[4], const uint32_t a[4], const uint32_t b[2]) {
    asm volatile("mma.sync.aligned.m16n8k16.row.col.f32.f16.f16.f32 "
        "{%0,%1,%2,%3}, {%4,%5,%6,%7}, {%8,%9}, {%0,%1,%2,%3};"
        : "+f"(c[0]), "+f"(c[1]), "+f"(c[2]), "+f"(c[3])
        : "r"(a[0]), "r"(a[1]), "r"(a[2]), "r"(a[3]), "r"(b[0]), "r"(b[1]));
}
__device__ __forceinline__ void split1(float x, uint16_t& hi, uint16_t& lo) {
    __nv_bfloat16 h = __float2bfloat16_rn(x);
    __nv_bfloat16 l = __float2bfloat16_rn(x - __bfloat162float(h));
    hi = *(uint16_t*)&h; lo = *(uint16_t*)&l;
}
// bf16 hi/lo pack of 8 floats
__device__ __forceinline__ void pack8(const float* v, uint4& H, uint4& L) {
    uint32_t* hp = (uint32_t*)&H;
    uint32_t* lp = (uint32_t*)&L;
#pragma unroll
    for (int i = 0; i < 4; i++) {
        float x0 = v[2*i], x1 = v[2*i+1];
        __nv_bfloat162 h2 = __floats2bfloat162_rn(x0, x1);
        float h0 = __low2float(h2), h1 = __high2float(h2);
        __nv_bfloat162 l2 = __floats2bfloat162_rn(x0 - h0, x1 - h1);
        hp[i] = *(uint32_t*)&h2;
        lp[i] = *(uint32_t*)&l2;
    }
}
// plain fp16 pack of 8 floats
__device__ __forceinline__ void pack8h(const float* v, uint4& H) {
    uint32_t* hp = (uint32_t*)&H;
#pragma unroll
    for (int i = 0; i < 4; i++) {
        __half2 h2 = __floats2half2_rn(v[2*i], v[2*i+1]);
        hp[i] = *(uint32_t*)&h2;
    }
}

// ---------------- prep: weight splits + bias concat + zero stats + grid zero ----
__global__ void prep_kernel(const float* __restrict__ wq,
                            const float* __restrict__ wk, const float* __restrict__ wv,
                            const float* __restrict__ wp2, const float* __restrict__ ww,
                            const float* __restrict__ bk, const float* __restrict__ bv) {
    int i = blockIdx.x * 256 + threadIdx.x;
    if (i < TOTW) {                          // bf16 split: wq, wkv (projections)
        float val;
        if (i < OKV) {                       // wq [256,256]
            val = wq[i];
        } else {                             // wkv [256,512]: row k = [wk_k | wv_k]
            int j = i - OKV, k = j >> 9, n = j & 511;
            val = (n < 256) ? wk[k*256 + n] : wv[k*256 + (n - 256)];
        }
        uint16_t h, l;
        split1(val, h, l);
        g_bth[i] = h; g_btl[i] = l;
    }
    if (i < TOTF) {                          // fp16 split: wp2, ww (w-path)
        float val = (i < FW) ? wp2[i] : ww[i - FW];
        __half h = __float2half_rn(val);
        __half l = __float2half_rn(val - __half2float(h));
        g_fh[i] = *(uint16_t*)&h;
        g_fl[i] = *(uint16_t*)&l;
    }
    if (i < 512) {
        g_bkv[i] = (i < 256) ? bk[i] : bv[i - 256];
        g_cellCnt[i] = 0;
    }
    if (i < 9) g_m[i] = 0.f;
    if (i < COUT) { g_s1[i] = 0.f; g_q1[i] = 0.f; g_s2[i] = 0.f; g_q2[i] = 0.f; }
}

// ---------------- u = kf + vf ----------------
__global__ void u_kernel() {
    int i = blockIdx.x * 256 + threadIdx.x;     // N_PTS*256
    int r = i >> 8, c = i & 255;
    g_u[i] = g_kv[(size_t)r*512 + c] + g_kv[(size_t)r*512 + 256 + c];
}

// ---------------- kNN: exact grid-accelerated, integrated fallback ----------------
__device__ __forceinline__ float norm3_ref(float x, float y, float z) {
    return __fadd_rn(__fadd_rn(__fmul_rn(x, x), __fmul_rn(y, y)), __fmul_rn(z, z));
}
__device__ __forceinline__ int gcell(float v) {
    int c = (int)(v * (float)GDIM);
    return c < 0 ? 0 : (c > GDIM-1 ? GDIM-1 : c);
}

__global__ void grid_count_kernel(const float* __restrict__ xyz_i) {
    int i = blockIdx.x * 256 + threadIdx.x;
    if (i >= N_PTS) return;
    int cx = gcell(xyz_i[i*3+0]);
    int cy = gcell(xyz_i[i*3+1]);
    int cz = gcell(xyz_i[i*3+2]);
    atomicAdd(&g_cellCnt[(cz*GDIM + cy)*GDIM + cx], 1);
}
__global__ void grid_scan_kernel() {
    __shared__ int s[GCELLS];
    int t = threadIdx.x;                  // 512
    int own = g_cellCnt[t];
    s[t] = own;
    __syncthreads();
    for (int off = 1; off < GCELLS; off <<= 1) {
        int u = 0;
        if (t >= off) u = s[t - off];
        __syncthreads();
        s[t] += u;
        __syncthreads();
    }
    g_cellStart[t] = s[t] - own;          // exclusive
    if (t == GCELLS-1) g_cellStart[GCELLS] = N_PTS;
    g_cellFill[t] = 0;
}
__global__ void grid_scatter_kernel(const float* __restrict__ xyz_i) {
    int i = blockIdx.x * 256 + threadIdx.x;
    if (i >= N_PTS) return;
    float x = xyz_i[i*3+0], y = xyz_i[i*3+1], z = xyz_i[i*3+2];
    int cell = (gcell(z)*GDIM + gcell(y))*GDIM + gcell(x);
    int pos = g_cellStart[cell] + atomicAdd(&g_cellFill[cell], 1);
    g_spts[pos] = make_float4(x, y, z, norm3_ref(x, y, z));
    g_sidx[pos] = i;
}

// warp per query: grid cells within KRAD; exact d2; lexicographic top-16;
// integrated exact fallback (full scan over sorted array) if radius insufficient.
__global__ void knn_grid_kernel(const float* __restrict__ xyz_last) {
    __shared__ float ld[QPB][KNN][32];
    __shared__ int   li[QPB][KNN][32];
    const int tid = threadIdx.x;
    const int w = tid >> 5, lane = tid & 31;
    const int q = blockIdx.x * QPB + w;
    const float qx = xyz_last[q*3+0];
    const float qy = xyz_last[q*3+1];
    const float qz = xyz_last[q*3+2];
    const float nq = norm3_ref(qx, qy, qz);
    const float cw = 1.f / (float)GDIM;

    float dist[KNN];
    int   idx [KNN];
#pragma unroll
    for (int j = 0; j < KNN; j++) { dist[j] = FLT_MAX; idx[j] = 0x7fffffff; }

    int zlo = (int)floorf((qz - KRAD) * (float)GDIM); if (zlo < 0) zlo = 0;
    int zhi = (int)floorf((qz + KRAD) * (float)GDIM); if (zhi > GDIM-1) zhi = GDIM-1;
    int ylo = (int)floorf((qy - KRAD) * (float)GDIM); if (ylo < 0) ylo = 0;
    int yhi = (int)floorf((qy + KRAD) * (float)GDIM); if (yhi > GDIM-1) yhi = GDIM-1;

    for (int z = zlo; z <= zhi; z++) {
        float dz = fmaxf(0.f, fmaxf((float)z * cw - qz, qz - (float)(z+1) * cw));
        float dz2 = dz * dz;
        for (int y = ylo; y <= yhi; y++) {
            float dy = fmaxf(0.f, fmaxf((float)y * cw - qy, qy - (float)(y+1) * cw));
            float dyz2 = dz2 + dy * dy;
            if (dyz2 > KRAD2) continue;
            float xr = sqrtf(KRAD2 - dyz2) + 1e-6f;
            int xlo = (int)floorf((qx - xr) * (float)GDIM); if (xlo < 0) xlo = 0;
            int xhi = (int)floorf((qx + xr) * (float)GDIM); if (xhi > GDIM-1) xhi = GDIM-1;
            int base = (z*GDIM + y)*GDIM;
            int s = g_cellStart[base + xlo];
            int e = g_cellStart[base + xhi + 1];
            for (int i = s + lane; i < e; i += 32) {
                float4 pv = g_spts[i];
                float t = __fmul_rn(qx, pv.x);
                t = __fmaf_rn(qy, pv.y, t);
                t = __fmaf_rn(qz, pv.z, t);
                float d2 = __fsub_rn(__fadd_rn(nq, pv.w), __fmul_rn(2.0f, t));
                int gi = g_sidx[i];
                bool ins = (d2 < dist[KNN-1]) || (d2 == dist[KNN-1] && gi < idx[KNN-1]);
                if (ins) {
                    dist[KNN-1] = d2;
                    idx[KNN-1]  = gi;
#pragma unroll
                    for (int j = KNN-1; j > 0; j--) {
                        float da = dist[j-1], db = dist[j];
                        int   ia = idx[j-1],  ib = idx[j];
                        bool sw = (db < da) || (db == da && ib < ia);
                        dist[j-1] = sw ? db : da;
                        dist[j]   = sw ? da : db;
                        idx[j-1]  = sw ? ib : ia;
                        idx[j]    = sw ? ia : ib;
                    }
                }
            }
        }
    }
#pragma unroll
    for (int j = 0; j < KNN; j++) { ld[w][j][lane] = dist[j]; li[w][j][lane] = idx[j]; }
    __syncwarp();

    int pos = 0;
    float last_v = FLT_MAX;
    for (int r = 0; r < KNN; r++) {
        float v = (pos < KNN) ? ld[w][pos][lane] : FLT_MAX;
        int  gi = (pos < KNN) ? li[w][pos][lane] : 0x7fffffff;
        int  owner = lane;
#pragma unroll
        for (int off = 16; off > 0; off >>= 1) {
            float v2  = __shfl_xor_sync(0xffffffffu, v, off);
            int   g2  = __shfl_xor_sync(0xffffffffu, gi, off);
            int   o2  = __shfl_xor_sync(0xffffffffu, owner, off);
            if (v2 < v || (v2 == v && g2 < gi)) { v = v2; gi = g2; owner = o2; }
        }
        if (lane == 0) g_idx[q*KNN + r] = gi;
        last_v = v;
        if (lane == owner) pos++;
    }
    // soundness: all non-enumerated points have d2 > KRAD2 (minus fp slack)
    if (!(last_v + 1e-4f < KRAD2)) {
        // exact fallback: full scan over sorted array (warp-local, rare)
#pragma unroll
        for (int j = 0; j < KNN; j++) { dist[j] = FLT_MAX; idx[j] = 0x7fffffff; }
        for (int i = lane; i < N_PTS; i += 32) {
            float4 pv = g_spts[i];
            float t = __fmul_rn(qx, pv.x);
            t = __fmaf_rn(qy, pv.y, t);
            t = __fmaf_rn(qz, pv.z, t);
            float d2 = __fsub_rn(__fadd_rn(nq, pv.w), __fmul_rn(2.0f, t));
            int gi = g_sidx[i];
            bool ins = (d2 < dist[KNN-1]) || (d2 == dist[KNN-1] && gi < idx[KNN-1]);
            if (ins) {
                dist[KNN-1] = d2;
                idx[KNN-1]  = gi;
#pragma unroll
                for (int j = KNN-1; j > 0; j--) {
                    float da = dist[j-1], db = dist[j];
                    int   ia = idx[j-1],  ib = idx[j];
                    bool sw = (db < da) || (db == da && ib < ia);
                    dist[j-1] = sw ? db : da;
                    dist[j]   = sw ? da : db;
                    idx[j-1]  = sw ? ib : ia;
                    idx[j]    = sw ? ia : ib;
                }
            }
        }
#pragma unroll
        for (int j = 0; j < KNN; j++) { ld[w][j][lane] = dist[j]; li[w][j][lane] = idx[j]; }
        __syncwarp();
        pos = 0;
        for (int r = 0; r < KNN; r++) {
            float v = (pos < KNN) ? ld[w][pos][lane] : FLT_MAX;
            int  gi = (pos < KNN) ? li[w][pos][lane] : 0x7fffffff;
            int  owner = lane;
#pragma unroll
            for (int off = 16; off > 0; off >>= 1) {
                float v2  = __shfl_xor_sync(0xffffffffu, v, off);
                int   g2  = __shfl_xor_sync(0xffffffffu, gi, off);
                int   o2  = __shfl_xor_sync(0xffffffffu, owner, off);
                if (v2 < v || (v2 == v && g2 < gi)) { v = v2; gi = g2; owner = o2; }
            }
            if (lane == 0) g_idx[q*KNN + r] = gi;
            if (lane == owner) pos++;
        }
    }
}

// ---------------- pe4 moments ----------------
__global__ void moments_kernel(const float* __restrict__ xyz_i,
                               const float* __restrict__ xyz_last) {
    float a0=0,a1=0,a2=0,a3=0,a4=0,a5=0,a6=0,a7=0,a8=0;
    for (int s = blockIdx.x * 256 + threadIdx.x; s < NK; s += gridDim.x * 256) {
        int n = s >> 4;
        int j = g_idx[s];
        float x = xyz_i[j*3+0] - xyz_last[n*3+0];
        float y = xyz_i[j*3+1] - xyz_last[n*3+1];
        float z = xyz_i[j*3+2] - xyz_last[n*3+2];
        a0 += x; a1 += y; a2 += z;
        a3 = fmaf(x,x,a3); a4 = fmaf(y,y,a4); a5 = fmaf(z,z,a5);
        a6 = fmaf(x,y,a6); a7 = fmaf(x,z,a7); a8 = fmaf(y,z,a8);
    }
    float v[9] = {a0,a1,a2,a3,a4,a5,a6,a7,a8};
#pragma unroll
    for (int i = 0; i < 9; i++) {
#pragma unroll
        for (int off = 16; off > 0; off >>= 1)
            v[i] += __shfl_xor_sync(0xffffffffu, v[i], off);
    }
    if ((threadIdx.x & 31) == 0) {
#pragma unroll
        for (int i = 0; i < 9; i++) atomicAdd(&g_m[i], v[i]);
    }
}

// ---------------- mma.sync GEMM: 64x128 tile, 256 thr, 2 CTAs/SM, double-buffered ----
// MODE 0: plain bf16 3-product (projections), A fp32, C fp32
// MODE 1: A generated from xyz (pe), fp16 2-product; C := w1 fp16 = q - kf[idx] + pe,
//         BN1 stats (fp32)
// MODE 2: A = lrelu(w1h*bn1) from fp16 w1, fp16 2-product; C := w2 fp16, BN2 stats
template<int MODE>
__global__ __launch_bounds__(256, 2)
void mma_gemm(const float* __restrict__ A,
              const uint16_t* __restrict__ Bth, const uint16_t* __restrict__ Btl,
              const float* __restrict__ bias, float* __restrict__ Cv,
              int M, int N, int K,
              const float* __restrict__ xyz_i, const float* __restrict__ xyz_last,
              const float* __restrict__ t_i, const float* __restrict__ t_last,
              const float* __restrict__ wp1, const float* __restrict__ bp1,
              const float* __restrict__ gma, const float* __restrict__ bta) {
    constexpr bool USE16 = (MODE == 1 || MODE == 2);
    __shared__ __align__(16) uint16_t Ah[2*64*ASTR], Al[2*64*ASTR];
    __shared__ __align__(16) uint16_t Bh[2*32*BSTR], Bl[2*32*BSTR];
    __shared__ float spx[64], spy[64], spz[64];
    __shared__ float swp[256], sbp[64], sps[64], ssh[64];
    __shared__ float ssc[256], ssh2[256];
    __shared__ float sbias[128], sstatS[128], sstatQ[128];

    const int tid = threadIdx.x;
    const int lane = tid & 31, wid = tid >> 5;
    const int wm = wid >> 2, wn = wid & 3;          // 2x4 warp grid, 32x32 tiles
    const int m0 = blockIdx.y * 64, n0 = blockIdx.x * 128;

    float* Cf = Cv;
    __half* Ch = (__half*)Cv;
    const __half* A16 = (const __half*)A;

    float dtv = 0.f;
    if (MODE == 1) {
        if (tid < 64) {
            int m = m0 + tid;
            int n = m >> 4;
            int j = g_idx[m];
            spx[tid] = xyz_i[j*3+0] - xyz_last[n*3+0];
            spy[tid] = xyz_i[j*3+1] - xyz_last[n*3+1];
            spz[tid] = xyz_i[j*3+2] - xyz_last[n*3+2];
        }
        swp[tid] = wp1[tid];
        dtv = t_i[0] - t_last[0];
        if (tid < 64) {
            // inline finalize_pe: analytic BN over generated h
            float inv = 1.f / (float)NK;
            float mx = g_m[0]*inv, my = g_m[1]*inv, mz = g_m[2]*inv;
            float exx = g_m[3]*inv, eyy = g_m[4]*inv, ezz = g_m[5]*inv;
            float exy = g_m[6]*inv, exz = g_m[7]*inv, eyz = g_m[8]*inv;
            float w0 = wp1[tid], w1 = wp1[64+tid], w2 = wp1[128+tid], w3 = wp1[192+tid];
            float a  = bp1[tid] + w3*dtv;
            float lm = w0*mx + w1*my + w2*mz;
            float mean = a + lm;
            float e2 = a*a + 2.f*a*lm
                     + w0*w0*exx + w1*w1*eyy + w2*w2*ezz
                     + 2.f*(w0*w1*exy + w0*w2*exz + w1*w2*eyz);
            float var = e2 - mean*mean;
            float s = gma[tid] * rsqrtf(var + EPS);
            sps[tid] = s;
            ssh[tid] = bta[tid] - mean*s;
            sbp[tid] = bp1[tid];
        }
    }
    if (MODE == 2) {
        // inline finalize BN1
        float inv = 1.f / (float)NK;
        float m = g_s1[tid] * inv;
        float v = g_q1[tid] * inv - m*m;
        float s = gma[tid] * rsqrtf(v + EPS);
        ssc[tid]  = s;
        ssh2[tid] = bta[tid] - m*s;
    }
    if (tid < 128) { sbias[tid] = bias[n0 + tid]; sstatS[tid] = 0.f; sstatQ[tid] = 0.f; }
    if (MODE == 1 || MODE == 2) __syncthreads();

    float acc[2][4][4];
#pragma unroll
    for (int i = 0; i < 2; i++)
#pragma unroll
        for (int j = 0; j < 4; j++)
#pragma unroll
            for (int e = 0; e < 4; e++) acc[i][j][e] = 0.f;

    const int arow = tid >> 2, ac = (tid & 3) * 8;     // A: 64 rows x 32 k
    const int brow = tid >> 4, bc = (tid & 15) * 8;    // B: rows brow, brow+16 x 128 n

    float4 a0r, a1r;      // MODE 0 A prefetch (fp32)
    uint4  ahr;           // MODE 2 A prefetch (8 halves)
    uint4 bhr[2], blr[2];
    const uint32_t AhB = su32(Ah), AlB = su32(Al), BhB = su32(Bh), BlB = su32(Bl);
    uint32_t a_off[2], b_off[2];
#pragma unroll
    for (int mt = 0; mt < 2; mt++)
        a_off[mt] = (uint32_t)(((wm*32 + mt*16 + (lane & 15))*ASTR + (lane >> 4)*8) * 2);
#pragma unroll
    for (int p = 0; p < 2; p++)
        b_off[p] = (uint32_t)(((lane & 15)*BSTR + wn*32 + p*16 + (lane >> 4)*8) * 2);

    const int nst = K >> 5;

    // ---- preamble: load stage 0 regs ----
    if (MODE == 0) {
        a0r = *(const float4*)(A + (size_t)(m0 + arow)*K + ac);
        a1r = *(const float4*)(A + (size_t)(m0 + arow)*K + ac + 4);
    } else if (MODE == 2) {
        ahr = *(const uint4*)(A16 + (size_t)(m0 + arow)*K + ac);
    }
    bhr[0] = *(const uint4*)(Bth + (size_t)brow*N + n0 + bc);
    blr[0] = *(const uint4*)(Btl + (size_t)brow*N + n0 + bc);
    bhr[1] = *(const uint4*)(Bth + (size_t)(brow+16)*N + n0 + bc);
    blr[1] = *(const uint4*)(Btl + (size_t)(brow+16)*N + n0 + bc);

    for (int kt = 0; kt < nst; kt++) {
        const int kb = kt * 32;
        const int sb = (kt & 1);             // store buffer for THIS stage
        // ---- store stage kt into buf sb ----
        {
            float v[8];
            if (MODE == 1) {
                float px = spx[arow], py = spy[arow], pz = spz[arow];
#pragma unroll
                for (int e = 0; e < 8; e++) {
                    int c = kb + ac + e;
                    float hh = sbp[c];
                    hh = fmaf(px,  swp[c],     hh);
                    hh = fmaf(py,  swp[64+c],  hh);
                    hh = fmaf(pz,  swp[128+c], hh);
                    hh = fmaf(dtv, swp[192+c], hh);
                    float x = fmaf(hh, sps[c], ssh[c]);
                    v[e] = (x >= 0.f) ? x : SLOPE*x;
                }
            } else if (MODE == 2) {
                const __half2* hp = (const __half2*)&ahr;
                int c = kb + ac;
#pragma unroll
                for (int i = 0; i < 4; i++) {
                    float2 f = __half22float2(hp[i]);
                    float x0 = fmaf(f.x, ssc[c+2*i],   ssh2[c+2*i]);
                    float x1 = fmaf(f.y, ssc[c+2*i+1], ssh2[c+2*i+1]);
                    v[2*i]   = (x0 >= 0.f) ? x0 : SLOPE*x0;
                    v[2*i+1] = (x1 >= 0.f) ? x1 : SLOPE*x1;
                }
            } else {
                v[0]=a0r.x; v[1]=a0r.y; v[2]=a0r.z; v[3]=a0r.w;
                v[4]=a1r.x; v[5]=a1r.y; v[6]=a1r.z; v[7]=a1r.w;
            }
            int aidx = sb*(64*ASTR) + arow*ASTR + ac;
            if (USE16) {
                uint4 H;
                pack8h(v, H);
                *(uint4*)&Ah[aidx] = H;
            } else {
                uint4 H, L;
                pack8(v, H, L);
                *(uint4*)&Ah[aidx] = H;
                *(uint4*)&Al[aidx] = L;
            }
            int bidx = sb*(32*BSTR) + brow*BSTR + bc;
            *(uint4*)&Bh[bidx] = bhr[0];
            *(uint4*)&Bl[bidx] = blr[0];
            *(uint4*)&Bh[bidx + 16*BSTR] = bhr[1];
            *(uint4*)&Bl[bidx + 16*BSTR] = blr[1];
        }
        // ---- prefetch regs for stage kt+1 ----
        if (kt + 1 < nst) {
            const int kn = kb + 32;
            if (MODE == 0) {
                a0r = *(const float4*)(A + (size_t)(m0 + arow)*K + kn + ac);
                a1r = *(const float4*)(A + (size_t)(m0 + arow)*K + kn + ac + 4);
            } else if (MODE == 2) {
                ahr = *(const uint4*)(A16 + (size_t)(m0 + arow)*K + kn + ac);
            }
            bhr[0] = *(const uint4*)(Bth + (size_t)(kn + brow)*N + n0 + bc);
            blr[0] = *(const uint4*)(Btl + (size_t)(kn + brow)*N + n0 + bc);
            bhr[1] = *(const uint4*)(Bth + (size_t)(kn + brow + 16)*N + n0 + bc);
            blr[1] = *(const uint4*)(Btl + (size_t)(kn + brow + 16)*N + n0 + bc);
        }
        __syncthreads();      // buf sb now full for all threads

        // ---- compute stage kt from buf sb ----
        const uint32_t ab = (uint32_t)(sb * ABYTES);
        const uint32_t bb = (uint32_t)(sb * BBYTES);
#pragma unroll
        for (int ko = 0; ko < 2; ko++) {
            uint32_t ah[2][4];
#pragma unroll
            for (int mt = 0; mt < 2; mt++)
                ldsm4(ah[mt],  AhB + ab + a_off[mt] + ko*32);
            uint32_t bh[4][2], bl[4][2];
#pragma unroll
            for (int p = 0; p < 2; p++) {
                uint32_t r[4];
                ldsm4t(r, BhB + bb + b_off[p] + ko*16*BSTR*2);
                bh[2*p][0] = r[0]; bh[2*p][1] = r[1];
                bh[2*p+1][0] = r[2]; bh[2*p+1][1] = r[3];
                ldsm4t(r, BlB + bb + b_off[p] + ko*16*BSTR*2);
                bl[2*p][0] = r[0]; bl[2*p][1] = r[1];
                bl[2*p+1][0] = r[2]; bl[2*p+1][1] = r[3];
            }
            if (USE16) {
#pragma unroll
                for (int mt = 0; mt < 2; mt++)
#pragma unroll
                    for (int nt = 0; nt < 4; nt++) {
                        mma16816h(acc[mt][nt], ah[mt], bh[nt]);
                        mma16816h(acc[mt][nt], ah[mt], bl[nt]);
                    }
            } else {
                uint32_t al_[2][4];
#pragma unroll
                for (int mt = 0; mt < 2; mt++)
                    ldsm4(al_[mt], AlB + ab + a_off[mt] + ko*32);
#pragma unroll
                for (int mt = 0; mt < 2; mt++)
#pragma unroll
                    for (int nt = 0; nt < 4; nt++) {
                        mma16816(acc[mt][nt], ah[mt],  bh[nt]);
                        mma16816(acc[mt][nt], ah[mt],  bl[nt]);
                        mma16816(acc[mt][nt], al_[mt], bh[nt]);
                    }
            }
        }
    }

    // ---- epilogue ----
    float colS[8], colQ[8];
#pragma unroll
    for (int i = 0; i < 8; i++) { colS[i] = 0.f; colQ[i] = 0.f; }

#pragma unroll
    for (int mt = 0; mt < 2; mt++) {
        int r0 = m0 + wm*32 + mt*16 + (lane >> 2);
        int r1 = r0 + 8;
        int j0 = 0, j1 = 0, p0 = 0, p1 = 0;
        if (MODE == 1) {
            j0 = g_idx[r0]; j1 = g_idx[r1];
            p0 = r0 >> 4;   p1 = r1 >> 4;
        }
#pragma unroll
        for (int nt = 0; nt < 4; nt++) {
            int cl = wn*32 + nt*8 + (lane & 3)*2;      // local col in [0,128)
            int c = n0 + cl;
            float v00 = acc[mt][nt][0] + sbias[cl],   v01 = acc[mt][nt][1] + sbias[cl+1];
            float v10 = acc[mt][nt][2] + sbias[cl],   v11 = acc[mt][nt][3] + sbias[cl+1];
            if (MODE == 1) {
                float2 q0 = *(const float2*)(g_q  + (size_t)p0*256 + c);
                float2 q1 = *(const float2*)(g_q  + (size_t)p1*256 + c);
                float2 k0 = *(const float2*)(g_kv + (size_t)j0*512 + c);
                float2 k1 = *(const float2*)(g_kv + (size_t)j1*512 + c);
                v00 = q0.x - k0.x + v00; v01 = q0.y - k0.y + v01;
                v10 = q1.x - k1.x + v10; v11 = q1.y - k1.y + v11;
            }
            if (MODE == 0) {
                *(float2*)(Cf + (size_t)r0*N + c) = make_float2(v00, v01);
                *(float2*)(Cf + (size_t)r1*N + c) = make_float2(v10, v11);
            } else {
                *(__half2*)(Ch + (size_t)r0*N + c) = __floats2half2_rn(v00, v01);
                *(__half2*)(Ch + (size_t)r1*N + c) = __floats2half2_rn(v10, v11);
            }
            if (MODE != 0) {
                colS[nt*2+0] += v00 + v10;  colS[nt*2+1] += v01 + v11;
                colQ[nt*2+0] += v00*v00 + v10*v10;
                colQ[nt*2+1] += v01*v01 + v11*v11;
            }
        }
    }
    if (MODE != 0) {
#pragma unroll
        for (int i = 0; i < 8; i++) {
#pragma unroll
            for (int off = 4; off <= 16; off <<= 1) {
                colS[i] += __shfl_xor_sync(0xffffffffu, colS[i], off);
                colQ[i] += __shfl_xor_sync(0xffffffffu, colQ[i], off);
            }
        }
        if (lane < 4) {
#pragma unroll
            for (int nt = 0; nt < 4; nt++) {
#pragma unroll
                for (int j = 0; j < 2; j++) {
                    int cl = wn*32 + nt*8 + lane*2 + j;
                    atomicAdd(&sstatS[cl], colS[nt*2+j]);
                    atomicAdd(&sstatQ[cl], colQ[nt*2+j]);
                }
            }
        }
        __syncthreads();
        if (tid < 128) {
            float* gS = (MODE == 1) ? g_s1 : g_s2;
            float* gQ = (MODE == 1) ? g_q1 : g_q2;
            atomicAdd(&gS[n0 + tid], sstatS[tid]);
            atomicAdd(&gQ[n0 + tid], sstatQ[tid]);
        }
    }
}

// ---------------- final: inline BN2 finalize + lrelu + softmax(K) + v-sum ------
// v = vf[j] + pe = u[j] + (w1 - q),  u = kf + vf precomputed; w1/w2 fp16
__global__ void final_kernel(float* __restrict__ out,
                             const float* __restrict__ gw2, const float* __restrict__ bw2) {
    int n = blockIdx.x, c = threadIdx.x;
    __shared__ int sidx[KNN];
    if (c < KNN) sidx[c] = g_idx[n*KNN + c];
    __syncthreads();
    float inv = 1.f / (float)NK;
    float mm = g_s2[c] * inv;
    float vv = g_q2[c] * inv - mm*mm;
    float sc = gw2[c] * rsqrtf(vv + EPS);
    float sh = bw2[c] - mm*sc;
    float qv = g_q[(size_t)n*COUT + c];
    float z[KNN], w1v[KNN];
    float m = -FLT_MAX;
#pragma unroll
    for (int k = 0; k < KNN; k++) {
        float x = __half2float(g_w2h[((size_t)n*KNN + k)*COUT + c]);
        w1v[k] = __half2float(g_w1h[((size_t)n*KNN + k)*COUT + c]);
        x = x*sc + sh;
        x = (x >= 0.f) ? x : SLOPE*x;
        z[k] = x;
        m = fmaxf(m, x);
    }
    float den = 0.f, num = 0.f;
#pragma unroll
    for (int k = 0; k < KNN; k++) {
        float e = __expf(z[k] - m);
        float v = g_u[(size_t)sidx[k]*256 + c] + (w1v[k] - qv);
        den += e;
        num = fmaf(e, v, num);
    }
    out[(size_t)n*COUT + c] = num / den;
}

// ---------------- launch (stream fork/join: kNN chain ∥ projection chain) ------
extern "C" void kernel_launch(void* const* d_in, const int* in_sizes, int n_in,
                              void* d_out, int out_size) {
    const float* fea_i    = (const float*)d_in[0];
    const float* fea_last = (const float*)d_in[1];
    const float* xyz_i    = (const float*)d_in[2];
    const float* xyz_last = (const float*)d_in[3];
    const float* t_i      = (const float*)d_in[4];
    const float* t_last   = (const float*)d_in[5];
    const float* wp1 = (const float*)d_in[6];
    const float* bp1 = (const float*)d_in[7];
    const float* gp  = (const float*)d_in[8];
    const float* bp  = (const float*)d_in[9];
    const float* wp2 = (const float*)d_in[10];
    const float* bp2 = (const float*)d_in[11];
    const float* wq  = (const float*)d_in[12];
    const float* bq  = (const float*)d_in[13];
    const float* wk  = (const float*)d_in[14];
    const float* bk  = (const float*)d_in[15];
    const float* wv  = (const float*)d_in[16];
    const float* bv  = (const float*)d_in[17];
    const float* gw1 = (const float*)d_in[18];
    const float* bw1 = (const float*)d_in[19];
    const float* ww  = (const float*)d_in[20];
    const float* bw  = (const float*)d_in[21];
    const float* gw2 = (const float*)d_in[22];
    const float* bw2 = (const float*)d_in[23];
    float* out = (float*)d_out;

    void* p;
    cudaGetSymbolAddress(&p, g_q);   float* p_q   = (float*)p;
    cudaGetSymbolAddress(&p, g_kv);  float* p_kv  = (float*)p;
    cudaGetSymbolAddress(&p, g_bkv); float* p_bkv = (float*)p;
    cudaGetSymbolAddress(&p, g_bth); uint16_t* p_bth = (uint16_t*)p;
    cudaGetSymbolAddress(&p, g_btl); uint16_t* p_btl = (uint16_t*)p;
    cudaGetSymbolAddress(&p, g_fh);  uint16_t* p_fh  = (uint16_t*)p;
    cudaGetSymbolAddress(&p, g_fl);  uint16_t* p_fl  = (uint16_t*)p;
    cudaGetSymbolAddress(&p, g_w1h); float* p_w1h = (float*)p;   // fp16 buffer (cast)
    cudaGetSymbolAddress(&p, g_w2h); float* p_w2h = (float*)p;   // fp16 buffer (cast)

    static cudaStream_t s2 = nullptr;
    static cudaEvent_t evFork = nullptr, evJoin = nullptr;
    if (s2 == nullptr) {
        cudaStreamCreateWithFlags(&s2, cudaStreamNonBlocking);
        cudaEventCreateWithFlags(&evFork, cudaEventDisableTiming);
        cudaEventCreateWithFlags(&evJoin, cudaEventDisableTiming);
    }

    // 0) prep (weight splits + bias + stat zero + grid zero) on main stream
    prep_kernel<<<(TOTW + 255)/256, 256>>>(wq, wk, wv, wp2, ww, bk, bv);

    // fork: side stream s2 runs projections (depend only on prep)
    cudaEventRecord(evFork, 0);
    cudaStreamWaitEvent(s2, evFork, 0);
    mma_gemm<0><<<dim3(2, 128), 256, 0, s2>>>(fea_last, p_bth + OQ,  p_btl + OQ,  bq,    p_q,  N_PTS, 256, CIN,
                                              nullptr, nullptr, nullptr, nullptr, nullptr, nullptr, nullptr, nullptr);
    mma_gemm<0><<<dim3(4, 128), 256, 0, s2>>>(fea_i,    p_bth + OKV, p_btl + OKV, p_bkv, p_kv, N_PTS, 512, CIN,
                                              nullptr, nullptr, nullptr, nullptr, nullptr, nullptr, nullptr, nullptr);
    u_kernel<<<(N_PTS*256)/256, 256, 0, s2>>>();
    cudaEventRecord(evJoin, s2);

    // main stream: kNN chain + moments (independent of projections)
    grid_count_kernel<<<N_PTS/256, 256>>>(xyz_i);
    grid_scan_kernel<<<1, 512>>>();
    grid_scatter_kernel<<<N_PTS/256, 256>>>(xyz_i);
    knn_grid_kernel<<<N_PTS/QPB, 256>>>(xyz_last);
    moments_kernel<<<64, 256>>>(xyz_i, xyz_last);

    // join: mma<1> needs both chains
    cudaStreamWaitEvent(0, evJoin, 0);

    // 4) pe GEMM (A generated, fp16 2-product) -> w1h = q - kf + pe, + BN1 stats
    mma_gemm<1><<<dim3(2, 2048), 256>>>(nullptr, p_fh + FP2, p_fl + FP2, bp2, p_w1h, NK, 256, HDIM,
                                        xyz_i, xyz_last, t_i, t_last, wp1, bp1, gp, bp);

    // 5) w2 GEMM (fp16 A from w1h, BN1 finalize inlined) + BN2 stats
    mma_gemm<2><<<dim3(2, 2048), 256>>>(p_w1h, p_fh + FW, p_fl + FW, bw, p_w2h, NK, 256, CIN,
                                        nullptr, nullptr, nullptr, nullptr, nullptr, nullptr, gw1, bw1);

    // 6) softmax over K + weighted v-sum (BN2 finalize inlined)
    final_kernel<<<N_PTS, COUT>>>(out, gw2, bw2);
}

// round 17
// speedup vs baseline: 1.5450x; 1.1510x over previous
#include <cuda_runtime.h>
#include <cuda_bf16.h>
#include <cuda_fp16.h>
#include <cstdint>
#include <cfloat>

#define N_PTS 8192
#define KNN   16
#define CIN   256
#define COUT  256
#define NK    (N_PTS*KNN)       // 131072
#define HDIM  64
#define SLOPE 0.01f
#define EPS   1e-5f
#define QPB   8
#define ASTR  40                // A smem row stride in halves
#define BSTR  136               // B smem row stride in halves
#define ABYTES (64*ASTR*2)      // 5120: one A tile buffer
#define BBYTES (32*BSTR*2)      // 8704: one B tile buffer

// kNN grid params
#define GDIM  8
#define GCELLS (GDIM*GDIM*GDIM)   // 512
#define KRAD  0.1875f
#define KRAD2 0.03515625f

// bf16 weight-split offsets (natural [K,N] layout) — used by projections
#define OQ   0
#define OKV  65536              // 256*256
#define TOTW 196608             // + 256*512
// fp16 weight-split offsets — used by mma<1>/mma<2>
#define FP2  0                  // wp2 [64,256]
#define FW   16384              // ww  [256,256]
#define TOTF 81920

// ---------------- device scratch (static, allocation-free) ----------------
__device__ int      g_idx[NK];
__device__ float    g_q  [N_PTS*COUT];
__device__ float    g_kv [N_PTS*512];     // [kf | vf]
__device__ float    g_u  [N_PTS*COUT];    // kf + vf (for final)
__device__ float    g_bkv[512];
__device__ uint16_t g_bth[TOTW];          // proj weights bf16 hi, [K,N]
__device__ uint16_t g_btl[TOTW];          // proj weights bf16 lo, [K,N]
__device__ uint16_t g_fh[TOTF];           // wp2|ww fp16 hi, [K,N]
__device__ uint16_t g_fl[TOTF];           // wp2|ww fp16 lo, [K,N]
__device__ __half   g_w1h[NK*COUT];       // w1 fp16 (64 MB)
__device__ __half   g_w2h[NK*COUT];       // w2 fp16 (64 MB)
__device__ float    g_m[9];               // pe4 moments
__device__ float    g_s1[COUT], g_q1[COUT];
__device__ float    g_s2[COUT], g_q2[COUT];
// grid structures
__device__ int      g_cellCnt[GCELLS];
__device__ int      g_cellFill[GCELLS];
__device__ int      g_cellStart[GCELLS+1];
__device__ float4   g_spts[N_PTS];
__device__ int      g_sidx[N_PTS];

// ---------------- PTX helpers ----------------
__device__ __forceinline__ uint32_t su32(const void* p) {
    return (uint32_t)__cvta_generic_to_shared(p);
}
__device__ __forceinline__ void ldsm4(uint32_t r[4], uint32_t a) {
    asm volatile("ldmatrix.sync.aligned.m8n8.x4.shared.b16 {%0,%1,%2,%3}, [%4];"
        : "=r"(r[0]), "=r"(r[1]), "=r"(r[2]), "=r"(r[3]) : "r"(a));
}
__device__ __forceinline__ void ldsm4t(uint32_t r[4], uint32_t a) {
    asm volatile("ldmatrix.sync.aligned.m8n8.x4.trans.shared.b16 {%0,%1,%2,%3}, [%4];"
        : "=r"(r[0]), "=r"(r[1]), "=r"(r[2]), "=r"(r[3]) : "r"(a));
}
__device__ __forceinline__ void mma16816(float c[4], const uint32_t a[4], const uint32_t b[2]) {
    asm volatile("mma.sync.aligned.m16n8k16.row.col.f32.bf16.bf16.f32 "
        "{%0,%1,%2,%3}, {%4,%5,%6,%7}, {%8,%9}, {%0,%1,%2,%3};"
        : "+f"(c[0]), "+f"(c[1]), "+f"(c[2]), "+f"(c[3])
        : "r"(a[0]), "r"(a[1]), "r"(a[2]), "r"(a[3]), "r"(b[0]), "r"(b[1]));
}
__device__ __forceinline__ void mma16816h(float c[4], const uint32_t a[4], const uint32_t b[2]) {
    asm volatile("mma.sync.aligned.m16n8k16.row.col.f32.f16.f16.f32 "
        "{%0,%1,%2,%3}, {%4,%5,%6,%7}, {%8,%9}, {%0,%1,%2,%3};"
        : "+f"(c[0]), "+f"(c[1]), "+f"(c[2]), "+f"(c[3])
        : "r"(a[0]), "r"(a[1]), "r"(a[2]), "r"(a[3]), "r"(b[0]), "r"(b[1]));
}
__device__ __forceinline__ void split1(float x, uint16_t& hi, uint16_t& lo) {
    __nv_bfloat16 h = __float2bfloat16_rn(x);
    __nv_bfloat16 l = __float2bfloat16_rn(x - __bfloat162float(h));
    hi = *(uint16_t*)&h; lo = *(uint16_t*)&l;
}
// bf16 hi/lo pack of 8 floats
__device__ __forceinline__ void pack8(const float* v, uint4& H, uint4& L) {
    uint32_t* hp = (uint32_t*)&H;
    uint32_t* lp = (uint32_t*)&L;
#pragma unroll
    for (int i = 0; i < 4; i++) {
        float x0 = v[2*i], x1 = v[2*i+1];
        __nv_bfloat162 h2 = __floats2bfloat162_rn(x0, x1);
        float h0 = __low2float(h2), h1 = __high2float(h2);
        __nv_bfloat162 l2 = __floats2bfloat162_rn(x0 - h0, x1 - h1);
        hp[i] = *(uint32_t*)&h2;
        lp[i] = *(uint32_t*)&l2;
    }
}
// plain fp16 pack of 8 floats
__device__ __forceinline__ void pack8h(const float* v, uint4& H) {
    uint32_t* hp = (uint32_t*)&H;
#pragma unroll
    for (int i = 0; i < 4; i++) {
        __half2 h2 = __floats2half2_rn(v[2*i], v[2*i+1]);
        hp[i] = *(uint32_t*)&h2;
    }
}

// ---------------- prep: weight splits + bias concat + zero stats + grid zero ----
__global__ void prep_kernel(const float* __restrict__ wq,
                            const float* __restrict__ wk, const float* __restrict__ wv,
                            const float* __restrict__ wp2, const float* __restrict__ ww,
                            const float* __restrict__ bk, const float* __restrict__ bv) {
    int i = blockIdx.x * 256 + threadIdx.x;
    if (i < TOTW) {                          // bf16 split: wq, wkv (projections)
        float val;
        if (i < OKV) {                       // wq [256,256]
            val = wq[i];
        } else {                             // wkv [256,512]: row k = [wk_k | wv_k]
            int j = i - OKV, k = j >> 9, n = j & 511;
            val = (n < 256) ? wk[k*256 + n] : wv[k*256 + (n - 256)];
        }
        uint16_t h, l;
        split1(val, h, l);
        g_bth[i] = h; g_btl[i] = l;
    }
    if (i < TOTF) {                          // fp16 split: wp2, ww (w-path)
        float val = (i < FW) ? wp2[i] : ww[i - FW];
        __half h = __float2half_rn(val);
        __half l = __float2half_rn(val - __half2float(h));
        g_fh[i] = *(uint16_t*)&h;
        g_fl[i] = *(uint16_t*)&l;
    }
    if (i < 512) {
        g_bkv[i] = (i < 256) ? bk[i] : bv[i - 256];
        g_cellCnt[i] = 0;
    }
    if (i < 9) g_m[i] = 0.f;
    if (i < COUT) { g_s1[i] = 0.f; g_q1[i] = 0.f; g_s2[i] = 0.f; g_q2[i] = 0.f; }
}

// ---------------- u = kf + vf ----------------
__global__ void u_kernel() {
    int i = blockIdx.x * 256 + threadIdx.x;     // N_PTS*256
    int r = i >> 8, c = i & 255;
    g_u[i] = g_kv[(size_t)r*512 + c] + g_kv[(size_t)r*512 + 256 + c];
}

// ---------------- kNN: exact grid-accelerated, integrated fallback ----------------
__device__ __forceinline__ float norm3_ref(float x, float y, float z) {
    return __fadd_rn(__fadd_rn(__fmul_rn(x, x), __fmul_rn(y, y)), __fmul_rn(z, z));
}
__device__ __forceinline__ int gcell(float v) {
    int c = (int)(v * (float)GDIM);
    return c < 0 ? 0 : (c > GDIM-1 ? GDIM-1 : c);
}

__global__ void grid_count_kernel(const float* __restrict__ xyz_i) {
    int i = blockIdx.x * 256 + threadIdx.x;
    if (i >= N_PTS) return;
    int cx = gcell(xyz_i[i*3+0]);
    int cy = gcell(xyz_i[i*3+1]);
    int cz = gcell(xyz_i[i*3+2]);
    atomicAdd(&g_cellCnt[(cz*GDIM + cy)*GDIM + cx], 1);
}
__global__ void grid_scan_kernel() {
    __shared__ int s[GCELLS];
    int t = threadIdx.x;                  // 512
    int own = g_cellCnt[t];
    s[t] = own;
    __syncthreads();
    for (int off = 1; off < GCELLS; off <<= 1) {
        int u = 0;
        if (t >= off) u = s[t - off];
        __syncthreads();
        s[t] += u;
        __syncthreads();
    }
    g_cellStart[t] = s[t] - own;          // exclusive
    if (t == GCELLS-1) g_cellStart[GCELLS] = N_PTS;
    g_cellFill[t] = 0;
}
__global__ void grid_scatter_kernel(const float* __restrict__ xyz_i) {
    int i = blockIdx.x * 256 + threadIdx.x;
    if (i >= N_PTS) return;
    float x = xyz_i[i*3+0], y = xyz_i[i*3+1], z = xyz_i[i*3+2];
    int cell = (gcell(z)*GDIM + gcell(y))*GDIM + gcell(x);
    int pos = g_cellStart[cell] + atomicAdd(&g_cellFill[cell], 1);
    g_spts[pos] = make_float4(x, y, z, norm3_ref(x, y, z));
    g_sidx[pos] = i;
}

// warp per query: grid cells within KRAD; exact d2; lexicographic top-16;
// integrated exact fallback (full scan over sorted array) if radius insufficient.
__global__ void knn_grid_kernel(const float* __restrict__ xyz_last) {
    __shared__ float ld[QPB][KNN][32];
    __shared__ int   li[QPB][KNN][32];
    const int tid = threadIdx.x;
    const int w = tid >> 5, lane = tid & 31;
    const int q = blockIdx.x * QPB + w;
    const float qx = xyz_last[q*3+0];
    const float qy = xyz_last[q*3+1];
    const float qz = xyz_last[q*3+2];
    const float nq = norm3_ref(qx, qy, qz);
    const float cw = 1.f / (float)GDIM;

    float dist[KNN];
    int   idx [KNN];
#pragma unroll
    for (int j = 0; j < KNN; j++) { dist[j] = FLT_MAX; idx[j] = 0x7fffffff; }

    int zlo = (int)floorf((qz - KRAD) * (float)GDIM); if (zlo < 0) zlo = 0;
    int zhi = (int)floorf((qz + KRAD) * (float)GDIM); if (zhi > GDIM-1) zhi = GDIM-1;
    int ylo = (int)floorf((qy - KRAD) * (float)GDIM); if (ylo < 0) ylo = 0;
    int yhi = (int)floorf((qy + KRAD) * (float)GDIM); if (yhi > GDIM-1) yhi = GDIM-1;

    for (int z = zlo; z <= zhi; z++) {
        float dz = fmaxf(0.f, fmaxf((float)z * cw - qz, qz - (float)(z+1) * cw));
        float dz2 = dz * dz;
        for (int y = ylo; y <= yhi; y++) {
            float dy = fmaxf(0.f, fmaxf((float)y * cw - qy, qy - (float)(y+1) * cw));
            float dyz2 = dz2 + dy * dy;
            if (dyz2 > KRAD2) continue;
            float xr = sqrtf(KRAD2 - dyz2) + 1e-6f;
            int xlo = (int)floorf((qx - xr) * (float)GDIM); if (xlo < 0) xlo = 0;
            int xhi = (int)floorf((qx + xr) * (float)GDIM); if (xhi > GDIM-1) xhi = GDIM-1;
            int base = (z*GDIM + y)*GDIM;
            int s = g_cellStart[base + xlo];
            int e = g_cellStart[base + xhi + 1];
            for (int i = s + lane; i < e; i += 32) {
                float4 pv = g_spts[i];
                float t = __fmul_rn(qx, pv.x);
                t = __fmaf_rn(qy, pv.y, t);
                t = __fmaf_rn(qz, pv.z, t);
                float d2 = __fsub_rn(__fadd_rn(nq, pv.w), __fmul_rn(2.0f, t));
                int gi = g_sidx[i];
                bool ins = (d2 < dist[KNN-1]) || (d2 == dist[KNN-1] && gi < idx[KNN-1]);
                if (ins) {
                    dist[KNN-1] = d2;
                    idx[KNN-1]  = gi;
#pragma unroll
                    for (int j = KNN-1; j > 0; j--) {
                        float da = dist[j-1], db = dist[j];
                        int   ia = idx[j-1],  ib = idx[j];
                        bool sw = (db < da) || (db == da && ib < ia);
                        dist[j-1] = sw ? db : da;
                        dist[j]   = sw ? da : db;
                        idx[j-1]  = sw ? ib : ia;
                        idx[j]    = sw ? ia : ib;
                    }
                }
            }
        }
    }
#pragma unroll
    for (int j = 0; j < KNN; j++) { ld[w][j][lane] = dist[j]; li[w][j][lane] = idx[j]; }
    __syncwarp();

    int pos = 0;
    float last_v = FLT_MAX;
    for (int r = 0; r < KNN; r++) {
        float v = (pos < KNN) ? ld[w][pos][lane] : FLT_MAX;
        int  gi = (pos < KNN) ? li[w][pos][lane] : 0x7fffffff;
        int  owner = lane;
#pragma unroll
        for (int off = 16; off > 0; off >>= 1) {
            float v2  = __shfl_xor_sync(0xffffffffu, v, off);
            int   g2  = __shfl_xor_sync(0xffffffffu, gi, off);
            int   o2  = __shfl_xor_sync(0xffffffffu, owner, off);
            if (v2 < v || (v2 == v && g2 < gi)) { v = v2; gi = g2; owner = o2; }
        }
        if (lane == 0) g_idx[q*KNN + r] = gi;
        last_v = v;
        if (lane == owner) pos++;
    }
    // soundness: all non-enumerated points have d2 > KRAD2 (minus fp slack)
    if (!(last_v + 1e-4f < KRAD2)) {
        // exact fallback: full scan over sorted array (warp-local, rare)
#pragma unroll
        for (int j = 0; j < KNN; j++) { dist[j] = FLT_MAX; idx[j] = 0x7fffffff; }
        for (int i = lane; i < N_PTS; i += 32) {
            float4 pv = g_spts[i];
            float t = __fmul_rn(qx, pv.x);
            t = __fmaf_rn(qy, pv.y, t);
            t = __fmaf_rn(qz, pv.z, t);
            float d2 = __fsub_rn(__fadd_rn(nq, pv.w), __fmul_rn(2.0f, t));
            int gi = g_sidx[i];
            bool ins = (d2 < dist[KNN-1]) || (d2 == dist[KNN-1] && gi < idx[KNN-1]);
            if (ins) {
                dist[KNN-1] = d2;
                idx[KNN-1]  = gi;
#pragma unroll
                for (int j = KNN-1; j > 0; j--) {
                    float da = dist[j-1], db = dist[j];
                    int   ia = idx[j-1],  ib = idx[j];
                    bool sw = (db < da) || (db == da && ib < ia);
                    dist[j-1] = sw ? db : da;
                    dist[j]   = sw ? da : db;
                    idx[j-1]  = sw ? ib : ia;
                    idx[j]    = sw ? ia : ib;
                }
            }
        }
#pragma unroll
        for (int j = 0; j < KNN; j++) { ld[w][j][lane] = dist[j]; li[w][j][lane] = idx[j]; }
        __syncwarp();
        pos = 0;
        for (int r = 0; r < KNN; r++) {
            float v = (pos < KNN) ? ld[w][pos][lane] : FLT_MAX;
            int  gi = (pos < KNN) ? li[w][pos][lane] : 0x7fffffff;
            int  owner = lane;
#pragma unroll
            for (int off = 16; off > 0; off >>= 1) {
                float v2  = __shfl_xor_sync(0xffffffffu, v, off);
                int   g2  = __shfl_xor_sync(0xffffffffu, gi, off);
                int   o2  = __shfl_xor_sync(0xffffffffu, owner, off);
                if (v2 < v || (v2 == v && g2 < gi)) { v = v2; gi = g2; owner = o2; }
            }
            if (lane == 0) g_idx[q*KNN + r] = gi;
            if (lane == owner) pos++;
        }
    }
}

// ---------------- pe4 moments ----------------
__global__ void moments_kernel(const float* __restrict__ xyz_i,
                               const float* __restrict__ xyz_last) {
    float a0=0,a1=0,a2=0,a3=0,a4=0,a5=0,a6=0,a7=0,a8=0;
    for (int s = blockIdx.x * 256 + threadIdx.x; s < NK; s += gridDim.x * 256) {
        int n = s >> 4;
        int j = g_idx[s];
        float x = xyz_i[j*3+0] - xyz_last[n*3+0];
        float y = xyz_i[j*3+1] - xyz_last[n*3+1];
        float z = xyz_i[j*3+2] - xyz_last[n*3+2];
        a0 += x; a1 += y; a2 += z;
        a3 = fmaf(x,x,a3); a4 = fmaf(y,y,a4); a5 = fmaf(z,z,a5);
        a6 = fmaf(x,y,a6); a7 = fmaf(x,z,a7); a8 = fmaf(y,z,a8);
    }
    float v[9] = {a0,a1,a2,a3,a4,a5,a6,a7,a8};
#pragma unroll
    for (int i = 0; i < 9; i++) {
#pragma unroll
        for (int off = 16; off > 0; off >>= 1)
            v[i] += __shfl_xor_sync(0xffffffffu, v[i], off);
    }
    if ((threadIdx.x & 31) == 0) {
#pragma unroll
        for (int i = 0; i < 9; i++) atomicAdd(&g_m[i], v[i]);
    }
}

// ---------------- mma.sync GEMM: 64x128 tile, 256 thr, 2 CTAs/SM, double-buffered ----
// MODE 0: plain bf16 3-product (projections), A fp32, C fp32
// MODE 1: A generated from xyz (pe), fp16 2-product; C := w1 fp16 = q - kf[idx] + pe,
//         BN1 stats (fp32)
// MODE 2: A = lrelu(w1h*bn1) from fp16 w1, fp16 2-product; C := w2 fp16, BN2 stats
template<int MODE>
__global__ __launch_bounds__(256, 2)
void mma_gemm(const float* __restrict__ A,
              const uint16_t* __restrict__ Bth, const uint16_t* __restrict__ Btl,
              const float* __restrict__ bias, float* __restrict__ Cv,
              int M, int N, int K,
              const float* __restrict__ xyz_i, const float* __restrict__ xyz_last,
              const float* __restrict__ t_i, const float* __restrict__ t_last,
              const float* __restrict__ wp1, const float* __restrict__ bp1,
              const float* __restrict__ gma, const float* __restrict__ bta) {
    constexpr bool USE16 = (MODE == 1 || MODE == 2);
    __shared__ __align__(16) uint16_t Ah[2*64*ASTR], Al[2*64*ASTR];
    __shared__ __align__(16) uint16_t Bh[2*32*BSTR], Bl[2*32*BSTR];
    __shared__ float spx[64], spy[64], spz[64];
    __shared__ float swp[256], sbp[64], sps[64], ssh[64];
    __shared__ float ssc[256], ssh2[256];
    __shared__ float sbias[128], sstatS[128], sstatQ[128];

    const int tid = threadIdx.x;
    const int lane = tid & 31, wid = tid >> 5;
    const int wm = wid >> 2, wn = wid & 3;          // 2x4 warp grid, 32x32 tiles
    const int m0 = blockIdx.y * 64, n0 = blockIdx.x * 128;

    float* Cf = Cv;
    __half* Ch = (__half*)Cv;
    const __half* A16 = (const __half*)A;

    float dtv = 0.f;
    if (MODE == 1) {
        if (tid < 64) {
            int m = m0 + tid;
            int n = m >> 4;
            int j = g_idx[m];
            spx[tid] = xyz_i[j*3+0] - xyz_last[n*3+0];
            spy[tid] = xyz_i[j*3+1] - xyz_last[n*3+1];
            spz[tid] = xyz_i[j*3+2] - xyz_last[n*3+2];
        }
        swp[tid] = wp1[tid];
        dtv = t_i[0] - t_last[0];
        if (tid < 64) {
            // inline finalize_pe: analytic BN over generated h
            float inv = 1.f / (float)NK;
            float mx = g_m[0]*inv, my = g_m[1]*inv, mz = g_m[2]*inv;
            float exx = g_m[3]*inv, eyy = g_m[4]*inv, ezz = g_m[5]*inv;
            float exy = g_m[6]*inv, exz = g_m[7]*inv, eyz = g_m[8]*inv;
            float w0 = wp1[tid], w1 = wp1[64+tid], w2 = wp1[128+tid], w3 = wp1[192+tid];
            float a  = bp1[tid] + w3*dtv;
            float lm = w0*mx + w1*my + w2*mz;
            float mean = a + lm;
            float e2 = a*a + 2.f*a*lm
                     + w0*w0*exx + w1*w1*eyy + w2*w2*ezz
                     + 2.f*(w0*w1*exy + w0*w2*exz + w1*w2*eyz);
            float var = e2 - mean*mean;
            float s = gma[tid] * rsqrtf(var + EPS);
            sps[tid] = s;
            ssh[tid] = bta[tid] - mean*s;
            sbp[tid] = bp1[tid];
        }
    }
    if (MODE == 2) {
        // inline finalize BN1
        float inv = 1.f / (float)NK;
        float m = g_s1[tid] * inv;
        float v = g_q1[tid] * inv - m*m;
        float s = gma[tid] * rsqrtf(v + EPS);
        ssc[tid]  = s;
        ssh2[tid] = bta[tid] - m*s;
    }
    if (tid < 128) { sbias[tid] = bias[n0 + tid]; sstatS[tid] = 0.f; sstatQ[tid] = 0.f; }
    if (MODE == 1 || MODE == 2) __syncthreads();

    float acc[2][4][4];
#pragma unroll
    for (int i = 0; i < 2; i++)
#pragma unroll
        for (int j = 0; j < 4; j++)
#pragma unroll
            for (int e = 0; e < 4; e++) acc[i][j][e] = 0.f;

    const int arow = tid >> 2, ac = (tid & 3) * 8;     // A: 64 rows x 32 k
    const int brow = tid >> 4, bc = (tid & 15) * 8;    // B: rows brow, brow+16 x 128 n

    float4 a0r, a1r;      // MODE 0 A prefetch (fp32)
    uint4  ahr;           // MODE 2 A prefetch (8 halves)
    uint4 bhr[2], blr[2];
    const uint32_t AhB = su32(Ah), AlB = su32(Al), BhB = su32(Bh), BlB = su32(Bl);
    uint32_t a_off[2], b_off[2];
#pragma unroll
    for (int mt = 0; mt < 2; mt++)
        a_off[mt] = (uint32_t)(((wm*32 + mt*16 + (lane & 15))*ASTR + (lane >> 4)*8) * 2);
#pragma unroll
    for (int p = 0; p < 2; p++)
        b_off[p] = (uint32_t)(((lane & 15)*BSTR + wn*32 + p*16 + (lane >> 4)*8) * 2);

    const int nst = K >> 5;

    // ---- preamble: load stage 0 regs ----
    if (MODE == 0) {
        a0r = *(const float4*)(A + (size_t)(m0 + arow)*K + ac);
        a1r = *(const float4*)(A + (size_t)(m0 + arow)*K + ac + 4);
    } else if (MODE == 2) {
        ahr = *(const uint4*)(A16 + (size_t)(m0 + arow)*K + ac);
    }
    bhr[0] = *(const uint4*)(Bth + (size_t)brow*N + n0 + bc);
    blr[0] = *(const uint4*)(Btl + (size_t)brow*N + n0 + bc);
    bhr[1] = *(const uint4*)(Bth + (size_t)(brow+16)*N + n0 + bc);
    blr[1] = *(const uint4*)(Btl + (size_t)(brow+16)*N + n0 + bc);

    for (int kt = 0; kt < nst; kt++) {
        const int kb = kt * 32;
        const int sb = (kt & 1);             // store buffer for THIS stage
        // ---- store stage kt into buf sb ----
        {
            float v[8];
            if (MODE == 1) {
                float px = spx[arow], py = spy[arow], pz = spz[arow];
#pragma unroll
                for (int e = 0; e < 8; e++) {
                    int c = kb + ac + e;
                    float hh = sbp[c];
                    hh = fmaf(px,  swp[c],     hh);
                    hh = fmaf(py,  swp[64+c],  hh);
                    hh = fmaf(pz,  swp[128+c], hh);
                    hh = fmaf(dtv, swp[192+c], hh);
                    float x = fmaf(hh, sps[c], ssh[c]);
                    v[e] = (x >= 0.f) ? x : SLOPE*x;
                }
            } else if (MODE == 2) {
                const __half2* hp = (const __half2*)&ahr;
                int c = kb + ac;
#pragma unroll
                for (int i = 0; i < 4; i++) {
                    float2 f = __half22float2(hp[i]);
                    float x0 = fmaf(f.x, ssc[c+2*i],   ssh2[c+2*i]);
                    float x1 = fmaf(f.y, ssc[c+2*i+1], ssh2[c+2*i+1]);
                    v[2*i]   = (x0 >= 0.f) ? x0 : SLOPE*x0;
                    v[2*i+1] = (x1 >= 0.f) ? x1 : SLOPE*x1;
                }
            } else {
                v[0]=a0r.x; v[1]=a0r.y; v[2]=a0r.z; v[3]=a0r.w;
                v[4]=a1r.x; v[5]=a1r.y; v[6]=a1r.z; v[7]=a1r.w;
            }
            int aidx = sb*(64*ASTR) + arow*ASTR + ac;
            if (USE16) {
                uint4 H;
                pack8h(v, H);
                *(uint4*)&Ah[aidx] = H;
            } else {
                uint4 H, L;
                pack8(v, H, L);
                *(uint4*)&Ah[aidx] = H;
                *(uint4*)&Al[aidx] = L;
            }
            int bidx = sb*(32*BSTR) + brow*BSTR + bc;
            *(uint4*)&Bh[bidx] = bhr[0];
            *(uint4*)&Bl[bidx] = blr[0];
            *(uint4*)&Bh[bidx + 16*BSTR] = bhr[1];
            *(uint4*)&Bl[bidx + 16*BSTR] = blr[1];
        }
        // ---- prefetch regs for stage kt+1 ----
        if (kt + 1 < nst) {
            const int kn = kb + 32;
            if (MODE == 0) {
                a0r = *(const float4*)(A + (size_t)(m0 + arow)*K + kn + ac);
                a1r = *(const float4*)(A + (size_t)(m0 + arow)*K + kn + ac + 4);
            } else if (MODE == 2) {
                ahr = *(const uint4*)(A16 + (size_t)(m0 + arow)*K + kn + ac);
            }
            bhr[0] = *(const uint4*)(Bth + (size_t)(kn + brow)*N + n0 + bc);
            blr[0] = *(const uint4*)(Btl + (size_t)(kn + brow)*N + n0 + bc);
            bhr[1] = *(const uint4*)(Bth + (size_t)(kn + brow + 16)*N + n0 + bc);
            blr[1] = *(const uint4*)(Btl + (size_t)(kn + brow + 16)*N + n0 + bc);
        }
        __syncthreads();      // buf sb now full for all threads

        // ---- compute stage kt from buf sb ----
        const uint32_t ab = (uint32_t)(sb * ABYTES);
        const uint32_t bb = (uint32_t)(sb * BBYTES);
#pragma unroll
        for (int ko = 0; ko < 2; ko++) {
            uint32_t ah[2][4];
#pragma unroll
            for (int mt = 0; mt < 2; mt++)
                ldsm4(ah[mt],  AhB + ab + a_off[mt] + ko*32);
            uint32_t bh[4][2], bl[4][2];
#pragma unroll
            for (int p = 0; p < 2; p++) {
                uint32_t r[4];
                ldsm4t(r, BhB + bb + b_off[p] + ko*16*BSTR*2);
                bh[2*p][0] = r[0]; bh[2*p][1] = r[1];
                bh[2*p+1][0] = r[2]; bh[2*p+1][1] = r[3];
                ldsm4t(r, BlB + bb + b_off[p] + ko*16*BSTR*2);
                bl[2*p][0] = r[0]; bl[2*p][1] = r[1];
                bl[2*p+1][0] = r[2]; bl[2*p+1][1] = r[3];
            }
            if (USE16) {
#pragma unroll
                for (int mt = 0; mt < 2; mt++)
#pragma unroll
                    for (int nt = 0; nt < 4; nt++) {
                        mma16816h(acc[mt][nt], ah[mt], bh[nt]);
                        mma16816h(acc[mt][nt], ah[mt], bl[nt]);
                    }
            } else {
                uint32_t al_[2][4];
#pragma unroll
                for (int mt = 0; mt < 2; mt++)
                    ldsm4(al_[mt], AlB + ab + a_off[mt] + ko*32);
#pragma unroll
                for (int mt = 0; mt < 2; mt++)
#pragma unroll
                    for (int nt = 0; nt < 4; nt++) {
                        mma16816(acc[mt][nt], ah[mt],  bh[nt]);
                        mma16816(acc[mt][nt], ah[mt],  bl[nt]);
                        mma16816(acc[mt][nt], al_[mt], bh[nt]);
                    }
            }
        }
    }

    // ---- epilogue ----
    float colS[8], colQ[8];
#pragma unroll
    for (int i = 0; i < 8; i++) { colS[i] = 0.f; colQ[i] = 0.f; }

#pragma unroll
    for (int mt = 0; mt < 2; mt++) {
        int r0 = m0 + wm*32 + mt*16 + (lane >> 2);
        int r1 = r0 + 8;
        int j0 = 0, j1 = 0, p0 = 0, p1 = 0;
        if (MODE == 1) {
            j0 = g_idx[r0]; j1 = g_idx[r1];
            p0 = r0 >> 4;   p1 = r1 >> 4;
        }
#pragma unroll
        for (int nt = 0; nt < 4; nt++) {
            int cl = wn*32 + nt*8 + (lane & 3)*2;      // local col in [0,128)
            int c = n0 + cl;
            float v00 = acc[mt][nt][0] + sbias[cl],   v01 = acc[mt][nt][1] + sbias[cl+1];
            float v10 = acc[mt][nt][2] + sbias[cl],   v11 = acc[mt][nt][3] + sbias[cl+1];
            if (MODE == 1) {
                float2 q0 = *(const float2*)(g_q  + (size_t)p0*256 + c);
                float2 q1 = *(const float2*)(g_q  + (size_t)p1*256 + c);
                float2 k0 = *(const float2*)(g_kv + (size_t)j0*512 + c);
                float2 k1 = *(const float2*)(g_kv + (size_t)j1*512 + c);
                v00 = q0.x - k0.x + v00; v01 = q0.y - k0.y + v01;
                v10 = q1.x - k1.x + v10; v11 = q1.y - k1.y + v11;
            }
            if (MODE == 0) {
                *(float2*)(Cf + (size_t)r0*N + c) = make_float2(v00, v01);
                *(float2*)(Cf + (size_t)r1*N + c) = make_float2(v10, v11);
            } else {
                *(__half2*)(Ch + (size_t)r0*N + c) = __floats2half2_rn(v00, v01);
                *(__half2*)(Ch + (size_t)r1*N + c) = __floats2half2_rn(v10, v11);
            }
            if (MODE != 0) {
                colS[nt*2+0] += v00 + v10;  colS[nt*2+1] += v01 + v11;
                colQ[nt*2+0] += v00*v00 + v10*v10;
                colQ[nt*2+1] += v01*v01 + v11*v11;
            }
        }
    }
    if (MODE != 0) {
#pragma unroll
        for (int i = 0; i < 8; i++) {
#pragma unroll
            for (int off = 4; off <= 16; off <<= 1) {
                colS[i] += __shfl_xor_sync(0xffffffffu, colS[i], off);
                colQ[i] += __shfl_xor_sync(0xffffffffu, colQ[i], off);
            }
        }
        if (lane < 4) {
#pragma unroll
            for (int nt = 0; nt < 4; nt++) {
#pragma unroll
                for (int j = 0; j < 2; j++) {
                    int cl = wn*32 + nt*8 + lane*2 + j;
                    atomicAdd(&sstatS[cl], colS[nt*2+j]);
                    atomicAdd(&sstatQ[cl], colQ[nt*2+j]);
                }
            }
        }
        __syncthreads();
        if (tid < 128) {
            float* gS = (MODE == 1) ? g_s1 : g_s2;
            float* gQ = (MODE == 1) ? g_q1 : g_q2;
            atomicAdd(&gS[n0 + tid], sstatS[tid]);
            atomicAdd(&gQ[n0 + tid], sstatQ[tid]);
        }
    }
}

// ---------------- final: inline BN2 finalize + lrelu + softmax(K) + v-sum ------
// 128 threads/block, 2 channels per thread via half2/float2.
// v = vf[j] + pe = u[j] + (w1 - q),  u = kf + vf precomputed; w1/w2 fp16
__global__ void final_kernel(float* __restrict__ out,
                             const float* __restrict__ gw2, const float* __restrict__ bw2) {
    int n = blockIdx.x, t = threadIdx.x;       // 128 threads
    int c = t * 2;
    __shared__ int sidx[KNN];
    if (t < KNN) sidx[t] = g_idx[n*KNN + t];
    __syncthreads();
    float inv = 1.f / (float)NK;
    float mm0 = g_s2[c]   * inv, mm1 = g_s2[c+1] * inv;
    float vv0 = g_q2[c]   * inv - mm0*mm0;
    float vv1 = g_q2[c+1] * inv - mm1*mm1;
    float sc0 = gw2[c]   * rsqrtf(vv0 + EPS);
    float sc1 = gw2[c+1] * rsqrtf(vv1 + EPS);
    float sh0 = bw2[c]   - mm0*sc0;
    float sh1 = bw2[c+1] - mm1*sc1;
    float2 qv = *(const float2*)(g_q + (size_t)n*COUT + c);
    float z0[KNN], z1[KNN];
    float2 w1v[KNN];
    float m0 = -FLT_MAX, m1 = -FLT_MAX;
#pragma unroll
    for (int k = 0; k < KNN; k++) {
        size_t base = ((size_t)n*KNN + k)*COUT + c;
        float2 x2 = __half22float2(*(const __half2*)(g_w2h + base));
        w1v[k] = __half22float2(*(const __half2*)(g_w1h + base));
        float x0 = x2.x*sc0 + sh0;
        float x1 = x2.y*sc1 + sh1;
        x0 = (x0 >= 0.f) ? x0 : SLOPE*x0;
        x1 = (x1 >= 0.f) ? x1 : SLOPE*x1;
        z0[k] = x0; z1[k] = x1;
        m0 = fmaxf(m0, x0); m1 = fmaxf(m1, x1);
    }
    float den0 = 0.f, num0 = 0.f, den1 = 0.f, num1 = 0.f;
#pragma unroll
    for (int k = 0; k < KNN; k++) {
        float e0 = __expf(z0[k] - m0);
        float e1 = __expf(z1[k] - m1);
        float2 u2 = *(const float2*)(g_u + (size_t)sidx[k]*256 + c);
        float v0 = u2.x + (w1v[k].x - qv.x);
        float v1 = u2.y + (w1v[k].y - qv.y);
        den0 += e0; num0 = fmaf(e0, v0, num0);
        den1 += e1; num1 = fmaf(e1, v1, num1);
    }
    *(float2*)(out + (size_t)n*COUT + c) = make_float2(num0/den0, num1/den1);
}

// ---------------- launch (stream fork/join: kNN chain ∥ projection chain) ------
extern "C" void kernel_launch(void* const* d_in, const int* in_sizes, int n_in,
                              void* d_out, int out_size) {
    const float* fea_i    = (const float*)d_in[0];
    const float* fea_last = (const float*)d_in[1];
    const float* xyz_i    = (const float*)d_in[2];
    const float* xyz_last = (const float*)d_in[3];
    const float* t_i      = (const float*)d_in[4];
    const float* t_last   = (const float*)d_in[5];
    const float* wp1 = (const float*)d_in[6];
    const float* bp1 = (const float*)d_in[7];
    const float* gp  = (const float*)d_in[8];
    const float* bp  = (const float*)d_in[9];
    const float* wp2 = (const float*)d_in[10];
    const float* bp2 = (const float*)d_in[11];
    const float* wq  = (const float*)d_in[12];
    const float* bq  = (const float*)d_in[13];
    const float* wk  = (const float*)d_in[14];
    const float* bk  = (const float*)d_in[15];
    const float* wv  = (const float*)d_in[16];
    const float* bv  = (const float*)d_in[17];
    const float* gw1 = (const float*)d_in[18];
    const float* bw1 = (const float*)d_in[19];
    const float* ww  = (const float*)d_in[20];
    const float* bw  = (const float*)d_in[21];
    const float* gw2 = (const float*)d_in[22];
    const float* bw2 = (const float*)d_in[23];
    float* out = (float*)d_out;

    void* p;
    cudaGetSymbolAddress(&p, g_q);   float* p_q   = (float*)p;
    cudaGetSymbolAddress(&p, g_kv);  float* p_kv  = (float*)p;
    cudaGetSymbolAddress(&p, g_bkv); float* p_bkv = (float*)p;
    cudaGetSymbolAddress(&p, g_bth); uint16_t* p_bth = (uint16_t*)p;
    cudaGetSymbolAddress(&p, g_btl); uint16_t* p_btl = (uint16_t*)p;
    cudaGetSymbolAddress(&p, g_fh);  uint16_t* p_fh  = (uint16_t*)p;
    cudaGetSymbolAddress(&p, g_fl);  uint16_t* p_fl  = (uint16_t*)p;
    cudaGetSymbolAddress(&p, g_w1h); float* p_w1h = (float*)p;   // fp16 buffer (cast)
    cudaGetSymbolAddress(&p, g_w2h); float* p_w2h = (float*)p;   // fp16 buffer (cast)

    static cudaStream_t s2 = nullptr;
    static cudaEvent_t evFork = nullptr, evJoin = nullptr;
    if (s2 == nullptr) {
        cudaStreamCreateWithFlags(&s2, cudaStreamNonBlocking);
        cudaEventCreateWithFlags(&evFork, cudaEventDisableTiming);
        cudaEventCreateWithFlags(&evJoin, cudaEventDisableTiming);
    }

    // 0) prep (weight splits + bias + stat zero + grid zero) on main stream
    prep_kernel<<<(TOTW + 255)/256, 256>>>(wq, wk, wv, wp2, ww, bk, bv);

    // fork: side stream s2 runs projections (depend only on prep)
    cudaEventRecord(evFork, 0);
    cudaStreamWaitEvent(s2, evFork, 0);
    mma_gemm<0><<<dim3(2, 128), 256, 0, s2>>>(fea_last, p_bth + OQ,  p_btl + OQ,  bq,    p_q,  N_PTS, 256, CIN,
                                              nullptr, nullptr, nullptr, nullptr, nullptr, nullptr, nullptr, nullptr);
    mma_gemm<0><<<dim3(4, 128), 256, 0, s2>>>(fea_i,    p_bth + OKV, p_btl + OKV, p_bkv, p_kv, N_PTS, 512, CIN,
                                              nullptr, nullptr, nullptr, nullptr, nullptr, nullptr, nullptr, nullptr);
    u_kernel<<<(N_PTS*256)/256, 256, 0, s2>>>();
    cudaEventRecord(evJoin, s2);

    // main stream: kNN chain + moments (independent of projections)
    grid_count_kernel<<<N_PTS/256, 256>>>(xyz_i);
    grid_scan_kernel<<<1, 512>>>();
    grid_scatter_kernel<<<N_PTS/256, 256>>>(xyz_i);
    knn_grid_kernel<<<N_PTS/QPB, 256>>>(xyz_last);
    moments_kernel<<<64, 256>>>(xyz_i, xyz_last);

    // join: mma<1> needs both chains
    cudaStreamWaitEvent(0, evJoin, 0);

    // 4) pe GEMM (A generated, fp16 2-product) -> w1h = q - kf + pe, + BN1 stats
    mma_gemm<1><<<dim3(2, 2048), 256>>>(nullptr, p_fh + FP2, p_fl + FP2, bp2, p_w1h, NK, 256, HDIM,
                                        xyz_i, xyz_last, t_i, t_last, wp1, bp1, gp, bp);

    // 5) w2 GEMM (fp16 A from w1h, BN1 finalize inlined) + BN2 stats
    mma_gemm<2><<<dim3(2, 2048), 256>>>(p_w1h, p_fh + FW, p_fl + FW, bw, p_w2h, NK, 256, CIN,
                                        nullptr, nullptr, nullptr, nullptr, nullptr, nullptr, gw1, bw1);

    // 6) softmax over K + weighted v-sum (BN2 finalize inlined)
    final_kernel<<<N_PTS, 128>>>(out, gw2, bw2);
}